// round 10
// baseline (speedup 1.0000x reference)
#include <cuda_runtime.h>
#include <cuda_bf16.h>
#include <cstdint>

#define NB 2
#define NC 128
#define NU 2048
#define KF 512
#define NZK 64
#define NT 32768
#define NTP (NT + 512)
#define GOF 256
#define XP  (NT + 512)
#define CAP (1<<18)

typedef unsigned long long ull;

static __device__ __align__(16) float g_bufA[NB*NC*NTP];
static __device__ __align__(16) float g_bufB[NB*NC*NTP];
static __device__ __align__(16) float g_Wt[12*256*128];      // [layer][k=2*ci+tap][cout] (for k_base)
static __device__ __align__(16) float g_upwT[128*2048];      // [c][u] (for k_sub)
static __device__ __align__(16) float g_xp[NB*XP];
static __device__ __align__(16) __nv_bfloat16 g_WA[12*2*128*256];   // [l][plane][cout][k]
static __device__ __align__(16) __nv_bfloat16 g_fbA[2*128*512];     // [plane][c][j]
static __device__ __align__(16) __nv_bfloat16 g_upA[NU*128];        // [u][c] bf16 (hi only)
static __device__ float g_ysub[NB*2048*512];
static __device__ float g_thresh[NB];
static __device__ int   g_candCnt[NB];
static __device__ float g_candVal[NB*CAP];
static __device__ unsigned g_candPack[NB*CAP];
static __device__ float g_selVal[NB*NZK];
static __device__ int   g_selU[NB*NZK];
static __device__ int   g_selT[NB*NZK];
static __device__ float g_base[7*128];
static __device__ int   g_act[NB*256];

// ---------------- cp.async / mma helpers ----------------
__device__ __forceinline__ void cp16(void* dst, const void* src) {
    unsigned d = (unsigned)__cvta_generic_to_shared(dst);
    asm volatile("cp.async.cg.shared.global [%0], [%1], 16;\n" :: "r"(d), "l"(src));
}
#define CP_COMMIT() asm volatile("cp.async.commit_group;\n")
#define CP_WAIT1()  asm volatile("cp.async.wait_group 1;\n")
#define CP_WAIT0()  asm volatile("cp.async.wait_group 0;\n")

__device__ __forceinline__ void ldmA4(unsigned* a, unsigned addr) {
    asm volatile("ldmatrix.sync.aligned.m8n8.x4.shared.b16 {%0,%1,%2,%3}, [%4];"
                 : "=r"(a[0]), "=r"(a[1]), "=r"(a[2]), "=r"(a[3]) : "r"(addr));
}
__device__ __forceinline__ void ldmB2t(unsigned* bq, unsigned addr) {
    asm volatile("ldmatrix.sync.aligned.m8n8.x2.trans.shared.b16 {%0,%1}, [%2];"
                 : "=r"(bq[0]), "=r"(bq[1]) : "r"(addr));
}
__device__ __forceinline__ void mma16816(float* c, const unsigned* a, const unsigned* bq) {
    asm volatile("mma.sync.aligned.m16n8k16.row.col.f32.bf16.bf16.f32 "
                 "{%0,%1,%2,%3}, {%4,%5,%6,%7}, {%8,%9}, {%0,%1,%2,%3};"
                 : "+f"(c[0]), "+f"(c[1]), "+f"(c[2]), "+f"(c[3])
                 : "r"(a[0]), "r"(a[1]), "r"(a[2]), "r"(a[3]), "r"(bq[0]), "r"(bq[1]));
}
__device__ __forceinline__ unsigned pkbf(float a, float b) {
    unsigned lo = (unsigned)__bfloat16_as_ushort(__float2bfloat16(a));
    unsigned hi = (unsigned)__bfloat16_as_ushort(__float2bfloat16(b));
    return lo | (hi << 16);
}

// ---------------- weight / input prep ----------------
__global__ void k_wt(const float* __restrict__ enc_w, const float* __restrict__ dec_w) {
    int idx = blockIdx.x * 256 + threadIdx.x;
    if (idx >= 12 * 256 * 128) return;
    int l = idx / 32768;
    int r = idx - l * 32768;
    int k = r >> 7, c = r & 127;
    int ci = k >> 1, tap = k & 1;
    const float* w = (l < 6) ? (enc_w + l * 32768) : (dec_w + (l - 6) * 32768);
    g_Wt[idx] = w[(c * 128 + ci) * 2 + tap];
}

__global__ void k_wA(const float* __restrict__ enc_w, const float* __restrict__ dec_w) {
    int idx = blockIdx.x * 256 + threadIdx.x;
    if (idx >= 12 * 128 * 256) return;
    int l = idx / 32768;
    int r = idx - l * 32768;
    int c = r >> 8, k = r & 255;
    int ci = k >> 1, tap = k & 1;
    const float* w = (l < 6) ? (enc_w + l * 32768) : (dec_w + (l - 6) * 32768);
    float v = w[(c * 128 + ci) * 2 + tap];
    __nv_bfloat16 h = __float2bfloat16(v);
    g_WA[((l * 2 + 0) * 128 + c) * 256 + k] = h;
    g_WA[((l * 2 + 1) * 128 + c) * 256 + k] = __float2bfloat16(v - __bfloat162float(h));
}

__global__ void k_fbA(const float* __restrict__ fb) {
    int idx = blockIdx.x * 256 + threadIdx.x;
    if (idx >= 128 * 512) return;
    float v = fb[idx];
    __nv_bfloat16 h = __float2bfloat16(v);
    g_fbA[idx] = h;
    g_fbA[65536 + idx] = __float2bfloat16(v - __bfloat162float(h));
}

__global__ void k_upwT(const float* __restrict__ up_w) {
    int idx = blockIdx.x * 256 + threadIdx.x;
    if (idx >= 128 * 2048) return;
    int c = idx >> 11, u = idx & 2047;
    g_upwT[idx] = up_w[u * 128 + c];
}

__global__ void k_upA(const float* __restrict__ up_w) {
    int idx = blockIdx.x * 256 + threadIdx.x;
    if (idx >= NU * 128) return;
    g_upA[idx] = __float2bfloat16(up_w[idx]);
}

__global__ void k_xp(const float* __restrict__ x) {
    int idx = blockIdx.x * 256 + threadIdx.x;
    if (idx >= NB * XP) return;
    int b = idx / XP, w = idx - b * XP;
    g_xp[idx] = (w >= GOF && w < NT + GOF) ? x[b * NT + (w - GOF)] : 0.f;
}

__global__ void k_guard() {
    int idx = blockIdx.x * 256 + threadIdx.x;
    int half = NB * NC * 512;
    if (idx >= 2 * half) return;
    float* buf = (idx < half) ? g_bufA : g_bufB;
    int r = (idx < half) ? idx : idx - half;
    int row = r >> 9, w = r & 511;
    int pos = (w < 256) ? w : (NT + 256 + (w - 256));
    buf[row * NTP + pos] = 0.f;
}

// ---------------- filterbank analysis via mma (bf16x3, K=512) ----------------
__global__ void __launch_bounds__(256, 2) k_fb_mma() {
    __shared__ __align__(16) __nv_bfloat16 Ah[128][24];
    __shared__ __align__(16) __nv_bfloat16 Al[128][24];
    __shared__ __align__(16) __nv_bfloat16 Bh[16][136];
    __shared__ __align__(16) __nv_bfloat16 Bl[16][136];
    int tid = threadIdx.x;
    int b = blockIdx.y, t0 = blockIdx.x * 128;
    int w = tid >> 5, lane = tid & 31;
    int wu = w >> 1, wt = w & 1;
    int q = lane >> 3, r = lane & 7;
    const float* xb = g_xp + b * XP;

    float acc[2][8][4];
#pragma unroll
    for (int mi = 0; mi < 2; mi++)
#pragma unroll
        for (int ni = 0; ni < 8; ni++)
#pragma unroll
            for (int v = 0; v < 4; v++) acc[mi][ni][v] = 0.f;

    unsigned aA[2], bA[8];
#pragma unroll
    for (int mi = 0; mi < 2; mi++)
        aA[mi] = (unsigned)__cvta_generic_to_shared(
            &Ah[wu * 32 + mi * 16 + (q & 1) * 8 + r][(q >> 1) * 8]);
#pragma unroll
    for (int ni = 0; ni < 8; ni++)
        bA[ni] = (unsigned)__cvta_generic_to_shared(
            &Bh[lane & 15][wt * 64 + ni * 8]);
    unsigned dA = (unsigned)__cvta_generic_to_shared(&Al[0][0]) -
                  (unsigned)__cvta_generic_to_shared(&Ah[0][0]);
    unsigned dB = (unsigned)__cvta_generic_to_shared(&Bl[0][0]) -
                  (unsigned)__cvta_generic_to_shared(&Bh[0][0]);

    int brow = tid >> 4, bcb = (tid & 15) * 8;
    int arow = tid >> 1, ahalf = (tid & 1) * 8;

    float vr[8];
    {   // prefetch chunk 0
        const float* src = xb + t0 + brow + bcb;
#pragma unroll
        for (int j = 0; j < 8; j++) vr[j] = src[j];
    }
    for (int ck = 0; ck < 32; ck++) {
        int kc = ck * 16;
        if (ck) __syncthreads();
        cp16(&Ah[arow][ahalf], g_fbA + arow * 512 + kc + ahalf);
        cp16(&Al[arow][ahalf], g_fbA + 65536 + arow * 512 + kc + ahalf);
        CP_COMMIT();
#pragma unroll
        for (int jj = 0; jj < 4; jj++) {
            float v0 = vr[2 * jj], v1 = vr[2 * jj + 1];
            float h0 = __bfloat162float(__float2bfloat16(v0));
            float h1 = __bfloat162float(__float2bfloat16(v1));
            *(unsigned*)&Bh[brow][bcb + 2 * jj] = pkbf(v0, v1);
            *(unsigned*)&Bl[brow][bcb + 2 * jj] = pkbf(v0 - h0, v1 - h1);
        }
        if (ck + 1 < 32) {
            const float* src = xb + t0 + kc + 16 + brow + bcb;
#pragma unroll
            for (int j = 0; j < 8; j++) vr[j] = src[j];
        }
        CP_WAIT0(); __syncthreads();
        unsigned bq[8][2], af[2][4];
#pragma unroll
        for (int ni = 0; ni < 8; ni++) ldmB2t(bq[ni], bA[ni]);
#pragma unroll
        for (int mi = 0; mi < 2; mi++) ldmA4(af[mi], aA[mi]);
#pragma unroll
        for (int mi = 0; mi < 2; mi++)
#pragma unroll
            for (int ni = 0; ni < 8; ni++) mma16816(acc[mi][ni], af[mi], bq[ni]);
#pragma unroll
        for (int mi = 0; mi < 2; mi++) ldmA4(af[mi], aA[mi] + dA);
#pragma unroll
        for (int mi = 0; mi < 2; mi++)
#pragma unroll
            for (int ni = 0; ni < 8; ni++) mma16816(acc[mi][ni], af[mi], bq[ni]);
#pragma unroll
        for (int ni = 0; ni < 8; ni++) ldmB2t(bq[ni], bA[ni] + dB);
#pragma unroll
        for (int mi = 0; mi < 2; mi++) ldmA4(af[mi], aA[mi]);
#pragma unroll
        for (int mi = 0; mi < 2; mi++)
#pragma unroll
            for (int ni = 0; ni < 8; ni++) mma16816(acc[mi][ni], af[mi], bq[ni]);
    }
    int gid = lane >> 2, tig = lane & 3;
#pragma unroll
    for (int mi = 0; mi < 2; mi++) {
        int c = wu * 32 + mi * 16 + gid;
        float* y0 = g_bufA + (b * NC + c) * NTP + GOF;
        float* y8 = y0 + 8 * NTP;
#pragma unroll
        for (int ni = 0; ni < 8; ni++) {
            int t = t0 + wt * 64 + ni * 8 + tig * 2;
            *(float2*)(y0 + t) = make_float2(acc[mi][ni][0], acc[mi][ni][1]);
            *(float2*)(y8 + t) = make_float2(acc[mi][ni][2], acc[mi][ni][3]);
        }
    }
}

// ---------------- residual dilated layer via mma (bf16x3, K=256, sparse) ----------------
__global__ void __launch_bounds__(256, 2) k_layer_mma(int srcIsA, int lidx,
                                                      const float* __restrict__ bias,
                                                      int o0, int o1, int sparse, int lvl) {
    __shared__ __align__(16) __nv_bfloat16 Ah[128][24];
    __shared__ __align__(16) __nv_bfloat16 Al[128][24];
    __shared__ __align__(16) __nv_bfloat16 Bh[16][136];
    __shared__ __align__(16) __nv_bfloat16 Bl[16][136];
    const float* X = srcIsA ? g_bufA : g_bufB;
    float* Y = srcIsA ? g_bufB : g_bufA;
    int tid = threadIdx.x;
    int b = blockIdx.y, blk = blockIdx.x, t0 = blk * 128;

    if (sparse && !g_act[b * 256 + blk]) {
        int tx = tid & 15, ty = tid >> 4;
#pragma unroll
        for (int i = 0; i < 8; i++) {
            float v = g_base[(lvl + 1) * 128 + ty * 8 + i];
#pragma unroll
            for (int j = 0; j < 8; j++) {
                int t = t0 + ((j < 4) ? (tx * 4 + j) : (64 + tx * 4 + j - 4));
                Y[(b * NC + ty * 8 + i) * NTP + GOF + t] = v;
            }
        }
        return;
    }

    int w = tid >> 5, lane = tid & 31;
    int wu = w >> 1, wt = w & 1;
    int q = lane >> 3, r = lane & 7;
    const float* Xb = X + b * NC * NTP;
    int dOff = o1 - o0;
    const __nv_bfloat16* WAh = g_WA + (size_t)(lidx * 2 + 0) * 32768;
    const __nv_bfloat16* WAl = g_WA + (size_t)(lidx * 2 + 1) * 32768;

    float acc[2][8][4];
#pragma unroll
    for (int mi = 0; mi < 2; mi++)
#pragma unroll
        for (int ni = 0; ni < 8; ni++)
#pragma unroll
            for (int v = 0; v < 4; v++) acc[mi][ni][v] = 0.f;

    unsigned aA[2], bA[8];
#pragma unroll
    for (int mi = 0; mi < 2; mi++)
        aA[mi] = (unsigned)__cvta_generic_to_shared(
            &Ah[wu * 32 + mi * 16 + (q & 1) * 8 + r][(q >> 1) * 8]);
#pragma unroll
    for (int ni = 0; ni < 8; ni++)
        bA[ni] = (unsigned)__cvta_generic_to_shared(
            &Bh[lane & 15][wt * 64 + ni * 8]);
    unsigned dA = (unsigned)__cvta_generic_to_shared(&Al[0][0]) -
                  (unsigned)__cvta_generic_to_shared(&Ah[0][0]);
    unsigned dB = (unsigned)__cvta_generic_to_shared(&Bl[0][0]) -
                  (unsigned)__cvta_generic_to_shared(&Bh[0][0]);

    int brow = tid >> 4, bcb = (tid & 15) * 8;
    int arow = tid >> 1, ahalf = (tid & 1) * 8;

    float vr[8];
    {
        int k = brow;
        const float* src = Xb + (k >> 1) * NTP + GOF + t0 + o0 + (k & 1) * dOff + bcb;
#pragma unroll
        for (int j = 0; j < 8; j++) vr[j] = src[j];
    }
    for (int ck = 0; ck < 16; ck++) {
        int kc = ck * 16;
        if (ck) __syncthreads();
        cp16(&Ah[arow][ahalf], WAh + arow * 256 + kc + ahalf);
        cp16(&Al[arow][ahalf], WAl + arow * 256 + kc + ahalf);
        CP_COMMIT();
#pragma unroll
        for (int jj = 0; jj < 4; jj++) {
            float v0 = vr[2 * jj], v1 = vr[2 * jj + 1];
            float h0 = __bfloat162float(__float2bfloat16(v0));
            float h1 = __bfloat162float(__float2bfloat16(v1));
            *(unsigned*)&Bh[brow][bcb + 2 * jj] = pkbf(v0, v1);
            *(unsigned*)&Bl[brow][bcb + 2 * jj] = pkbf(v0 - h0, v1 - h1);
        }
        if (ck + 1 < 16) {
            int k = kc + 16 + brow;
            const float* src = Xb + (k >> 1) * NTP + GOF + t0 + o0 + (k & 1) * dOff + bcb;
#pragma unroll
            for (int j = 0; j < 8; j++) vr[j] = src[j];
        }
        CP_WAIT0(); __syncthreads();
        unsigned bq[8][2], af[2][4];
#pragma unroll
        for (int ni = 0; ni < 8; ni++) ldmB2t(bq[ni], bA[ni]);
#pragma unroll
        for (int mi = 0; mi < 2; mi++) ldmA4(af[mi], aA[mi]);
#pragma unroll
        for (int mi = 0; mi < 2; mi++)
#pragma unroll
            for (int ni = 0; ni < 8; ni++) mma16816(acc[mi][ni], af[mi], bq[ni]);
#pragma unroll
        for (int mi = 0; mi < 2; mi++) ldmA4(af[mi], aA[mi] + dA);
#pragma unroll
        for (int mi = 0; mi < 2; mi++)
#pragma unroll
            for (int ni = 0; ni < 8; ni++) mma16816(acc[mi][ni], af[mi], bq[ni]);
#pragma unroll
        for (int ni = 0; ni < 8; ni++) ldmB2t(bq[ni], bA[ni] + dB);
#pragma unroll
        for (int mi = 0; mi < 2; mi++) ldmA4(af[mi], aA[mi]);
#pragma unroll
        for (int mi = 0; mi < 2; mi++)
#pragma unroll
            for (int ni = 0; ni < 8; ni++) mma16816(acc[mi][ni], af[mi], bq[ni]);
    }
    int gid = lane >> 2, tig = lane & 3;
#pragma unroll
    for (int mi = 0; mi < 2; mi++) {
        int c = wu * 32 + mi * 16 + gid;
        float bi0 = bias[c], bi8 = bias[c + 8];
        const float* x0 = Xb + c * NTP + GOF;
        const float* x8 = x0 + 8 * NTP;
        float* y0 = Y + (b * NC + c) * NTP + GOF;
        float* y8 = y0 + 8 * NTP;
#pragma unroll
        for (int ni = 0; ni < 8; ni++) {
            int t = t0 + wt * 64 + ni * 8 + tig * 2;
            float h0 = acc[mi][ni][0] + bi0; h0 = (h0 > 0.f) ? h0 : 0.2f * h0;
            float h1 = acc[mi][ni][1] + bi0; h1 = (h1 > 0.f) ? h1 : 0.2f * h1;
            float h2 = acc[mi][ni][2] + bi8; h2 = (h2 > 0.f) ? h2 : 0.2f * h2;
            float h3 = acc[mi][ni][3] + bi8; h3 = (h3 > 0.f) ? h3 : 0.2f * h3;
            float2 xa = *(const float2*)(x0 + t);
            float2 xb2 = *(const float2*)(x8 + t);
            *(float2*)(y0 + t) = make_float2(xa.x + h0, xa.y + h1);
            *(float2*)(y8 + t) = make_float2(xb2.x + h2, xb2.y + h3);
        }
    }
}

// ---------------- subsampled up-projection (threshold bootstrap) ----------------
__global__ void __launch_bounds__(256) k_sub(const float* __restrict__ up_b) {
    __shared__ float es[16][128];
    int b = blockIdx.z;
    int u = blockIdx.x * 256 + threadIdx.x;
    int ts0 = blockIdx.y * 16;
    const float* E = g_bufA + b * NC * NTP + GOF;
    for (int i = threadIdx.x; i < 16 * 128; i += 256) {
        int tsl = i >> 7, c = i & 127;
        es[tsl][c] = E[c * NTP + (ts0 + tsl) * 64];
    }
    __syncthreads();
    float acc[16];
    float bi = up_b[u];
#pragma unroll
    for (int j = 0; j < 16; j++) acc[j] = bi;
    for (int c = 0; c < 128; c++) {
        float w = g_upwT[c * 2048 + u];
#pragma unroll
        for (int j = 0; j < 16; j++) acc[j] += w * es[j][c];
    }
#pragma unroll
    for (int j = 0; j < 16; j++)
        g_ysub[(b * 2048 + u) * 512 + ts0 + j] = acc[j];
}

__device__ __forceinline__ unsigned f2ord(float v) {
    unsigned u = __float_as_uint(v);
    return (u & 0x80000000u) ? ~u : (u | 0x80000000u);
}
__device__ __forceinline__ float ord2f(unsigned k) {
    unsigned u = (k & 0x80000000u) ? (k ^ 0x80000000u) : ~k;
    return __uint_as_float(u);
}

// ---------------- conservative threshold (with relative margin for bf16 GEMM) ----------------
__global__ void k_thresh() {
    __shared__ unsigned hist[2048];
    __shared__ int s_b1, s_m;
    int b = blockIdx.x, tid = threadIdx.x;
    const float* ys = g_ysub + b * 2048 * 512;
    for (int i = tid; i < 2048; i += 1024) hist[i] = 0;
    __syncthreads();
    for (int i = tid; i < 2048 * 512; i += 1024)
        atomicAdd(&hist[f2ord(ys[i]) >> 21], 1u);
    __syncthreads();
    if (tid == 0) {
        unsigned acc = 0;
        int b1 = 0, m = 64;
        for (int i = 2047; i >= 0; i--) {
            acc += hist[i];
            if (acc >= 64) { b1 = i; m = 64 - (int)(acc - hist[i]); break; }
        }
        s_b1 = b1; s_m = m;
    }
    __syncthreads();
    int b1 = s_b1, m = s_m;
    for (int i = tid; i < 2048; i += 1024) hist[i] = 0;
    __syncthreads();
    for (int i = tid; i < 2048 * 512; i += 1024) {
        unsigned key = f2ord(ys[i]);
        if ((int)(key >> 21) == b1) atomicAdd(&hist[(key >> 10) & 2047], 1u);
    }
    __syncthreads();
    if (tid == 0) {
        unsigned acc = 0;
        int b2 = 0;
        for (int i = 2047; i >= 0; i--) {
            acc += hist[i];
            if ((int)acc >= m) { b2 = i; break; }
        }
        unsigned tk = ((unsigned)b1 << 21) | ((unsigned)b2 << 10);
        if (tk >= (1u << 10)) tk -= (1u << 10);  // one-bin safety margin
        float tf = ord2f(tk);
        // relative margin covering single-plane bf16 GEMM error (~0.25% 3-sigma)
        g_thresh[b] = tf - 0.05f * fabsf(tf);
        g_candCnt[b] = 0;
    }
}

// ---------------- up-projection via mma.sync (single-plane bf16, K=128) ----------------
// CTA: 128u x 128t. A tile resident (loaded once); B converted on-the-fly from g_bufA.
__global__ void __launch_bounds__(256, 2) k_up_mma(const float* __restrict__ up_b) {
    __shared__ __align__(16) __nv_bfloat16 Ah[128][136];
    __shared__ __align__(16) __nv_bfloat16 Bh[16][136];
    int tid = threadIdx.x;
    int b = blockIdx.z;
    int u0 = blockIdx.y * 128;
    int t0 = blockIdx.x * 128;
    int w = tid >> 5, lane = tid & 31;
    int wu = w >> 1, wt = w & 1;
    int q = lane >> 3, r = lane & 7;

    // load A tile [128u][128k] once
    for (int i = tid; i < 2048; i += 256) {
        int row = i >> 4, c8 = (i & 15) * 8;
        cp16(&Ah[row][c8], g_upA + (u0 + row) * 128 + c8);
    }
    CP_COMMIT();

    float acc[2][8][4];
#pragma unroll
    for (int mi = 0; mi < 2; mi++)
#pragma unroll
        for (int ni = 0; ni < 8; ni++)
#pragma unroll
            for (int v = 0; v < 4; v++) acc[mi][ni][v] = 0.f;

    unsigned aA[2], bA[8];
#pragma unroll
    for (int mi = 0; mi < 2; mi++)
        aA[mi] = (unsigned)__cvta_generic_to_shared(
            &Ah[wu * 32 + mi * 16 + (q & 1) * 8 + r][(q >> 1) * 8]);
#pragma unroll
    for (int ni = 0; ni < 8; ni++)
        bA[ni] = (unsigned)__cvta_generic_to_shared(
            &Bh[lane & 15][wt * 64 + ni * 8]);

    const float* Xb = g_bufA + b * NC * NTP + GOF + t0;
    int brow = tid >> 4, bcb = (tid & 15) * 8;

    float vr[8];
    {
        const float* src = Xb + brow * NTP + bcb;
#pragma unroll
        for (int j = 0; j < 8; j++) vr[j] = src[j];
    }
    CP_WAIT0();
    __syncthreads();

    for (int ck = 0; ck < 8; ck++) {
        if (ck) __syncthreads();
#pragma unroll
        for (int jj = 0; jj < 4; jj++)
            *(unsigned*)&Bh[brow][bcb + 2 * jj] = pkbf(vr[2 * jj], vr[2 * jj + 1]);
        if (ck + 1 < 8) {
            const float* src = Xb + ((ck + 1) * 16 + brow) * NTP + bcb;
#pragma unroll
            for (int j = 0; j < 8; j++) vr[j] = src[j];
        }
        __syncthreads();
        unsigned bq[8][2], af[2][4];
#pragma unroll
        for (int ni = 0; ni < 8; ni++) ldmB2t(bq[ni], bA[ni]);
#pragma unroll
        for (int mi = 0; mi < 2; mi++) ldmA4(af[mi], aA[mi] + ck * 32);
#pragma unroll
        for (int mi = 0; mi < 2; mi++)
#pragma unroll
            for (int ni = 0; ni < 8; ni++) mma16816(acc[mi][ni], af[mi], bq[ni]);
    }

    // epilogue: threshold + append
    float T0 = g_thresh[b];
    int gid = lane >> 2, tig = lane & 3;
#pragma unroll
    for (int mi = 0; mi < 2; mi++) {
        int ub = u0 + wu * 32 + mi * 16 + gid;
        float bi0 = up_b[ub];
        float bi8 = up_b[ub + 8];
#pragma unroll
        for (int ni = 0; ni < 8; ni++) {
            int tb = t0 + wt * 64 + ni * 8 + tig * 2;
            float vv[4] = {acc[mi][ni][0] + bi0, acc[mi][ni][1] + bi0,
                           acc[mi][ni][2] + bi8, acc[mi][ni][3] + bi8};
            int uu[4] = {ub, ub, ub + 8, ub + 8};
            int tt[4] = {tb, tb + 1, tb, tb + 1};
#pragma unroll
            for (int v = 0; v < 4; v++) {
                if (vv[v] >= T0) {
                    int idx = atomicAdd(&g_candCnt[b], 1);
                    if (idx < CAP) {
                        g_candVal[b * CAP + idx] = vv[v];
                        g_candPack[b * CAP + idx] =
                            ((unsigned)uu[v] << 16) | (unsigned)tt[v];
                    }
                }
            }
        }
    }
}

// ---------------- exact fp32 rescore of ALL candidates ----------------
__global__ void k_rescoreAll(const float* __restrict__ up_w, const float* __restrict__ up_b) {
    int b = blockIdx.y;
    int cnt = g_candCnt[b];
    if (cnt > CAP) cnt = CAP;
    int warpId = blockIdx.x * 8 + (threadIdx.x >> 5);
    int nw = gridDim.x * 8;
    int lane = threadIdx.x & 31;
    for (int i = warpId; i < cnt; i += nw) {
        unsigned pack = g_candPack[b * CAP + i];
        int u = (int)(pack >> 16), t = (int)(pack & 0xFFFFu);
        float s = 0.f;
#pragma unroll
        for (int c = lane; c < 128; c += 32)
            s += up_w[u * 128 + c] * g_bufA[(b * NC + c) * NTP + GOF + t];
#pragma unroll
        for (int o = 16; o; o >>= 1) s += __shfl_xor_sync(0xFFFFFFFFu, s, o);
        if (lane == 0) g_candVal[b * CAP + i] = s + up_b[u];
    }
}

// ---------------- exact top-64 of candidates (now exact values) ----------------
__global__ void k_select() {
    __shared__ ull keys[5632];
    __shared__ ull red[256];
    int b = blockIdx.x, tid = threadIdx.x;
    int cnt = g_candCnt[b];
    if (cnt > CAP) cnt = CAP;
    bool useS = (cnt <= 5632);
    if (useS) {
        for (int i = tid; i < cnt; i += 256) {
            unsigned key = f2ord(g_candVal[b * CAP + i]);
            unsigned pack = g_candPack[b * CAP + i];
            keys[i] = ((ull)key << 32) | (ull)(~pack);
        }
    }
    __syncthreads();
    ull prev = 0xFFFFFFFFFFFFFFFFull;
    for (int r = 0; r < 64; r++) {
        ull best = 0;
        if (useS) {
            for (int i = tid; i < cnt; i += 256) {
                ull k64 = keys[i];
                if (k64 < prev && k64 > best) best = k64;
            }
        } else {
            for (int i = tid; i < cnt; i += 256) {
                unsigned key = f2ord(g_candVal[b * CAP + i]);
                unsigned pack = g_candPack[b * CAP + i];
                ull k64 = ((ull)key << 32) | (ull)(~pack);
                if (k64 < prev && k64 > best) best = k64;
            }
        }
        red[tid] = best;
        __syncthreads();
        for (int s = 128; s > 0; s >>= 1) {
            if (tid < s) { if (red[tid + s] > red[tid]) red[tid] = red[tid + s]; }
            __syncthreads();
        }
        best = red[0];
        if (tid == 0) {
            unsigned key = (unsigned)(best >> 32);
            unsigned pack = ~((unsigned)best);
            g_selVal[b * 64 + r] = ord2f(key);
            g_selU[b * 64 + r] = (int)(pack >> 16);
            g_selT[b * 64 + r] = (int)(pack & 0xFFFFu);
        }
        prev = best;
        __syncthreads();
    }
}

// ---------------- decoder steady-state baselines ----------------
__global__ void k_base(const float* __restrict__ down_b, const float* __restrict__ dec_b) {
    __shared__ float cur[128];
    int c = threadIdx.x;
    cur[c] = down_b[c];
    g_base[c] = cur[c];
    __syncthreads();
    for (int l = 0; l < 6; l++) {
        const float* Wt = g_Wt + (6 + l) * 32768;
        float h = dec_b[l * 128 + c];
        for (int ci = 0; ci < 128; ci++)
            h += (Wt[(2 * ci) * 128 + c] + Wt[(2 * ci + 1) * 128 + c]) * cur[ci];
        h = (h > 0.f) ? h : 0.2f * h;
        float nv = cur[c] + h;
        __syncthreads();
        cur[c] = nv;
        g_base[(l + 1) * 128 + c] = nv;
        __syncthreads();
    }
}

__global__ void k_flags() {
    int idx = threadIdx.x;
    if (idx >= NB * 256) return;
    int b = idx >> 8, blk = idx & 255;
    int lo = blk * 128, hi = lo + 127;
    int act = (lo < 123) ? 1 : 0;
    for (int e = 0; e < 64; e++) {
        int s = g_selT[b * 64 + e];
        if (s <= hi && s + 122 >= lo) act = 1;
    }
    g_act[idx] = act;
}

__global__ void k_fill(const float* __restrict__ down_b) {
    int idx = blockIdx.x * 256 + threadIdx.x;
    if (idx >= NB * NC * NT / 4) return;
    int row = idx >> 13, t4 = idx & 8191;
    float v = down_b[row & 127];
    *(float4*)(&g_bufB[row * NTP + GOF + t4 * 4]) = make_float4(v, v, v, v);
}

__global__ void k_scatter(const float* __restrict__ down_w) {
    int tid = threadIdx.x;
    int b = tid >> 7, c = tid & 127;
    float* dst = g_bufB + (b * NC + c) * NTP + GOF;
    for (int e = 0; e < 64; e++) {
        float v = g_selVal[b * 64 + e];
        int u = g_selU[b * 64 + e];
        int t = g_selT[b * 64 + e];
        dst[t] += down_w[c * 2048 + u] * v;
    }
}

// ---------------- transposed filterbank synthesis (sliding window) ----------------
__global__ void __launch_bounds__(256) k_final(const float* __restrict__ fb,
                                               float* __restrict__ out) {
    __shared__ __align__(16) float fbs[8][512];
    __shared__ __align__(16) float ds[8][640];
    __shared__ float red[8][128];
    int b = blockIdx.y, t0 = blockIdx.x * 128;
    int tid = threadIdx.x;
    int lane = tid & 31, cs = tid >> 5;
    const float* D = g_bufB + b * NC * NTP + GOF;

    float acc[4] = {0.f, 0.f, 0.f, 0.f};
    for (int cc = cs; cc < 128; cc += 8) {
        const float* fr = fb + cc * 512;
#pragma unroll
        for (int i = 0; i < 16; i++) {
            int w = lane + 32 * i;
            fbs[cs][w] = fr[511 - w];
        }
        const float* Dr = D + cc * NTP + t0 - 255;
#pragma unroll
        for (int i = 0; i < 20; i++) {
            int w = lane + 32 * i;
            if (w < 639) ds[cs][w] = Dr[w];
        }
        __syncwarp();
        float w0 = ds[cs][lane * 4 + 0];
        float w1 = ds[cs][lane * 4 + 1];
        float w2 = ds[cs][lane * 4 + 2];
        float w3 = ds[cs][lane * 4 + 3];
#pragma unroll 4
        for (int k = 0; k < 512; k += 4) {
            float4 f = *(const float4*)&fbs[cs][k];
            float4 n = *(const float4*)&ds[cs][lane * 4 + k + 4];
            acc[0] += f.x * w0; acc[1] += f.x * w1; acc[2] += f.x * w2; acc[3] += f.x * w3;
            acc[0] += f.y * w1; acc[1] += f.y * w2; acc[2] += f.y * w3; acc[3] += f.y * n.x;
            acc[0] += f.z * w2; acc[1] += f.z * w3; acc[2] += f.z * n.x; acc[3] += f.z * n.y;
            acc[0] += f.w * w3; acc[1] += f.w * n.x; acc[2] += f.w * n.y; acc[3] += f.w * n.z;
            w0 = n.x; w1 = n.y; w2 = n.z; w3 = n.w;
        }
        __syncwarp();
    }
#pragma unroll
    for (int j = 0; j < 4; j++) red[cs][lane * 4 + j] = acc[j];
    __syncthreads();
    if (tid < 128) {
        float s = 0.f;
#pragma unroll
        for (int g = 0; g < 8; g++) s += red[g][tid];
        out[b * NT + t0 + tid] = s;
    }
}

// ---------------- host driver ----------------
extern "C" void kernel_launch(void* const* d_in, const int* in_sizes, int n_in,
                              void* d_out, int out_size) {
    const float* x      = (const float*)d_in[0];
    const float* fb     = (const float*)d_in[1];
    const float* enc_w  = (const float*)d_in[2];
    const float* enc_b  = (const float*)d_in[3];
    const float* up_w   = (const float*)d_in[4];
    const float* up_b   = (const float*)d_in[5];
    const float* down_w = (const float*)d_in[6];
    const float* down_b = (const float*)d_in[7];
    const float* dec_w  = (const float*)d_in[8];
    const float* dec_b  = (const float*)d_in[9];
    float* out = (float*)d_out;

    static const int dil[6] = {1, 3, 9, 27, 81, 1};

    k_wt<<<(12 * 256 * 128 + 255) / 256, 256>>>(enc_w, dec_w);
    k_wA<<<(12 * 128 * 256 + 255) / 256, 256>>>(enc_w, dec_w);
    k_fbA<<<(128 * 512 + 255) / 256, 256>>>(fb);
    k_upwT<<<(128 * 2048 + 255) / 256, 256>>>(up_w);
    k_upA<<<(NU * 128 + 255) / 256, 256>>>(up_w);
    k_xp<<<(NB * XP + 255) / 256, 256>>>(x);
    k_guard<<<(2 * NB * NC * 512 + 255) / 256, 256>>>();

    k_fb_mma<<<dim3(NT / 128, NB), 256>>>();

    // encoder: 'only-future' -> offsets (0, +d)
    int srcIsA = 1;
    for (int l = 0; l < 6; l++) {
        k_layer_mma<<<dim3(256, NB), 256>>>(srcIsA, l, enc_b + l * 128, 0, dil[l], 0, 0);
        srcIsA ^= 1;
    }
    // encoder output in bufA

    k_sub<<<dim3(NU / 256, 512 / 16, NB), 256>>>(up_b);
    k_thresh<<<NB, 1024>>>();
    k_up_mma<<<dim3(NT / 128, NU / 128, NB), 256>>>(up_b);
    k_rescoreAll<<<dim3(64, NB), 256>>>(up_w, up_b);
    k_select<<<NB, 256>>>();

    k_base<<<1, 128>>>(down_b, dec_b);
    k_flags<<<1, 512>>>();
    k_fill<<<(NB * NC * NT / 4 + 255) / 256, 256>>>(down_b);
    k_scatter<<<1, 256>>>(down_w);

    // decoder: 'only-past' -> offsets (-d, 0), sparse block-skip
    srcIsA = 0;
    for (int l = 0; l < 6; l++) {
        k_layer_mma<<<dim3(256, NB), 256>>>(srcIsA, 6 + l, dec_b + l * 128, -dil[l], 0, 1, l);
        srcIsA ^= 1;
    }
    // decoder output in bufB

    k_final<<<dim3(NT / 128, NB), 256>>>(fb, out);
    (void)in_sizes; (void)n_in; (void)out_size;
}

// round 11
// speedup vs baseline: 1.4470x; 1.4470x over previous
#include <cuda_runtime.h>
#include <cuda_bf16.h>
#include <cstdint>

#define NB 2
#define NC 128
#define NU 2048
#define NZK 64
#define NT 32768
#define NTP (NT + 512)
#define GOF 256
#define XP  (NT + 512)
#define CAP (1<<18)

typedef unsigned long long ull;

static __device__ __align__(16) float g_bufA[NB*NC*NTP];
static __device__ __align__(16) float g_bufB[NB*NC*NTP];
static __device__ __align__(16) float g_Wt[12*256*128];
static __device__ __align__(16) float g_upwT[128*2048];
static __device__ __align__(16) float g_xp[NB*XP];
static __device__ __align__(16) __nv_bfloat16 g_WA[12*2*128*256];
static __device__ __align__(16) __nv_bfloat16 g_fbA[2*128*512];
static __device__ __align__(16) __nv_bfloat16 g_upA[NU*128];
static __device__ float g_ysub[NB*2048*512];
static __device__ float g_thresh[NB];
static __device__ int   g_candCnt[NB];
static __device__ float g_candVal[NB*CAP];
static __device__ unsigned g_candPack[NB*CAP];
static __device__ float g_selVal[NB*NZK];
static __device__ int   g_selU[NB*NZK];
static __device__ int   g_selT[NB*NZK];
static __device__ float g_base[7*128];
static __device__ int   g_act[NB*256];
static __device__ float g_pref[513];

__device__ __forceinline__ void cp16(void* dst, const void* src) {
    unsigned d = (unsigned)__cvta_generic_to_shared(dst);
    asm volatile("cp.async.cg.shared.global [%0], [%1], 16;\n" :: "r"(d), "l"(src));
}
#define CP_COMMIT() asm volatile("cp.async.commit_group;\n")
#define CP_WAIT0()  asm volatile("cp.async.wait_group 0;\n")

__device__ __forceinline__ void ldmA4(unsigned* a, unsigned addr) {
    asm volatile("ldmatrix.sync.aligned.m8n8.x4.shared.b16 {%0,%1,%2,%3}, [%4];"
                 : "=r"(a[0]), "=r"(a[1]), "=r"(a[2]), "=r"(a[3]) : "r"(addr));
}
__device__ __forceinline__ void ldmB2t(unsigned* bq, unsigned addr) {
    asm volatile("ldmatrix.sync.aligned.m8n8.x2.trans.shared.b16 {%0,%1}, [%2];"
                 : "=r"(bq[0]), "=r"(bq[1]) : "r"(addr));
}
__device__ __forceinline__ void ldmB2(unsigned* bq, unsigned addr) {
    asm volatile("ldmatrix.sync.aligned.m8n8.x2.shared.b16 {%0,%1}, [%2];"
                 : "=r"(bq[0]), "=r"(bq[1]) : "r"(addr));
}
__device__ __forceinline__ void mma16816(float* c, const unsigned* a, const unsigned* bq) {
    asm volatile("mma.sync.aligned.m16n8k16.row.col.f32.bf16.bf16.f32 "
                 "{%0,%1,%2,%3}, {%4,%5,%6,%7}, {%8,%9}, {%0,%1,%2,%3};"
                 : "+f"(c[0]), "+f"(c[1]), "+f"(c[2]), "+f"(c[3])
                 : "r"(a[0]), "r"(a[1]), "r"(a[2]), "r"(a[3]), "r"(bq[0]), "r"(bq[1]));
}
__device__ __forceinline__ unsigned pkbf(float a, float b) {
    unsigned lo = (unsigned)__bfloat16_as_ushort(__float2bfloat16(a));
    unsigned hi = (unsigned)__bfloat16_as_ushort(__float2bfloat16(b));
    return lo | (hi << 16);
}

__global__ void k_wt(const float* __restrict__ enc_w, const float* __restrict__ dec_w) {
    int idx = blockIdx.x * 256 + threadIdx.x;
    if (idx >= 12 * 256 * 128) return;
    int l = idx / 32768;
    int r = idx - l * 32768;
    int k = r >> 7, c = r & 127;
    const float* w = (l < 6) ? (enc_w + l * 32768) : (dec_w + (l - 6) * 32768);
    g_Wt[idx] = w[(c * 128 + (k >> 1)) * 2 + (k & 1)];
}

__global__ void k_wA(const float* __restrict__ enc_w, const float* __restrict__ dec_w) {
    int idx = blockIdx.x * 256 + threadIdx.x;
    if (idx >= 12 * 128 * 256) return;
    int l = idx / 32768;
    int r = idx - l * 32768;
    int c = r >> 8, k = r & 255;
    const float* w = (l < 6) ? (enc_w + l * 32768) : (dec_w + (l - 6) * 32768);
    float v = w[(c * 128 + (k >> 1)) * 2 + (k & 1)];
    __nv_bfloat16 h = __float2bfloat16(v);
    g_WA[((l * 2 + 0) * 128 + c) * 256 + k] = h;
    g_WA[((l * 2 + 1) * 128 + c) * 256 + k] = __float2bfloat16(v - __bfloat162float(h));
}

__global__ void k_fbA(const float* __restrict__ fb) {
    int idx = blockIdx.x * 256 + threadIdx.x;
    if (idx >= 128 * 512) return;
    float v = fb[idx];
    __nv_bfloat16 h = __float2bfloat16(v);
    g_fbA[idx] = h;
    g_fbA[65536 + idx] = __float2bfloat16(v - __bfloat162float(h));
}

__global__ void k_upwT(const float* __restrict__ up_w) {
    int idx = blockIdx.x * 256 + threadIdx.x;
    if (idx >= 128 * 2048) return;
    int c = idx >> 11, u = idx & 2047;
    g_upwT[idx] = up_w[u * 128 + c];
}

__global__ void k_upA(const float* __restrict__ up_w) {
    int idx = blockIdx.x * 256 + threadIdx.x;
    if (idx >= NU * 128) return;
    g_upA[idx] = __float2bfloat16(up_w[idx]);
}

__global__ void k_xp(const float* __restrict__ x) {
    int idx = blockIdx.x * 256 + threadIdx.x;
    if (idx >= NB * XP) return;
    int b = idx / XP, w = idx - b * XP;
    g_xp[idx] = (w >= GOF && w < NT + GOF) ? x[b * NT + (w - GOF)] : 0.f;
}

__global__ void k_guard() {
    int idx = blockIdx.x * 256 + threadIdx.x;
    int half = NB * NC * 512;
    if (idx >= 2 * half) return;
    float* buf = (idx < half) ? g_bufA : g_bufB;
    int r = (idx < half) ? idx : idx - half;
    int row = r >> 9, w = r & 511;
    int pos = (w < 256) ? w : (NT + 256 + (w - 256));
    buf[row * NTP + pos] = 0.f;
}

// ---------------- filterbank analysis via mma (bf16x3, K=512) ----------------
__global__ void __launch_bounds__(256, 2) k_fb_mma() {
    __shared__ __align__(16) __nv_bfloat16 Ah[128][24];
    __shared__ __align__(16) __nv_bfloat16 Al[128][24];
    __shared__ __align__(16) __nv_bfloat16 Bh[16][136];
    __shared__ __align__(16) __nv_bfloat16 Bl[16][136];
    int tid = threadIdx.x;
    int b = blockIdx.y, t0 = blockIdx.x * 128;
    int w = tid >> 5, lane = tid & 31;
    int wu = w >> 1, wt = w & 1;
    int q = lane >> 3, r = lane & 7;
    const float* xb = g_xp + b * XP;

    float acc[2][8][4];
#pragma unroll
    for (int mi = 0; mi < 2; mi++)
#pragma unroll
        for (int ni = 0; ni < 8; ni++)
#pragma unroll
            for (int v = 0; v < 4; v++) acc[mi][ni][v] = 0.f;

    unsigned aA[2], bA[8];
#pragma unroll
    for (int mi = 0; mi < 2; mi++)
        aA[mi] = (unsigned)__cvta_generic_to_shared(
            &Ah[wu * 32 + mi * 16 + (q & 1) * 8 + r][(q >> 1) * 8]);
#pragma unroll
    for (int ni = 0; ni < 8; ni++)
        bA[ni] = (unsigned)__cvta_generic_to_shared(&Bh[lane & 15][wt * 64 + ni * 8]);
    unsigned dA = (unsigned)__cvta_generic_to_shared(&Al[0][0]) -
                  (unsigned)__cvta_generic_to_shared(&Ah[0][0]);
    unsigned dB = (unsigned)__cvta_generic_to_shared(&Bl[0][0]) -
                  (unsigned)__cvta_generic_to_shared(&Bh[0][0]);

    int brow = tid >> 4, bcb = (tid & 15) * 8;
    int arow = tid >> 1, ahalf = (tid & 1) * 8;

    float vr[8];
    {
        const float* src = xb + t0 + brow + bcb;
#pragma unroll
        for (int j = 0; j < 8; j++) vr[j] = src[j];
    }
    for (int ck = 0; ck < 32; ck++) {
        int kc = ck * 16;
        if (ck) __syncthreads();
        cp16(&Ah[arow][ahalf], g_fbA + arow * 512 + kc + ahalf);
        cp16(&Al[arow][ahalf], g_fbA + 65536 + arow * 512 + kc + ahalf);
        CP_COMMIT();
#pragma unroll
        for (int jj = 0; jj < 4; jj++) {
            float v0 = vr[2 * jj], v1 = vr[2 * jj + 1];
            float h0 = __bfloat162float(__float2bfloat16(v0));
            float h1 = __bfloat162float(__float2bfloat16(v1));
            *(unsigned*)&Bh[brow][bcb + 2 * jj] = pkbf(v0, v1);
            *(unsigned*)&Bl[brow][bcb + 2 * jj] = pkbf(v0 - h0, v1 - h1);
        }
        if (ck + 1 < 32) {
            const float* src = xb + t0 + kc + 16 + brow + bcb;
#pragma unroll
            for (int j = 0; j < 8; j++) vr[j] = src[j];
        }
        CP_WAIT0(); __syncthreads();
        unsigned bq[8][2], af[2][4];
#pragma unroll
        for (int ni = 0; ni < 8; ni++) ldmB2t(bq[ni], bA[ni]);
#pragma unroll
        for (int mi = 0; mi < 2; mi++) ldmA4(af[mi], aA[mi]);
#pragma unroll
        for (int mi = 0; mi < 2; mi++)
#pragma unroll
            for (int ni = 0; ni < 8; ni++) mma16816(acc[mi][ni], af[mi], bq[ni]);
#pragma unroll
        for (int mi = 0; mi < 2; mi++) ldmA4(af[mi], aA[mi] + dA);
#pragma unroll
        for (int mi = 0; mi < 2; mi++)
#pragma unroll
            for (int ni = 0; ni < 8; ni++) mma16816(acc[mi][ni], af[mi], bq[ni]);
#pragma unroll
        for (int ni = 0; ni < 8; ni++) ldmB2t(bq[ni], bA[ni] + dB);
#pragma unroll
        for (int mi = 0; mi < 2; mi++) ldmA4(af[mi], aA[mi]);
#pragma unroll
        for (int mi = 0; mi < 2; mi++)
#pragma unroll
            for (int ni = 0; ni < 8; ni++) mma16816(acc[mi][ni], af[mi], bq[ni]);
    }
    int gid = lane >> 2, tig = lane & 3;
#pragma unroll
    for (int mi = 0; mi < 2; mi++) {
        int c = wu * 32 + mi * 16 + gid;
        float* y0 = g_bufA + (b * NC + c) * NTP + GOF;
        float* y8 = y0 + 8 * NTP;
#pragma unroll
        for (int ni = 0; ni < 8; ni++) {
            int t = t0 + wt * 64 + ni * 8 + tig * 2;
            *(float2*)(y0 + t) = make_float2(acc[mi][ni][0], acc[mi][ni][1]);
            *(float2*)(y8 + t) = make_float2(acc[mi][ni][2], acc[mi][ni][3]);
        }
    }
}

// ---------------- residual dilated layer via mma (bf16x3, K=256, sparse) ----------------
__global__ void __launch_bounds__(256, 2) k_layer_mma(int srcIsA, int lidx,
                                                      const float* __restrict__ bias,
                                                      int o0, int o1, int sparse, int lvl) {
    __shared__ __align__(16) __nv_bfloat16 Ah[128][24];
    __shared__ __align__(16) __nv_bfloat16 Al[128][24];
    __shared__ __align__(16) __nv_bfloat16 Bh[16][136];
    __shared__ __align__(16) __nv_bfloat16 Bl[16][136];
    const float* X = srcIsA ? g_bufA : g_bufB;
    float* Y = srcIsA ? g_bufB : g_bufA;
    int tid = threadIdx.x;
    int b = blockIdx.y, blk = blockIdx.x, t0 = blk * 128;

    if (sparse && !g_act[b * 256 + blk]) {
        int tx = tid & 15, ty = tid >> 4;
#pragma unroll
        for (int i = 0; i < 8; i++) {
            float v = g_base[(lvl + 1) * 128 + ty * 8 + i];
#pragma unroll
            for (int j = 0; j < 8; j++) {
                int t = t0 + ((j < 4) ? (tx * 4 + j) : (64 + tx * 4 + j - 4));
                Y[(b * NC + ty * 8 + i) * NTP + GOF + t] = v;
            }
        }
        return;
    }

    int w = tid >> 5, lane = tid & 31;
    int wu = w >> 1, wt = w & 1;
    int q = lane >> 3, r = lane & 7;
    const float* Xb = X + b * NC * NTP;
    int dOff = o1 - o0;
    const __nv_bfloat16* WAh = g_WA + (size_t)(lidx * 2 + 0) * 32768;
    const __nv_bfloat16* WAl = g_WA + (size_t)(lidx * 2 + 1) * 32768;

    float acc[2][8][4];
#pragma unroll
    for (int mi = 0; mi < 2; mi++)
#pragma unroll
        for (int ni = 0; ni < 8; ni++)
#pragma unroll
            for (int v = 0; v < 4; v++) acc[mi][ni][v] = 0.f;

    unsigned aA[2], bA[8];
#pragma unroll
    for (int mi = 0; mi < 2; mi++)
        aA[mi] = (unsigned)__cvta_generic_to_shared(
            &Ah[wu * 32 + mi * 16 + (q & 1) * 8 + r][(q >> 1) * 8]);
#pragma unroll
    for (int ni = 0; ni < 8; ni++)
        bA[ni] = (unsigned)__cvta_generic_to_shared(&Bh[lane & 15][wt * 64 + ni * 8]);
    unsigned dA = (unsigned)__cvta_generic_to_shared(&Al[0][0]) -
                  (unsigned)__cvta_generic_to_shared(&Ah[0][0]);
    unsigned dB = (unsigned)__cvta_generic_to_shared(&Bl[0][0]) -
                  (unsigned)__cvta_generic_to_shared(&Bh[0][0]);

    int brow = tid >> 4, bcb = (tid & 15) * 8;
    int arow = tid >> 1, ahalf = (tid & 1) * 8;

    float vr[8];
    {
        int k = brow;
        const float* src = Xb + (k >> 1) * NTP + GOF + t0 + o0 + (k & 1) * dOff + bcb;
#pragma unroll
        for (int j = 0; j < 8; j++) vr[j] = src[j];
    }
    for (int ck = 0; ck < 16; ck++) {
        int kc = ck * 16;
        if (ck) __syncthreads();
        cp16(&Ah[arow][ahalf], WAh + arow * 256 + kc + ahalf);
        cp16(&Al[arow][ahalf], WAl + arow * 256 + kc + ahalf);
        CP_COMMIT();
#pragma unroll
        for (int jj = 0; jj < 4; jj++) {
            float v0 = vr[2 * jj], v1 = vr[2 * jj + 1];
            float h0 = __bfloat162float(__float2bfloat16(v0));
            float h1 = __bfloat162float(__float2bfloat16(v1));
            *(unsigned*)&Bh[brow][bcb + 2 * jj] = pkbf(v0, v1);
            *(unsigned*)&Bl[brow][bcb + 2 * jj] = pkbf(v0 - h0, v1 - h1);
        }
        if (ck + 1 < 16) {
            int k = kc + 16 + brow;
            const float* src = Xb + (k >> 1) * NTP + GOF + t0 + o0 + (k & 1) * dOff + bcb;
#pragma unroll
            for (int j = 0; j < 8; j++) vr[j] = src[j];
        }
        CP_WAIT0(); __syncthreads();
        unsigned bq[8][2], af[2][4];
#pragma unroll
        for (int ni = 0; ni < 8; ni++) ldmB2t(bq[ni], bA[ni]);
#pragma unroll
        for (int mi = 0; mi < 2; mi++) ldmA4(af[mi], aA[mi]);
#pragma unroll
        for (int mi = 0; mi < 2; mi++)
#pragma unroll
            for (int ni = 0; ni < 8; ni++) mma16816(acc[mi][ni], af[mi], bq[ni]);
#pragma unroll
        for (int mi = 0; mi < 2; mi++) ldmA4(af[mi], aA[mi] + dA);
#pragma unroll
        for (int mi = 0; mi < 2; mi++)
#pragma unroll
            for (int ni = 0; ni < 8; ni++) mma16816(acc[mi][ni], af[mi], bq[ni]);
#pragma unroll
        for (int ni = 0; ni < 8; ni++) ldmB2t(bq[ni], bA[ni] + dB);
#pragma unroll
        for (int mi = 0; mi < 2; mi++) ldmA4(af[mi], aA[mi]);
#pragma unroll
        for (int mi = 0; mi < 2; mi++)
#pragma unroll
            for (int ni = 0; ni < 8; ni++) mma16816(acc[mi][ni], af[mi], bq[ni]);
    }
    int gid = lane >> 2, tig = lane & 3;
#pragma unroll
    for (int mi = 0; mi < 2; mi++) {
        int c = wu * 32 + mi * 16 + gid;
        float bi0 = bias[c], bi8 = bias[c + 8];
        const float* x0 = Xb + c * NTP + GOF;
        const float* x8 = x0 + 8 * NTP;
        float* y0 = Y + (b * NC + c) * NTP + GOF;
        float* y8 = y0 + 8 * NTP;
#pragma unroll
        for (int ni = 0; ni < 8; ni++) {
            int t = t0 + wt * 64 + ni * 8 + tig * 2;
            float h0 = acc[mi][ni][0] + bi0; h0 = (h0 > 0.f) ? h0 : 0.2f * h0;
            float h1 = acc[mi][ni][1] + bi0; h1 = (h1 > 0.f) ? h1 : 0.2f * h1;
            float h2 = acc[mi][ni][2] + bi8; h2 = (h2 > 0.f) ? h2 : 0.2f * h2;
            float h3 = acc[mi][ni][3] + bi8; h3 = (h3 > 0.f) ? h3 : 0.2f * h3;
            float2 xa = *(const float2*)(x0 + t);
            float2 xb2 = *(const float2*)(x8 + t);
            *(float2*)(y0 + t) = make_float2(xa.x + h0, xa.y + h1);
            *(float2*)(y8 + t) = make_float2(xb2.x + h2, xb2.y + h3);
        }
    }
}

// ---------------- subsampled up-projection ----------------
__global__ void __launch_bounds__(256) k_sub(const float* __restrict__ up_b) {
    __shared__ float es[16][128];
    int b = blockIdx.z;
    int u = blockIdx.x * 256 + threadIdx.x;
    int ts0 = blockIdx.y * 16;
    const float* E = g_bufA + b * NC * NTP + GOF;
    for (int i = threadIdx.x; i < 16 * 128; i += 256) {
        int tsl = i >> 7, c = i & 127;
        es[tsl][c] = E[c * NTP + (ts0 + tsl) * 64];
    }
    __syncthreads();
    float acc[16];
    float bi = up_b[u];
#pragma unroll
    for (int j = 0; j < 16; j++) acc[j] = bi;
    for (int c = 0; c < 128; c++) {
        float w = g_upwT[c * 2048 + u];
#pragma unroll
        for (int j = 0; j < 16; j++) acc[j] += w * es[j][c];
    }
#pragma unroll
    for (int j = 0; j < 16; j++)
        g_ysub[(b * 2048 + u) * 512 + ts0 + j] = acc[j];
}

__device__ __forceinline__ unsigned f2ord(float v) {
    unsigned u = __float_as_uint(v);
    return (u & 0x80000000u) ? ~u : (u | 0x80000000u);
}
__device__ __forceinline__ float ord2f(unsigned k) {
    unsigned u = (k & 0x80000000u) ? (k ^ 0x80000000u) : ~k;
    return __uint_as_float(u);
}

__global__ void k_thresh() {
    __shared__ unsigned hist[2048];
    __shared__ int s_b1, s_m;
    int b = blockIdx.x, tid = threadIdx.x;
    const float* ys = g_ysub + b * 2048 * 512;
    for (int i = tid; i < 2048; i += 1024) hist[i] = 0;
    __syncthreads();
    for (int i = tid; i < 2048 * 512; i += 1024)
        atomicAdd(&hist[f2ord(ys[i]) >> 21], 1u);
    __syncthreads();
    if (tid == 0) {
        unsigned acc = 0;
        int b1 = 0, m = 64;
        for (int i = 2047; i >= 0; i--) {
            acc += hist[i];
            if (acc >= 64) { b1 = i; m = 64 - (int)(acc - hist[i]); break; }
        }
        s_b1 = b1; s_m = m;
    }
    __syncthreads();
    int b1 = s_b1, m = s_m;
    for (int i = tid; i < 2048; i += 1024) hist[i] = 0;
    __syncthreads();
    for (int i = tid; i < 2048 * 512; i += 1024) {
        unsigned key = f2ord(ys[i]);
        if ((int)(key >> 21) == b1) atomicAdd(&hist[(key >> 10) & 2047], 1u);
    }
    __syncthreads();
    if (tid == 0) {
        unsigned acc = 0;
        int b2 = 0;
        for (int i = 2047; i >= 0; i--) {
            acc += hist[i];
            if ((int)acc >= m) { b2 = i; break; }
        }
        unsigned tk = ((unsigned)b1 << 21) | ((unsigned)b2 << 10);
        if (tk >= (1u << 10)) tk -= (1u << 10);
        float tf = ord2f(tk);
        g_thresh[b] = tf - 0.05f * fabsf(tf);
        g_candCnt[b] = 0;
    }
}

// ---------------- up-projection via mma.sync (single-plane bf16, K=128) ----------------
__global__ void __launch_bounds__(256, 2) k_up_mma(const float* __restrict__ up_b) {
    __shared__ __align__(16) __nv_bfloat16 Ah[128][136];
    __shared__ __align__(16) __nv_bfloat16 Bh[16][136];
    int tid = threadIdx.x;
    int b = blockIdx.z;
    int u0 = blockIdx.y * 128;
    int t0 = blockIdx.x * 128;
    int w = tid >> 5, lane = tid & 31;
    int wu = w >> 1, wt = w & 1;
    int q = lane >> 3, r = lane & 7;

    for (int i = tid; i < 2048; i += 256) {
        int row = i >> 4, c8 = (i & 15) * 8;
        cp16(&Ah[row][c8], g_upA + (u0 + row) * 128 + c8);
    }
    CP_COMMIT();

    float acc[2][8][4];
#pragma unroll
    for (int mi = 0; mi < 2; mi++)
#pragma unroll
        for (int ni = 0; ni < 8; ni++)
#pragma unroll
            for (int v = 0; v < 4; v++) acc[mi][ni][v] = 0.f;

    unsigned aA[2], bA[8];
#pragma unroll
    for (int mi = 0; mi < 2; mi++)
        aA[mi] = (unsigned)__cvta_generic_to_shared(
            &Ah[wu * 32 + mi * 16 + (q & 1) * 8 + r][(q >> 1) * 8]);
#pragma unroll
    for (int ni = 0; ni < 8; ni++)
        bA[ni] = (unsigned)__cvta_generic_to_shared(&Bh[lane & 15][wt * 64 + ni * 8]);

    const float* Xb = g_bufA + b * NC * NTP + GOF + t0;
    int brow = tid >> 4, bcb = (tid & 15) * 8;

    float vr[8];
    {
        const float* src = Xb + brow * NTP + bcb;
#pragma unroll
        for (int j = 0; j < 8; j++) vr[j] = src[j];
    }
    CP_WAIT0();
    __syncthreads();

    for (int ck = 0; ck < 8; ck++) {
        if (ck) __syncthreads();
#pragma unroll
        for (int jj = 0; jj < 4; jj++)
            *(unsigned*)&Bh[brow][bcb + 2 * jj] = pkbf(vr[2 * jj], vr[2 * jj + 1]);
        if (ck + 1 < 8) {
            const float* src = Xb + ((ck + 1) * 16 + brow) * NTP + bcb;
#pragma unroll
            for (int j = 0; j < 8; j++) vr[j] = src[j];
        }
        __syncthreads();
        unsigned bq[8][2], af[2][4];
#pragma unroll
        for (int ni = 0; ni < 8; ni++) ldmB2t(bq[ni], bA[ni]);
#pragma unroll
        for (int mi = 0; mi < 2; mi++) ldmA4(af[mi], aA[mi] + ck * 32);
#pragma unroll
        for (int mi = 0; mi < 2; mi++)
#pragma unroll
            for (int ni = 0; ni < 8; ni++) mma16816(acc[mi][ni], af[mi], bq[ni]);
    }

    float T0 = g_thresh[b];
    int gid = lane >> 2, tig = lane & 3;
#pragma unroll
    for (int mi = 0; mi < 2; mi++) {
        int ub = u0 + wu * 32 + mi * 16 + gid;
        float bi0 = up_b[ub];
        float bi8 = up_b[ub + 8];
#pragma unroll
        for (int ni = 0; ni < 8; ni++) {
            int tb = t0 + wt * 64 + ni * 8 + tig * 2;
            float vv[4] = {acc[mi][ni][0] + bi0, acc[mi][ni][1] + bi0,
                           acc[mi][ni][2] + bi8, acc[mi][ni][3] + bi8};
            int uu[4] = {ub, ub, ub + 8, ub + 8};
            int tt[4] = {tb, tb + 1, tb, tb + 1};
#pragma unroll
            for (int v = 0; v < 4; v++) {
                if (vv[v] >= T0) {
                    int idx = atomicAdd(&g_candCnt[b], 1);
                    if (idx < CAP) {
                        g_candVal[b * CAP + idx] = vv[v];
                        g_candPack[b * CAP + idx] =
                            ((unsigned)uu[v] << 16) | (unsigned)tt[v];
                    }
                }
            }
        }
    }
}

__global__ void k_rescoreAll(const float* __restrict__ up_w, const float* __restrict__ up_b) {
    int b = blockIdx.y;
    int cnt = g_candCnt[b];
    if (cnt > CAP) cnt = CAP;
    int warpId = blockIdx.x * 8 + (threadIdx.x >> 5);
    int nw = gridDim.x * 8;
    int lane = threadIdx.x & 31;
    for (int i = warpId; i < cnt; i += nw) {
        unsigned pack = g_candPack[b * CAP + i];
        int u = (int)(pack >> 16), t = (int)(pack & 0xFFFFu);
        float s = 0.f;
#pragma unroll
        for (int c = lane; c < 128; c += 32)
            s += up_w[u * 128 + c] * g_bufA[(b * NC + c) * NTP + GOF + t];
#pragma unroll
        for (int o = 16; o; o >>= 1) s += __shfl_xor_sync(0xFFFFFFFFu, s, o);
        if (lane == 0) g_candVal[b * CAP + i] = s + up_b[u];
    }
}

__global__ void k_select() {
    __shared__ ull keys[5632];
    __shared__ ull red[256];
    int b = blockIdx.x, tid = threadIdx.x;
    int cnt = g_candCnt[b];
    if (cnt > CAP) cnt = CAP;
    bool useS = (cnt <= 5632);
    if (useS) {
        for (int i = tid; i < cnt; i += 256) {
            unsigned key = f2ord(g_candVal[b * CAP + i]);
            unsigned pack = g_candPack[b * CAP + i];
            keys[i] = ((ull)key << 32) | (ull)(~pack);
        }
    }
    __syncthreads();
    ull prev = 0xFFFFFFFFFFFFFFFFull;
    for (int r = 0; r < 64; r++) {
        ull best = 0;
        if (useS) {
            for (int i = tid; i < cnt; i += 256) {
                ull k64 = keys[i];
                if (k64 < prev && k64 > best) best = k64;
            }
        } else {
            for (int i = tid; i < cnt; i += 256) {
                unsigned key = f2ord(g_candVal[b * CAP + i]);
                unsigned pack = g_candPack[b * CAP + i];
                ull k64 = ((ull)key << 32) | (ull)(~pack);
                if (k64 < prev && k64 > best) best = k64;
            }
        }
        red[tid] = best;
        __syncthreads();
        for (int s = 128; s > 0; s >>= 1) {
            if (tid < s) { if (red[tid + s] > red[tid]) red[tid] = red[tid + s]; }
            __syncthreads();
        }
        best = red[0];
        if (tid == 0) {
            unsigned key = (unsigned)(best >> 32);
            unsigned pack = ~((unsigned)best);
            g_selVal[b * 64 + r] = ord2f(key);
            g_selU[b * 64 + r] = (int)(pack >> 16);
            g_selT[b * 64 + r] = (int)(pack & 0xFFFFu);
        }
        prev = best;
        __syncthreads();
    }
}

__global__ void k_base(const float* __restrict__ down_b, const float* __restrict__ dec_b) {
    __shared__ float cur[128];
    int c = threadIdx.x;
    cur[c] = down_b[c];
    g_base[c] = cur[c];
    __syncthreads();
    for (int l = 0; l < 6; l++) {
        const float* Wt = g_Wt + (6 + l) * 32768;
        float h = dec_b[l * 128 + c];
        for (int ci = 0; ci < 128; ci++)
            h += (Wt[(2 * ci) * 128 + c] + Wt[(2 * ci + 1) * 128 + c]) * cur[ci];
        h = (h > 0.f) ? h : 0.2f * h;
        float nv = cur[c] + h;
        __syncthreads();
        cur[c] = nv;
        g_base[(l + 1) * 128 + c] = nv;
        __syncthreads();
    }
}

__global__ void k_flags() {
    int idx = threadIdx.x;
    if (idx >= NB * 256) return;
    int b = idx >> 8, blk = idx & 255;
    int lo = blk * 128, hi = lo + 127;
    int act = (lo < 123) ? 1 : 0;
    for (int e = 0; e < 64; e++) {
        int s = g_selT[b * 64 + e];
        if (s <= hi && s + 122 >= lo) act = 1;
    }
    g_act[idx] = act;
}

__global__ void k_fill(const float* __restrict__ down_b) {
    int idx = blockIdx.x * 256 + threadIdx.x;
    if (idx >= NB * NC * NT / 4) return;
    int row = idx >> 13, t4 = idx & 8191;
    float v = down_b[row & 127];
    *(float4*)(&g_bufB[row * NTP + GOF + t4 * 4]) = make_float4(v, v, v, v);
}

__global__ void k_scatter(const float* __restrict__ down_w) {
    int tid = threadIdx.x;
    int b = tid >> 7, c = tid & 127;
    float* dst = g_bufB + (b * NC + c) * NTP + GOF;
    for (int e = 0; e < 64; e++) {
        float v = g_selVal[b * 64 + e];
        int u = g_selU[b * 64 + e];
        int t = g_selT[b * 64 + e];
        dst[t] += down_w[c * 2048 + u] * v;
    }
}

// ---------------- sparse synthesis: constant part ----------------
__global__ void k_pref(const float* __restrict__ fb) {
    __shared__ float pr[512];
    int j = threadIdx.x;
    float s = 0.f;
    for (int c = 0; c < 128; c++) s += g_base[768 + c] * fb[c * 512 + j];
    pr[j] = s;
    __syncthreads();
    if (j == 0) {
        float acc = 0.f;
        g_pref[0] = 0.f;
        for (int k = 0; k < 512; k++) { acc += pr[k]; g_pref[k + 1] = acc; }
    }
}

__global__ void k_fillOut(float* __restrict__ out) {
    int idx = blockIdx.x * 256 + threadIdx.x;
    if (idx >= NB * NT) return;
    int t = idx & (NT - 1);
    int jlo = 256 + t - (NT - 1); if (jlo < 0) jlo = 0;
    int jhi = 256 + t; if (jhi > 511) jhi = 511;
    out[idx] = g_pref[jhi + 1] - g_pref[jlo];
}

// ---------------- sparse synthesis: per-active-block correction ----------------
// out[tg] += sum_c sum_col fb[c][t-col] * (D[c][s+col]-base6[c]), tg = s-256+t
__global__ void __launch_bounds__(256) k_corr(const float* __restrict__ fb,
                                              float* __restrict__ out) {
    __shared__ __align__(16) float fbx[8][768];
    __shared__ __align__(16) float dev[8][128];
    int b = blockIdx.y, blk = blockIdx.x;
    if (!g_act[b * 256 + blk]) return;
    int s = blk * 128;
    int tid = threadIdx.x;
    const float* D = g_bufB + b * NC * NTP + GOF;

    // zero pads once (j<128 and j>=640 regions never overwritten)
    for (int i = tid; i < 8 * 256; i += 256) {
        int c = i >> 8, p = i & 255;
        fbx[c][(p < 128) ? p : (512 + p)] = 0.f;
    }

    float a0 = 0.f, a1 = 0.f, a2 = 0.f, a3 = 0.f;
    int t0 = 4 * tid;   // active for tid < 160

    for (int cg = 0; cg < 16; cg++) {
        __syncthreads();
        for (int i = tid; i < 8 * 512; i += 256)
            fbx[i >> 9][128 + (i & 511)] = fb[(cg * 8 + (i >> 9)) * 512 + (i & 511)];
        for (int i = tid; i < 8 * 128; i += 256) {
            int c = i >> 7, col = i & 127;
            dev[c][col] = D[(cg * 8 + c) * NTP + s + col] - g_base[768 + cg * 8 + c];
        }
        __syncthreads();
        if (tid < 160) {
#pragma unroll 2
            for (int c = 0; c < 8; c++) {
                const float* fx = &fbx[c][0];
                const float4* dv4 = (const float4*)&dev[c][0];
                // iterate col4 descending so m0 ascends; slide window
                int m0 = t0 + 128 - 124;                 // col4 = 124 (c4i=31)
                float4 fa = *(const float4*)&fx[m0 - 4];
                for (int c4 = 31; c4 >= 0; c4--) {
                    float4 d4 = dv4[c4];
                    float4 fbv = *(const float4*)&fx[m0];
                    float wm3 = fa.y, wm2 = fa.z, wm1 = fa.w;
                    a0 += fbv.x * d4.x + wm1 * d4.y + wm2 * d4.z + wm3 * d4.w;
                    a1 += fbv.y * d4.x + fbv.x * d4.y + wm1 * d4.z + wm2 * d4.w;
                    a2 += fbv.z * d4.x + fbv.y * d4.y + fbv.x * d4.z + wm1 * d4.w;
                    a3 += fbv.w * d4.x + fbv.z * d4.y + fbv.y * d4.z + fbv.x * d4.w;
                    fa = fbv;
                    m0 += 4;
                }
            }
        }
    }
    if (tid < 160) {
        float av[4] = {a0, a1, a2, a3};
#pragma unroll
        for (int qd = 0; qd < 4; qd++) {
            int t = t0 + qd;
            if (t < 639) {
                int tg = s - 256 + t;
                if (tg >= 0 && tg < NT && av[qd] != 0.f)
                    atomicAdd(&out[b * NT + tg], av[qd]);
            }
        }
    }
}

// ---------------- host driver ----------------
extern "C" void kernel_launch(void* const* d_in, const int* in_sizes, int n_in,
                              void* d_out, int out_size) {
    const float* x      = (const float*)d_in[0];
    const float* fb     = (const float*)d_in[1];
    const float* enc_w  = (const float*)d_in[2];
    const float* enc_b  = (const float*)d_in[3];
    const float* up_w   = (const float*)d_in[4];
    const float* up_b   = (const float*)d_in[5];
    const float* down_w = (const float*)d_in[6];
    const float* down_b = (const float*)d_in[7];
    const float* dec_w  = (const float*)d_in[8];
    const float* dec_b  = (const float*)d_in[9];
    float* out = (float*)d_out;

    static const int dil[6] = {1, 3, 9, 27, 81, 1};

    k_wt<<<(12 * 256 * 128 + 255) / 256, 256>>>(enc_w, dec_w);
    k_wA<<<(12 * 128 * 256 + 255) / 256, 256>>>(enc_w, dec_w);
    k_fbA<<<(128 * 512 + 255) / 256, 256>>>(fb);
    k_upwT<<<(128 * 2048 + 255) / 256, 256>>>(up_w);
    k_upA<<<(NU * 128 + 255) / 256, 256>>>(up_w);
    k_xp<<<(NB * XP + 255) / 256, 256>>>(x);
    k_guard<<<(2 * NB * NC * 512 + 255) / 256, 256>>>();

    k_fb_mma<<<dim3(NT / 128, NB), 256>>>();

    int srcIsA = 1;
    for (int l = 0; l < 6; l++) {
        k_layer_mma<<<dim3(256, NB), 256>>>(srcIsA, l, enc_b + l * 128, 0, dil[l], 0, 0);
        srcIsA ^= 1;
    }

    k_sub<<<dim3(NU / 256, 512 / 16, NB), 256>>>(up_b);
    k_thresh<<<NB, 1024>>>();
    k_up_mma<<<dim3(NT / 128, NU / 128, NB), 256>>>(up_b);
    k_rescoreAll<<<dim3(64, NB), 256>>>(up_w, up_b);
    k_select<<<NB, 256>>>();

    k_base<<<1, 128>>>(down_b, dec_b);
    k_flags<<<1, 512>>>();
    k_fill<<<(NB * NC * NT / 4 + 255) / 256, 256>>>(down_b);
    k_scatter<<<1, 256>>>(down_w);

    srcIsA = 0;
    for (int l = 0; l < 6; l++) {
        k_layer_mma<<<dim3(256, NB), 256>>>(srcIsA, 6 + l, dec_b + l * 128, -dil[l], 0, 1, l);
        srcIsA ^= 1;
    }
    // decoder output in bufB

    k_pref<<<1, 512>>>(fb);
    k_fillOut<<<(NB * NT + 255) / 256, 256>>>(out);
    k_corr<<<dim3(256, NB), 256>>>(fb, out);
    (void)in_sizes; (void)n_in; (void)out_size;
}

// round 12
// speedup vs baseline: 1.6111x; 1.1133x over previous
#include <cuda_runtime.h>
#include <cuda_bf16.h>
#include <cstdint>

#define NB 2
#define NC 128
#define NU 2048
#define NZK 64
#define NT 32768
#define NTP (NT + 512)
#define GOF 256
#define XP  (NT + 512)
#define CAP (1<<18)

typedef unsigned long long ull;

static __device__ __align__(16) float g_bufA[NB*NC*NTP];
static __device__ __align__(16) float g_bufB[NB*NC*NTP];
static __device__ __align__(16) float g_Wt[12*256*128];
static __device__ __align__(16) float g_upwT[128*2048];
static __device__ __align__(16) float g_xp[NB*XP];
static __device__ __align__(16) __nv_bfloat16 g_WA[12*2*128*256];
static __device__ __align__(16) __nv_bfloat16 g_fbA[2*128*512];
static __device__ __align__(16) __nv_bfloat16 g_upA[NU*128];
static __device__ __align__(16) __nv_bfloat16 g_xB[(long)NB*NT*128];  // [b][t][c] bf16
static __device__ float g_ysub[NB*2048*512];
static __device__ float g_thresh[NB];
static __device__ int   g_candCnt[NB];
static __device__ float g_candVal[NB*CAP];
static __device__ unsigned g_candPack[NB*CAP];
static __device__ float g_selVal[NB*NZK];
static __device__ int   g_selU[NB*NZK];
static __device__ int   g_selT[NB*NZK];
static __device__ float g_base[7*128];
static __device__ int   g_act[NB*256];
static __device__ float g_pref[513];

__device__ __forceinline__ void cp16(void* dst, const void* src) {
    unsigned d = (unsigned)__cvta_generic_to_shared(dst);
    asm volatile("cp.async.cg.shared.global [%0], [%1], 16;\n" :: "r"(d), "l"(src));
}
#define CP_COMMIT() asm volatile("cp.async.commit_group;\n")
#define CP_WAIT0()  asm volatile("cp.async.wait_group 0;\n")

__device__ __forceinline__ void ldmA4(unsigned* a, unsigned addr) {
    asm volatile("ldmatrix.sync.aligned.m8n8.x4.shared.b16 {%0,%1,%2,%3}, [%4];"
                 : "=r"(a[0]), "=r"(a[1]), "=r"(a[2]), "=r"(a[3]) : "r"(addr));
}
__device__ __forceinline__ void ldmB2t(unsigned* bq, unsigned addr) {
    asm volatile("ldmatrix.sync.aligned.m8n8.x2.trans.shared.b16 {%0,%1}, [%2];"
                 : "=r"(bq[0]), "=r"(bq[1]) : "r"(addr));
}
__device__ __forceinline__ void ldmB2(unsigned* bq, unsigned addr) {
    asm volatile("ldmatrix.sync.aligned.m8n8.x2.shared.b16 {%0,%1}, [%2];"
                 : "=r"(bq[0]), "=r"(bq[1]) : "r"(addr));
}
__device__ __forceinline__ void mma16816(float* c, const unsigned* a, const unsigned* bq) {
    asm volatile("mma.sync.aligned.m16n8k16.row.col.f32.bf16.bf16.f32 "
                 "{%0,%1,%2,%3}, {%4,%5,%6,%7}, {%8,%9}, {%0,%1,%2,%3};"
                 : "+f"(c[0]), "+f"(c[1]), "+f"(c[2]), "+f"(c[3])
                 : "r"(a[0]), "r"(a[1]), "r"(a[2]), "r"(a[3]), "r"(bq[0]), "r"(bq[1]));
}
__device__ __forceinline__ unsigned pkbf(float a, float b) {
    unsigned lo = (unsigned)__bfloat16_as_ushort(__float2bfloat16(a));
    unsigned hi = (unsigned)__bfloat16_as_ushort(__float2bfloat16(b));
    return lo | (hi << 16);
}

__global__ void k_wt(const float* __restrict__ enc_w, const float* __restrict__ dec_w) {
    int idx = blockIdx.x * 256 + threadIdx.x;
    if (idx >= 12 * 256 * 128) return;
    int l = idx / 32768;
    int r = idx - l * 32768;
    int k = r >> 7, c = r & 127;
    const float* w = (l < 6) ? (enc_w + l * 32768) : (dec_w + (l - 6) * 32768);
    g_Wt[idx] = w[(c * 128 + (k >> 1)) * 2 + (k & 1)];
}

__global__ void k_wA(const float* __restrict__ enc_w, const float* __restrict__ dec_w) {
    int idx = blockIdx.x * 256 + threadIdx.x;
    if (idx >= 12 * 128 * 256) return;
    int l = idx / 32768;
    int r = idx - l * 32768;
    int c = r >> 8, k = r & 255;
    const float* w = (l < 6) ? (enc_w + l * 32768) : (dec_w + (l - 6) * 32768);
    float v = w[(c * 128 + (k >> 1)) * 2 + (k & 1)];
    __nv_bfloat16 h = __float2bfloat16(v);
    g_WA[((l * 2 + 0) * 128 + c) * 256 + k] = h;
    g_WA[((l * 2 + 1) * 128 + c) * 256 + k] = __float2bfloat16(v - __bfloat162float(h));
}

__global__ void k_fbA(const float* __restrict__ fb) {
    int idx = blockIdx.x * 256 + threadIdx.x;
    if (idx >= 128 * 512) return;
    float v = fb[idx];
    __nv_bfloat16 h = __float2bfloat16(v);
    g_fbA[idx] = h;
    g_fbA[65536 + idx] = __float2bfloat16(v - __bfloat162float(h));
}

__global__ void k_upwT(const float* __restrict__ up_w) {
    int idx = blockIdx.x * 256 + threadIdx.x;
    if (idx >= 128 * 2048) return;
    int c = idx >> 11, u = idx & 2047;
    g_upwT[idx] = up_w[u * 128 + c];
}

__global__ void k_upA(const float* __restrict__ up_w) {
    int idx = blockIdx.x * 256 + threadIdx.x;
    if (idx >= NU * 128) return;
    g_upA[idx] = __float2bfloat16(up_w[idx]);
}

__global__ void k_xp(const float* __restrict__ x) {
    int idx = blockIdx.x * 256 + threadIdx.x;
    if (idx >= NB * XP) return;
    int b = idx / XP, w = idx - b * XP;
    g_xp[idx] = (w >= GOF && w < NT + GOF) ? x[b * NT + (w - GOF)] : 0.f;
}

__global__ void k_guard() {
    int idx = blockIdx.x * 256 + threadIdx.x;
    int half = NB * NC * 512;
    if (idx >= 2 * half) return;
    float* buf = (idx < half) ? g_bufA : g_bufB;
    int r = (idx < half) ? idx : idx - half;
    int row = r >> 9, w = r & 511;
    int pos = (w < 256) ? w : (NT + 256 + (w - 256));
    buf[row * NTP + pos] = 0.f;
}

// ---------------- filterbank analysis via mma (bf16x3, K=512) ----------------
__global__ void __launch_bounds__(256, 2) k_fb_mma() {
    __shared__ __align__(16) __nv_bfloat16 Ah[128][24];
    __shared__ __align__(16) __nv_bfloat16 Al[128][24];
    __shared__ __align__(16) __nv_bfloat16 Bh[16][136];
    __shared__ __align__(16) __nv_bfloat16 Bl[16][136];
    int tid = threadIdx.x;
    int b = blockIdx.y, t0 = blockIdx.x * 128;
    int w = tid >> 5, lane = tid & 31;
    int wu = w >> 1, wt = w & 1;
    int q = lane >> 3, r = lane & 7;
    const float* xb = g_xp + b * XP;

    float acc[2][8][4];
#pragma unroll
    for (int mi = 0; mi < 2; mi++)
#pragma unroll
        for (int ni = 0; ni < 8; ni++)
#pragma unroll
            for (int v = 0; v < 4; v++) acc[mi][ni][v] = 0.f;

    unsigned aA[2], bA[8];
#pragma unroll
    for (int mi = 0; mi < 2; mi++)
        aA[mi] = (unsigned)__cvta_generic_to_shared(
            &Ah[wu * 32 + mi * 16 + (q & 1) * 8 + r][(q >> 1) * 8]);
#pragma unroll
    for (int ni = 0; ni < 8; ni++)
        bA[ni] = (unsigned)__cvta_generic_to_shared(&Bh[lane & 15][wt * 64 + ni * 8]);
    unsigned dA = (unsigned)__cvta_generic_to_shared(&Al[0][0]) -
                  (unsigned)__cvta_generic_to_shared(&Ah[0][0]);
    unsigned dB = (unsigned)__cvta_generic_to_shared(&Bl[0][0]) -
                  (unsigned)__cvta_generic_to_shared(&Bh[0][0]);

    int brow = tid >> 4, bcb = (tid & 15) * 8;
    int arow = tid >> 1, ahalf = (tid & 1) * 8;

    float vr[8];
    {
        const float* src = xb + t0 + brow + bcb;
#pragma unroll
        for (int j = 0; j < 8; j++) vr[j] = src[j];
    }
    for (int ck = 0; ck < 32; ck++) {
        int kc = ck * 16;
        if (ck) __syncthreads();
        cp16(&Ah[arow][ahalf], g_fbA + arow * 512 + kc + ahalf);
        cp16(&Al[arow][ahalf], g_fbA + 65536 + arow * 512 + kc + ahalf);
        CP_COMMIT();
#pragma unroll
        for (int jj = 0; jj < 4; jj++) {
            float v0 = vr[2 * jj], v1 = vr[2 * jj + 1];
            float h0 = __bfloat162float(__float2bfloat16(v0));
            float h1 = __bfloat162float(__float2bfloat16(v1));
            *(unsigned*)&Bh[brow][bcb + 2 * jj] = pkbf(v0, v1);
            *(unsigned*)&Bl[brow][bcb + 2 * jj] = pkbf(v0 - h0, v1 - h1);
        }
        if (ck + 1 < 32) {
            const float* src = xb + t0 + kc + 16 + brow + bcb;
#pragma unroll
            for (int j = 0; j < 8; j++) vr[j] = src[j];
        }
        CP_WAIT0(); __syncthreads();
        unsigned bq[8][2], af[2][4];
#pragma unroll
        for (int ni = 0; ni < 8; ni++) ldmB2t(bq[ni], bA[ni]);
#pragma unroll
        for (int mi = 0; mi < 2; mi++) ldmA4(af[mi], aA[mi]);
#pragma unroll
        for (int mi = 0; mi < 2; mi++)
#pragma unroll
            for (int ni = 0; ni < 8; ni++) mma16816(acc[mi][ni], af[mi], bq[ni]);
#pragma unroll
        for (int mi = 0; mi < 2; mi++) ldmA4(af[mi], aA[mi] + dA);
#pragma unroll
        for (int mi = 0; mi < 2; mi++)
#pragma unroll
            for (int ni = 0; ni < 8; ni++) mma16816(acc[mi][ni], af[mi], bq[ni]);
#pragma unroll
        for (int ni = 0; ni < 8; ni++) ldmB2t(bq[ni], bA[ni] + dB);
#pragma unroll
        for (int mi = 0; mi < 2; mi++) ldmA4(af[mi], aA[mi]);
#pragma unroll
        for (int mi = 0; mi < 2; mi++)
#pragma unroll
            for (int ni = 0; ni < 8; ni++) mma16816(acc[mi][ni], af[mi], bq[ni]);
    }
    int gid = lane >> 2, tig = lane & 3;
#pragma unroll
    for (int mi = 0; mi < 2; mi++) {
        int c = wu * 32 + mi * 16 + gid;
        float* y0 = g_bufA + (b * NC + c) * NTP + GOF;
        float* y8 = y0 + 8 * NTP;
#pragma unroll
        for (int ni = 0; ni < 8; ni++) {
            int t = t0 + wt * 64 + ni * 8 + tig * 2;
            *(float2*)(y0 + t) = make_float2(acc[mi][ni][0], acc[mi][ni][1]);
            *(float2*)(y8 + t) = make_float2(acc[mi][ni][2], acc[mi][ni][3]);
        }
    }
}

// ---------------- residual dilated layer via mma (bf16x3, K=256, sparse) ----------------
__global__ void __launch_bounds__(256, 2) k_layer_mma(int srcIsA, int lidx,
                                                      const float* __restrict__ bias,
                                                      int o0, int o1, int sparse, int lvl) {
    __shared__ __align__(16) __nv_bfloat16 Ah[128][24];
    __shared__ __align__(16) __nv_bfloat16 Al[128][24];
    __shared__ __align__(16) __nv_bfloat16 Bh[16][136];
    __shared__ __align__(16) __nv_bfloat16 Bl[16][136];
    const float* X = srcIsA ? g_bufA : g_bufB;
    float* Y = srcIsA ? g_bufB : g_bufA;
    int tid = threadIdx.x;
    int b = blockIdx.y, blk = blockIdx.x, t0 = blk * 128;

    if (sparse && !g_act[b * 256 + blk]) {
        int tx = tid & 15, ty = tid >> 4;
#pragma unroll
        for (int i = 0; i < 8; i++) {
            float v = g_base[(lvl + 1) * 128 + ty * 8 + i];
#pragma unroll
            for (int j = 0; j < 8; j++) {
                int t = t0 + ((j < 4) ? (tx * 4 + j) : (64 + tx * 4 + j - 4));
                Y[(b * NC + ty * 8 + i) * NTP + GOF + t] = v;
            }
        }
        return;
    }

    int w = tid >> 5, lane = tid & 31;
    int wu = w >> 1, wt = w & 1;
    int q = lane >> 3, r = lane & 7;
    const float* Xb = X + b * NC * NTP;
    int dOff = o1 - o0;
    const __nv_bfloat16* WAh = g_WA + (size_t)(lidx * 2 + 0) * 32768;
    const __nv_bfloat16* WAl = g_WA + (size_t)(lidx * 2 + 1) * 32768;

    float acc[2][8][4];
#pragma unroll
    for (int mi = 0; mi < 2; mi++)
#pragma unroll
        for (int ni = 0; ni < 8; ni++)
#pragma unroll
            for (int v = 0; v < 4; v++) acc[mi][ni][v] = 0.f;

    unsigned aA[2], bA[8];
#pragma unroll
    for (int mi = 0; mi < 2; mi++)
        aA[mi] = (unsigned)__cvta_generic_to_shared(
            &Ah[wu * 32 + mi * 16 + (q & 1) * 8 + r][(q >> 1) * 8]);
#pragma unroll
    for (int ni = 0; ni < 8; ni++)
        bA[ni] = (unsigned)__cvta_generic_to_shared(&Bh[lane & 15][wt * 64 + ni * 8]);
    unsigned dA = (unsigned)__cvta_generic_to_shared(&Al[0][0]) -
                  (unsigned)__cvta_generic_to_shared(&Ah[0][0]);
    unsigned dB = (unsigned)__cvta_generic_to_shared(&Bl[0][0]) -
                  (unsigned)__cvta_generic_to_shared(&Bh[0][0]);

    int brow = tid >> 4, bcb = (tid & 15) * 8;
    int arow = tid >> 1, ahalf = (tid & 1) * 8;

    float vr[8];
    {
        int k = brow;
        const float* src = Xb + (k >> 1) * NTP + GOF + t0 + o0 + (k & 1) * dOff + bcb;
#pragma unroll
        for (int j = 0; j < 8; j++) vr[j] = src[j];
    }
    for (int ck = 0; ck < 16; ck++) {
        int kc = ck * 16;
        if (ck) __syncthreads();
        cp16(&Ah[arow][ahalf], WAh + arow * 256 + kc + ahalf);
        cp16(&Al[arow][ahalf], WAl + arow * 256 + kc + ahalf);
        CP_COMMIT();
#pragma unroll
        for (int jj = 0; jj < 4; jj++) {
            float v0 = vr[2 * jj], v1 = vr[2 * jj + 1];
            float h0 = __bfloat162float(__float2bfloat16(v0));
            float h1 = __bfloat162float(__float2bfloat16(v1));
            *(unsigned*)&Bh[brow][bcb + 2 * jj] = pkbf(v0, v1);
            *(unsigned*)&Bl[brow][bcb + 2 * jj] = pkbf(v0 - h0, v1 - h1);
        }
        if (ck + 1 < 16) {
            int k = kc + 16 + brow;
            const float* src = Xb + (k >> 1) * NTP + GOF + t0 + o0 + (k & 1) * dOff + bcb;
#pragma unroll
            for (int j = 0; j < 8; j++) vr[j] = src[j];
        }
        CP_WAIT0(); __syncthreads();
        unsigned bq[8][2], af[2][4];
#pragma unroll
        for (int ni = 0; ni < 8; ni++) ldmB2t(bq[ni], bA[ni]);
#pragma unroll
        for (int mi = 0; mi < 2; mi++) ldmA4(af[mi], aA[mi]);
#pragma unroll
        for (int mi = 0; mi < 2; mi++)
#pragma unroll
            for (int ni = 0; ni < 8; ni++) mma16816(acc[mi][ni], af[mi], bq[ni]);
#pragma unroll
        for (int mi = 0; mi < 2; mi++) ldmA4(af[mi], aA[mi] + dA);
#pragma unroll
        for (int mi = 0; mi < 2; mi++)
#pragma unroll
            for (int ni = 0; ni < 8; ni++) mma16816(acc[mi][ni], af[mi], bq[ni]);
#pragma unroll
        for (int ni = 0; ni < 8; ni++) ldmB2t(bq[ni], bA[ni] + dB);
#pragma unroll
        for (int mi = 0; mi < 2; mi++) ldmA4(af[mi], aA[mi]);
#pragma unroll
        for (int mi = 0; mi < 2; mi++)
#pragma unroll
            for (int ni = 0; ni < 8; ni++) mma16816(acc[mi][ni], af[mi], bq[ni]);
    }
    int gid = lane >> 2, tig = lane & 3;
#pragma unroll
    for (int mi = 0; mi < 2; mi++) {
        int c = wu * 32 + mi * 16 + gid;
        float bi0 = bias[c], bi8 = bias[c + 8];
        const float* x0 = Xb + c * NTP + GOF;
        const float* x8 = x0 + 8 * NTP;
        float* y0 = Y + (b * NC + c) * NTP + GOF;
        float* y8 = y0 + 8 * NTP;
#pragma unroll
        for (int ni = 0; ni < 8; ni++) {
            int t = t0 + wt * 64 + ni * 8 + tig * 2;
            float h0 = acc[mi][ni][0] + bi0; h0 = (h0 > 0.f) ? h0 : 0.2f * h0;
            float h1 = acc[mi][ni][1] + bi0; h1 = (h1 > 0.f) ? h1 : 0.2f * h1;
            float h2 = acc[mi][ni][2] + bi8; h2 = (h2 > 0.f) ? h2 : 0.2f * h2;
            float h3 = acc[mi][ni][3] + bi8; h3 = (h3 > 0.f) ? h3 : 0.2f * h3;
            float2 xa = *(const float2*)(x0 + t);
            float2 xb2 = *(const float2*)(x8 + t);
            *(float2*)(y0 + t) = make_float2(xa.x + h0, xa.y + h1);
            *(float2*)(y8 + t) = make_float2(xb2.x + h2, xb2.y + h3);
        }
    }
}

// ---------------- encoder output transpose -> bf16 [b][t][c] ----------------
__global__ void k_xB() {
    __shared__ float tile[32][33];
    int b = blockIdx.z;
    int t0 = blockIdx.x * 32, c0 = blockIdx.y * 32;
    int lx = threadIdx.x, ly = threadIdx.y;   // 32 x 8
#pragma unroll
    for (int i = 0; i < 32; i += 8)
        tile[ly + i][lx] = g_bufA[(b * NC + c0 + ly + i) * NTP + GOF + t0 + lx];
    __syncthreads();
#pragma unroll
    for (int i = 0; i < 32; i += 8) {
        int t = t0 + ly + i, c = c0 + lx;
        g_xB[(long)(b * NT + t) * 128 + c] = __float2bfloat16(tile[lx][ly + i]);
    }
}

// ---------------- subsampled up-projection ----------------
__global__ void __launch_bounds__(256) k_sub(const float* __restrict__ up_b) {
    __shared__ float es[16][128];
    int b = blockIdx.z;
    int u = blockIdx.x * 256 + threadIdx.x;
    int ts0 = blockIdx.y * 16;
    const float* E = g_bufA + b * NC * NTP + GOF;
    for (int i = threadIdx.x; i < 16 * 128; i += 256) {
        int tsl = i >> 7, c = i & 127;
        es[tsl][c] = E[c * NTP + (ts0 + tsl) * 64];
    }
    __syncthreads();
    float acc[16];
    float bi = up_b[u];
#pragma unroll
    for (int j = 0; j < 16; j++) acc[j] = bi;
    for (int c = 0; c < 128; c++) {
        float w = g_upwT[c * 2048 + u];
#pragma unroll
        for (int j = 0; j < 16; j++) acc[j] += w * es[j][c];
    }
#pragma unroll
    for (int j = 0; j < 16; j++)
        g_ysub[(b * 2048 + u) * 512 + ts0 + j] = acc[j];
}

__device__ __forceinline__ unsigned f2ord(float v) {
    unsigned u = __float_as_uint(v);
    return (u & 0x80000000u) ? ~u : (u | 0x80000000u);
}
__device__ __forceinline__ float ord2f(unsigned k) {
    unsigned u = (k & 0x80000000u) ? (k ^ 0x80000000u) : ~k;
    return __uint_as_float(u);
}

__global__ void k_thresh() {
    __shared__ unsigned hist[2048];
    __shared__ int s_b1, s_m;
    int b = blockIdx.x, tid = threadIdx.x;
    const float* ys = g_ysub + b * 2048 * 512;
    for (int i = tid; i < 2048; i += 1024) hist[i] = 0;
    __syncthreads();
    for (int i = tid; i < 2048 * 512; i += 1024)
        atomicAdd(&hist[f2ord(ys[i]) >> 21], 1u);
    __syncthreads();
    if (tid == 0) {
        unsigned acc = 0;
        int b1 = 0, m = 64;
        for (int i = 2047; i >= 0; i--) {
            acc += hist[i];
            if (acc >= 64) { b1 = i; m = 64 - (int)(acc - hist[i]); break; }
        }
        s_b1 = b1; s_m = m;
    }
    __syncthreads();
    int b1 = s_b1, m = s_m;
    for (int i = tid; i < 2048; i += 1024) hist[i] = 0;
    __syncthreads();
    for (int i = tid; i < 2048 * 512; i += 1024) {
        unsigned key = f2ord(ys[i]);
        if ((int)(key >> 21) == b1) atomicAdd(&hist[(key >> 10) & 2047], 1u);
    }
    __syncthreads();
    if (tid == 0) {
        unsigned acc = 0;
        int b2 = 0;
        for (int i = 2047; i >= 0; i--) {
            acc += hist[i];
            if ((int)acc >= m) { b2 = i; break; }
        }
        unsigned tk = ((unsigned)b1 << 21) | ((unsigned)b2 << 10);
        if (tk >= (1u << 10)) tk -= (1u << 10);
        float tf = ord2f(tk);
        g_thresh[b] = tf - 0.05f * fabsf(tf);
        g_candCnt[b] = 0;
    }
}

// ---------------- up-projection via mma.sync (bf16, K=128, 1 sync/chunk) ----------------
__global__ void __launch_bounds__(256, 2) k_up_mma(const float* __restrict__ up_b) {
    __shared__ __align__(16) __nv_bfloat16 Ah[128][136];
    __shared__ __align__(16) __nv_bfloat16 Bs[2][128][24];
    int tid = threadIdx.x;
    int b = blockIdx.z;
    int u0 = blockIdx.y * 128;
    int t0 = blockIdx.x * 128;
    int w = tid >> 5, lane = tid & 31;
    int wu = w >> 1, wt = w & 1;
    int q = lane >> 3, r = lane & 7;

    const __nv_bfloat16* Bg = g_xB + (long)(b * NT + t0) * 128;
    int lr = tid >> 1, lh = tid & 1;

    // prologue: A tile + B stage 0
    for (int i = tid; i < 2048; i += 256) {
        int row = i >> 4, c8 = (i & 15) * 8;
        cp16(&Ah[row][c8], g_upA + (u0 + row) * 128 + c8);
    }
    cp16(&Bs[0][lr][lh * 8], Bg + lr * 128 + 0 + lh * 8);
    CP_COMMIT();

    float acc[2][8][4];
#pragma unroll
    for (int mi = 0; mi < 2; mi++)
#pragma unroll
        for (int ni = 0; ni < 8; ni++)
#pragma unroll
            for (int v = 0; v < 4; v++) acc[mi][ni][v] = 0.f;

    unsigned aA[2], bA[8];
#pragma unroll
    for (int mi = 0; mi < 2; mi++)
        aA[mi] = (unsigned)__cvta_generic_to_shared(
            &Ah[wu * 32 + mi * 16 + (q & 1) * 8 + r][(q >> 1) * 8]);
#pragma unroll
    for (int ni = 0; ni < 8; ni++)
        bA[ni] = (unsigned)__cvta_generic_to_shared(
            &Bs[0][wt * 64 + ni * 8 + r][(q & 1) * 8]);
    const unsigned SB = 128 * 24 * 2;

    for (int ck = 0; ck < 8; ck++) {
        int s = ck & 1;
        CP_WAIT0();
        __syncthreads();
        if (ck + 1 < 8)
            cp16(&Bs[s ^ 1][lr][lh * 8], Bg + lr * 128 + (ck + 1) * 16 + lh * 8);
        CP_COMMIT();
        unsigned bq[8][2], af[2][4];
#pragma unroll
        for (int ni = 0; ni < 8; ni++) ldmB2(bq[ni], bA[ni] + s * SB);
#pragma unroll
        for (int mi = 0; mi < 2; mi++) ldmA4(af[mi], aA[mi] + ck * 32);
#pragma unroll
        for (int mi = 0; mi < 2; mi++)
#pragma unroll
            for (int ni = 0; ni < 8; ni++) mma16816(acc[mi][ni], af[mi], bq[ni]);
    }

    float T0 = g_thresh[b];
    int gid = lane >> 2, tig = lane & 3;
#pragma unroll
    for (int mi = 0; mi < 2; mi++) {
        int ub = u0 + wu * 32 + mi * 16 + gid;
        float bi0 = up_b[ub];
        float bi8 = up_b[ub + 8];
#pragma unroll
        for (int ni = 0; ni < 8; ni++) {
            int tb = t0 + wt * 64 + ni * 8 + tig * 2;
            float vv[4] = {acc[mi][ni][0] + bi0, acc[mi][ni][1] + bi0,
                           acc[mi][ni][2] + bi8, acc[mi][ni][3] + bi8};
            int uu[4] = {ub, ub, ub + 8, ub + 8};
            int tt[4] = {tb, tb + 1, tb, tb + 1};
#pragma unroll
            for (int v = 0; v < 4; v++) {
                if (vv[v] >= T0) {
                    int idx = atomicAdd(&g_candCnt[b], 1);
                    if (idx < CAP) {
                        g_candVal[b * CAP + idx] = vv[v];
                        g_candPack[b * CAP + idx] =
                            ((unsigned)uu[v] << 16) | (unsigned)tt[v];
                    }
                }
            }
        }
    }
}

__global__ void k_rescoreAll(const float* __restrict__ up_w, const float* __restrict__ up_b) {
    int b = blockIdx.y;
    int cnt = g_candCnt[b];
    if (cnt > CAP) cnt = CAP;
    int warpId = blockIdx.x * 8 + (threadIdx.x >> 5);
    int nw = gridDim.x * 8;
    int lane = threadIdx.x & 31;
    for (int i = warpId; i < cnt; i += nw) {
        unsigned pack = g_candPack[b * CAP + i];
        int u = (int)(pack >> 16), t = (int)(pack & 0xFFFFu);
        float s = 0.f;
#pragma unroll
        for (int c = lane; c < 128; c += 32)
            s += up_w[u * 128 + c] * g_bufA[(b * NC + c) * NTP + GOF + t];
#pragma unroll
        for (int o = 16; o; o >>= 1) s += __shfl_xor_sync(0xFFFFFFFFu, s, o);
        if (lane == 0) g_candVal[b * CAP + i] = s + up_b[u];
    }
}

__global__ void k_select() {
    __shared__ ull keys[5632];
    __shared__ ull red[256];
    int b = blockIdx.x, tid = threadIdx.x;
    int cnt = g_candCnt[b];
    if (cnt > CAP) cnt = CAP;
    bool useS = (cnt <= 5632);
    if (useS) {
        for (int i = tid; i < cnt; i += 256) {
            unsigned key = f2ord(g_candVal[b * CAP + i]);
            unsigned pack = g_candPack[b * CAP + i];
            keys[i] = ((ull)key << 32) | (ull)(~pack);
        }
    }
    __syncthreads();
    ull prev = 0xFFFFFFFFFFFFFFFFull;
    for (int r = 0; r < 64; r++) {
        ull best = 0;
        if (useS) {
            for (int i = tid; i < cnt; i += 256) {
                ull k64 = keys[i];
                if (k64 < prev && k64 > best) best = k64;
            }
        } else {
            for (int i = tid; i < cnt; i += 256) {
                unsigned key = f2ord(g_candVal[b * CAP + i]);
                unsigned pack = g_candPack[b * CAP + i];
                ull k64 = ((ull)key << 32) | (ull)(~pack);
                if (k64 < prev && k64 > best) best = k64;
            }
        }
        red[tid] = best;
        __syncthreads();
        for (int s = 128; s > 0; s >>= 1) {
            if (tid < s) { if (red[tid + s] > red[tid]) red[tid] = red[tid + s]; }
            __syncthreads();
        }
        best = red[0];
        if (tid == 0) {
            unsigned key = (unsigned)(best >> 32);
            unsigned pack = ~((unsigned)best);
            g_selVal[b * 64 + r] = ord2f(key);
            g_selU[b * 64 + r] = (int)(pack >> 16);
            g_selT[b * 64 + r] = (int)(pack & 0xFFFFu);
        }
        prev = best;
        __syncthreads();
    }
}

__global__ void k_base(const float* __restrict__ down_b, const float* __restrict__ dec_b) {
    __shared__ float cur[128];
    int c = threadIdx.x;
    cur[c] = down_b[c];
    g_base[c] = cur[c];
    __syncthreads();
    for (int l = 0; l < 6; l++) {
        const float* Wt = g_Wt + (6 + l) * 32768;
        float h = dec_b[l * 128 + c];
        for (int ci = 0; ci < 128; ci++)
            h += (Wt[(2 * ci) * 128 + c] + Wt[(2 * ci + 1) * 128 + c]) * cur[ci];
        h = (h > 0.f) ? h : 0.2f * h;
        float nv = cur[c] + h;
        __syncthreads();
        cur[c] = nv;
        g_base[(l + 1) * 128 + c] = nv;
        __syncthreads();
    }
}

__global__ void k_flags() {
    int idx = threadIdx.x;
    if (idx >= NB * 256) return;
    int b = idx >> 8, blk = idx & 255;
    int lo = blk * 128, hi = lo + 127;
    int act = (lo < 123) ? 1 : 0;
    for (int e = 0; e < 64; e++) {
        int s = g_selT[b * 64 + e];
        if (s <= hi && s + 122 >= lo) act = 1;
    }
    g_act[idx] = act;
}

__global__ void k_fill(const float* __restrict__ down_b) {
    int idx = blockIdx.x * 256 + threadIdx.x;
    if (idx >= NB * NC * NT / 4) return;
    int row = idx >> 13, t4 = idx & 8191;
    float v = down_b[row & 127];
    *(float4*)(&g_bufB[row * NTP + GOF + t4 * 4]) = make_float4(v, v, v, v);
}

__global__ void k_scatter(const float* __restrict__ down_w) {
    int tid = threadIdx.x;
    int b = tid >> 7, c = tid & 127;
    float* dst = g_bufB + (b * NC + c) * NTP + GOF;
    for (int e = 0; e < 64; e++) {
        float v = g_selVal[b * 64 + e];
        int u = g_selU[b * 64 + e];
        int t = g_selT[b * 64 + e];
        dst[t] += down_w[c * 2048 + u] * v;
    }
}

// ---------------- sparse synthesis: constant part ----------------
__global__ void k_pref(const float* __restrict__ fb) {
    __shared__ float pr[512];
    int j = threadIdx.x;
    float s = 0.f;
    for (int c = 0; c < 128; c++) s += g_base[768 + c] * fb[c * 512 + j];
    pr[j] = s;
    __syncthreads();
    if (j == 0) {
        float acc = 0.f;
        g_pref[0] = 0.f;
        for (int k = 0; k < 512; k++) { acc += pr[k]; g_pref[k + 1] = acc; }
    }
}

__global__ void k_fillOut(float* __restrict__ out) {
    int idx = blockIdx.x * 256 + threadIdx.x;
    if (idx >= NB * NT) return;
    int t = idx & (NT - 1);
    int jlo = 256 + t - (NT - 1); if (jlo < 0) jlo = 0;
    int jhi = 256 + t; if (jhi > 511) jhi = 511;
    out[idx] = g_pref[jhi + 1] - g_pref[jlo];
}

// ---------------- sparse synthesis: correction, parallel over channel-groups ----------------
__global__ void __launch_bounds__(256) k_corr(const float* __restrict__ fb,
                                              float* __restrict__ out) {
    __shared__ __align__(16) float fbx[8][768];
    __shared__ __align__(16) float dev[8][128];
    int b = blockIdx.z, blk = blockIdx.x, cg = blockIdx.y;
    if (!g_act[b * 256 + blk]) return;
    int s = blk * 128;
    int tid = threadIdx.x;
    const float* D = g_bufB + b * NC * NTP + GOF;

    for (int i = tid; i < 8 * 256; i += 256) {
        int c = i >> 8, p = i & 255;
        fbx[c][(p < 128) ? p : (512 + p)] = 0.f;
    }
    for (int i = tid; i < 8 * 512; i += 256)
        fbx[i >> 9][128 + (i & 511)] = fb[(cg * 8 + (i >> 9)) * 512 + (i & 511)];
    for (int i = tid; i < 8 * 128; i += 256) {
        int c = i >> 7, col = i & 127;
        dev[c][col] = D[(cg * 8 + c) * NTP + s + col] - g_base[768 + cg * 8 + c];
    }
    __syncthreads();

    if (tid >= 160) return;
    float a0 = 0.f, a1 = 0.f, a2 = 0.f, a3 = 0.f;
    int t0 = 4 * tid;
#pragma unroll 2
    for (int c = 0; c < 8; c++) {
        const float* fx = &fbx[c][0];
        const float4* dv4 = (const float4*)&dev[c][0];
        int m0 = t0 + 4;
        float4 fa = *(const float4*)&fx[m0 - 4];
        for (int c4 = 31; c4 >= 0; c4--) {
            float4 d4 = dv4[c4];
            float4 fbv = *(const float4*)&fx[m0];
            float wm3 = fa.y, wm2 = fa.z, wm1 = fa.w;
            a0 += fbv.x * d4.x + wm1 * d4.y + wm2 * d4.z + wm3 * d4.w;
            a1 += fbv.y * d4.x + fbv.x * d4.y + wm1 * d4.z + wm2 * d4.w;
            a2 += fbv.z * d4.x + fbv.y * d4.y + fbv.x * d4.z + wm1 * d4.w;
            a3 += fbv.w * d4.x + fbv.z * d4.y + fbv.y * d4.z + fbv.x * d4.w;
            fa = fbv;
            m0 += 4;
        }
    }
    float av[4] = {a0, a1, a2, a3};
#pragma unroll
    for (int qd = 0; qd < 4; qd++) {
        int t = t0 + qd;
        if (t < 639) {
            int tg = s - 256 + t;
            if (tg >= 0 && tg < NT && av[qd] != 0.f)
                atomicAdd(&out[b * NT + tg], av[qd]);
        }
    }
}

// ---------------- host driver ----------------
extern "C" void kernel_launch(void* const* d_in, const int* in_sizes, int n_in,
                              void* d_out, int out_size) {
    const float* x      = (const float*)d_in[0];
    const float* fb     = (const float*)d_in[1];
    const float* enc_w  = (const float*)d_in[2];
    const float* enc_b  = (const float*)d_in[3];
    const float* up_w   = (const float*)d_in[4];
    const float* up_b   = (const float*)d_in[5];
    const float* down_w = (const float*)d_in[6];
    const float* down_b = (const float*)d_in[7];
    const float* dec_w  = (const float*)d_in[8];
    const float* dec_b  = (const float*)d_in[9];
    float* out = (float*)d_out;

    static const int dil[6] = {1, 3, 9, 27, 81, 1};

    k_wt<<<(12 * 256 * 128 + 255) / 256, 256>>>(enc_w, dec_w);
    k_wA<<<(12 * 128 * 256 + 255) / 256, 256>>>(enc_w, dec_w);
    k_fbA<<<(128 * 512 + 255) / 256, 256>>>(fb);
    k_upwT<<<(128 * 2048 + 255) / 256, 256>>>(up_w);
    k_upA<<<(NU * 128 + 255) / 256, 256>>>(up_w);
    k_xp<<<(NB * XP + 255) / 256, 256>>>(x);
    k_guard<<<(2 * NB * NC * 512 + 255) / 256, 256>>>();

    k_fb_mma<<<dim3(NT / 128, NB), 256>>>();

    int srcIsA = 1;
    for (int l = 0; l < 6; l++) {
        k_layer_mma<<<dim3(256, NB), 256>>>(srcIsA, l, enc_b + l * 128, 0, dil[l], 0, 0);
        srcIsA ^= 1;
    }

    k_xB<<<dim3(NT / 32, NC / 32, NB), dim3(32, 8)>>>();
    k_sub<<<dim3(NU / 256, 512 / 16, NB), 256>>>(up_b);
    k_thresh<<<NB, 1024>>>();
    k_up_mma<<<dim3(NT / 128, NU / 128, NB), 256>>>(up_b);
    k_rescoreAll<<<dim3(64, NB), 256>>>(up_w, up_b);
    k_select<<<NB, 256>>>();

    k_base<<<1, 128>>>(down_b, dec_b);
    k_flags<<<1, 512>>>();
    k_fill<<<(NB * NC * NT / 4 + 255) / 256, 256>>>(down_b);
    k_scatter<<<1, 256>>>(down_w);

    srcIsA = 0;
    for (int l = 0; l < 6; l++) {
        k_layer_mma<<<dim3(256, NB), 256>>>(srcIsA, 6 + l, dec_b + l * 128, -dil[l], 0, 1, l);
        srcIsA ^= 1;
    }

    k_pref<<<1, 512>>>(fb);
    k_fillOut<<<(NB * NT + 255) / 256, 256>>>(out);
    k_corr<<<dim3(256, 16, NB), 256>>>(fb, out);
    (void)in_sizes; (void)n_in; (void)out_size;
}

// round 13
// speedup vs baseline: 1.6115x; 1.0003x over previous
#include <cuda_runtime.h>
#include <cuda_bf16.h>
#include <cstdint>

#define NB 2
#define NC 128
#define NU 2048
#define NZK 64
#define NT 32768
#define NTP (NT + 512)
#define GOF 256
#define XP  (NT + 512)
#define CAP (1<<18)

typedef unsigned long long ull;

static __device__ __align__(16) float g_bufA[NB*NC*NTP];
static __device__ __align__(16) float g_bufB[NB*NC*NTP];
static __device__ __align__(16) float g_Wt[12*256*128];
static __device__ __align__(16) float g_upwT[128*2048];
static __device__ __align__(16) float g_xp[NB*XP];
static __device__ __align__(16) __nv_bfloat16 g_WA[12*2*128*256];
static __device__ __align__(16) __nv_bfloat16 g_fbA[2*128*512];
static __device__ __align__(16) __nv_bfloat16 g_upA[NU*128];
static __device__ __align__(16) __nv_bfloat16 g_xB[(long)NB*NT*128];
static __device__ float g_ysub[NB*2048*512];
static __device__ float g_thresh[NB];
static __device__ int   g_candCnt[NB];
static __device__ float g_candVal[NB*CAP];
static __device__ unsigned g_candPack[NB*CAP];
static __device__ float g_selVal[NB*NZK];
static __device__ int   g_selU[NB*NZK];
static __device__ int   g_selT[NB*NZK];
static __device__ float g_base[7*128];
static __device__ int   g_act[NB*256];
static __device__ float g_pref[513];
static __device__ unsigned g_h1[NB*2048];
static __device__ unsigned g_h2[NB*2048];
static __device__ int g_tb1[NB];
static __device__ int g_tm[NB];

__device__ __forceinline__ void cp16(void* dst, const void* src) {
    unsigned d = (unsigned)__cvta_generic_to_shared(dst);
    asm volatile("cp.async.cg.shared.global [%0], [%1], 16;\n" :: "r"(d), "l"(src));
}
#define CP_COMMIT() asm volatile("cp.async.commit_group;\n")
#define CP_WAIT0()  asm volatile("cp.async.wait_group 0;\n")

__device__ __forceinline__ void ldmA4(unsigned* a, unsigned addr) {
    asm volatile("ldmatrix.sync.aligned.m8n8.x4.shared.b16 {%0,%1,%2,%3}, [%4];"
                 : "=r"(a[0]), "=r"(a[1]), "=r"(a[2]), "=r"(a[3]) : "r"(addr));
}
__device__ __forceinline__ void ldmB2t(unsigned* bq, unsigned addr) {
    asm volatile("ldmatrix.sync.aligned.m8n8.x2.trans.shared.b16 {%0,%1}, [%2];"
                 : "=r"(bq[0]), "=r"(bq[1]) : "r"(addr));
}
__device__ __forceinline__ void ldmB2(unsigned* bq, unsigned addr) {
    asm volatile("ldmatrix.sync.aligned.m8n8.x2.shared.b16 {%0,%1}, [%2];"
                 : "=r"(bq[0]), "=r"(bq[1]) : "r"(addr));
}
__device__ __forceinline__ void mma16816(float* c, const unsigned* a, const unsigned* bq) {
    asm volatile("mma.sync.aligned.m16n8k16.row.col.f32.bf16.bf16.f32 "
                 "{%0,%1,%2,%3}, {%4,%5,%6,%7}, {%8,%9}, {%0,%1,%2,%3};"
                 : "+f"(c[0]), "+f"(c[1]), "+f"(c[2]), "+f"(c[3])
                 : "r"(a[0]), "r"(a[1]), "r"(a[2]), "r"(a[3]), "r"(bq[0]), "r"(bq[1]));
}
__device__ __forceinline__ unsigned pkbf(float a, float b) {
    unsigned lo = (unsigned)__bfloat16_as_ushort(__float2bfloat16(a));
    unsigned hi = (unsigned)__bfloat16_as_ushort(__float2bfloat16(b));
    return lo | (hi << 16);
}

__global__ void k_wt(const float* __restrict__ enc_w, const float* __restrict__ dec_w) {
    int idx = blockIdx.x * 256 + threadIdx.x;
    if (idx >= 12 * 256 * 128) return;
    int l = idx / 32768;
    int r = idx - l * 32768;
    int k = r >> 7, c = r & 127;
    const float* w = (l < 6) ? (enc_w + l * 32768) : (dec_w + (l - 6) * 32768);
    g_Wt[idx] = w[(c * 128 + (k >> 1)) * 2 + (k & 1)];
}

__global__ void k_wA(const float* __restrict__ enc_w, const float* __restrict__ dec_w) {
    int idx = blockIdx.x * 256 + threadIdx.x;
    if (idx >= 12 * 128 * 256) return;
    int l = idx / 32768;
    int r = idx - l * 32768;
    int c = r >> 8, k = r & 255;
    const float* w = (l < 6) ? (enc_w + l * 32768) : (dec_w + (l - 6) * 32768);
    float v = w[(c * 128 + (k >> 1)) * 2 + (k & 1)];
    __nv_bfloat16 h = __float2bfloat16(v);
    g_WA[((l * 2 + 0) * 128 + c) * 256 + k] = h;
    g_WA[((l * 2 + 1) * 128 + c) * 256 + k] = __float2bfloat16(v - __bfloat162float(h));
}

__global__ void k_fbA(const float* __restrict__ fb) {
    int idx = blockIdx.x * 256 + threadIdx.x;
    if (idx >= 128 * 512) return;
    float v = fb[idx];
    __nv_bfloat16 h = __float2bfloat16(v);
    g_fbA[idx] = h;
    g_fbA[65536 + idx] = __float2bfloat16(v - __bfloat162float(h));
}

__global__ void k_upwT(const float* __restrict__ up_w) {
    int idx = blockIdx.x * 256 + threadIdx.x;
    if (idx >= 128 * 2048) return;
    int c = idx >> 11, u = idx & 2047;
    g_upwT[idx] = up_w[u * 128 + c];
}

__global__ void k_upA(const float* __restrict__ up_w) {
    int idx = blockIdx.x * 256 + threadIdx.x;
    if (idx >= NU * 128) return;
    g_upA[idx] = __float2bfloat16(up_w[idx]);
}

__global__ void k_xp(const float* __restrict__ x) {
    int idx = blockIdx.x * 256 + threadIdx.x;
    if (idx >= NB * XP) return;
    int b = idx / XP, w = idx - b * XP;
    g_xp[idx] = (w >= GOF && w < NT + GOF) ? x[b * NT + (w - GOF)] : 0.f;
}

__global__ void k_guard() {
    int idx = blockIdx.x * 256 + threadIdx.x;
    int half = NB * NC * 512;
    if (idx >= 2 * half) return;
    float* buf = (idx < half) ? g_bufA : g_bufB;
    int r = (idx < half) ? idx : idx - half;
    int row = r >> 9, w = r & 511;
    int pos = (w < 256) ? w : (NT + 256 + (w - 256));
    buf[row * NTP + pos] = 0.f;
}

// consume macro: 3 bf16 product groups for one chunk (stage offsets sA/sB)
#define MMA_CONSUME(sA, sB) {                                                \
    unsigned bq[8][2], af[2][4];                                             \
    _Pragma("unroll") for (int ni = 0; ni < 8; ni++) ldmB2t(bq[ni], bA[ni] + (sB)); \
    _Pragma("unroll") for (int mi = 0; mi < 2; mi++) ldmA4(af[mi], aA[mi] + (sA)); \
    _Pragma("unroll") for (int mi = 0; mi < 2; mi++)                         \
        _Pragma("unroll") for (int ni = 0; ni < 8; ni++) mma16816(acc[mi][ni], af[mi], bq[ni]); \
    _Pragma("unroll") for (int mi = 0; mi < 2; mi++) ldmA4(af[mi], aA[mi] + (sA) + dA); \
    _Pragma("unroll") for (int mi = 0; mi < 2; mi++)                         \
        _Pragma("unroll") for (int ni = 0; ni < 8; ni++) mma16816(acc[mi][ni], af[mi], bq[ni]); \
    _Pragma("unroll") for (int ni = 0; ni < 8; ni++) ldmB2t(bq[ni], bA[ni] + (sB) + dB); \
    _Pragma("unroll") for (int mi = 0; mi < 2; mi++) ldmA4(af[mi], aA[mi] + (sA)); \
    _Pragma("unroll") for (int mi = 0; mi < 2; mi++)                         \
        _Pragma("unroll") for (int ni = 0; ni < 8; ni++) mma16816(acc[mi][ni], af[mi], bq[ni]); }

#define CONV_B(st) {                                                         \
    _Pragma("unroll") for (int jj = 0; jj < 4; jj++) {                       \
        float v0 = vr[2 * jj], v1 = vr[2 * jj + 1];                          \
        float h0 = __bfloat162float(__float2bfloat16(v0));                   \
        float h1 = __bfloat162float(__float2bfloat16(v1));                   \
        *(unsigned*)&Bh[st][brow][bcb + 2 * jj] = pkbf(v0, v1);              \
        *(unsigned*)&Bl[st][brow][bcb + 2 * jj] = pkbf(v0 - h0, v1 - h1);    \
    } }

// ---------------- filterbank analysis (bf16x3, K=512, 1 sync/chunk) ----------------
__global__ void __launch_bounds__(256, 2) k_fb_mma() {
    __shared__ __align__(16) __nv_bfloat16 Ah[2][128][24];
    __shared__ __align__(16) __nv_bfloat16 Al[2][128][24];
    __shared__ __align__(16) __nv_bfloat16 Bh[2][16][136];
    __shared__ __align__(16) __nv_bfloat16 Bl[2][16][136];
    int tid = threadIdx.x;
    int b = blockIdx.y, t0 = blockIdx.x * 128;
    int w = tid >> 5, lane = tid & 31;
    int wu = w >> 1, wt = w & 1;
    int q = lane >> 3, r = lane & 7;
    const float* xb = g_xp + b * XP;

    float acc[2][8][4];
#pragma unroll
    for (int mi = 0; mi < 2; mi++)
#pragma unroll
        for (int ni = 0; ni < 8; ni++)
#pragma unroll
            for (int v = 0; v < 4; v++) acc[mi][ni][v] = 0.f;

    unsigned aA[2], bA[8];
#pragma unroll
    for (int mi = 0; mi < 2; mi++)
        aA[mi] = (unsigned)__cvta_generic_to_shared(
            &Ah[0][wu * 32 + mi * 16 + (q & 1) * 8 + r][(q >> 1) * 8]);
#pragma unroll
    for (int ni = 0; ni < 8; ni++)
        bA[ni] = (unsigned)__cvta_generic_to_shared(&Bh[0][lane & 15][wt * 64 + ni * 8]);
    unsigned dA = (unsigned)__cvta_generic_to_shared(&Al[0][0][0]) -
                  (unsigned)__cvta_generic_to_shared(&Ah[0][0][0]);
    unsigned dB = (unsigned)__cvta_generic_to_shared(&Bl[0][0][0]) -
                  (unsigned)__cvta_generic_to_shared(&Bh[0][0][0]);
    const unsigned SA = 128 * 24 * 2, SBt = 16 * 136 * 2;

    int brow = tid >> 4, bcb = (tid & 15) * 8;
    int arow = tid >> 1, ahalf = (tid & 1) * 8;

    float vr[8];
    cp16(&Ah[0][arow][ahalf], g_fbA + arow * 512 + ahalf);
    cp16(&Al[0][arow][ahalf], g_fbA + 65536 + arow * 512 + ahalf);
    CP_COMMIT();
    {
        const float* src = xb + t0 + brow + bcb;
#pragma unroll
        for (int j = 0; j < 8; j++) vr[j] = src[j];
        CONV_B(0);
        const float* s1 = xb + t0 + 16 + brow + bcb;
#pragma unroll
        for (int j = 0; j < 8; j++) vr[j] = s1[j];
    }
    CP_WAIT0(); __syncthreads();

    for (int ck = 0; ck < 32; ck++) {
        int s = ck & 1;
        if (ck + 1 < 32) {
            int kc1 = (ck + 1) * 16;
            cp16(&Ah[s ^ 1][arow][ahalf], g_fbA + arow * 512 + kc1 + ahalf);
            cp16(&Al[s ^ 1][arow][ahalf], g_fbA + 65536 + arow * 512 + kc1 + ahalf);
            CP_COMMIT();
            CONV_B(s ^ 1);
            if (ck + 2 < 32) {
                const float* src = xb + t0 + (ck + 2) * 16 + brow + bcb;
#pragma unroll
                for (int j = 0; j < 8; j++) vr[j] = src[j];
            }
        }
        MMA_CONSUME(s * SA, s * SBt);
        if (ck + 1 < 32) CP_WAIT0();
        __syncthreads();
    }
    int gid = lane >> 2, tig = lane & 3;
#pragma unroll
    for (int mi = 0; mi < 2; mi++) {
        int c = wu * 32 + mi * 16 + gid;
        float* y0 = g_bufA + (b * NC + c) * NTP + GOF;
        float* y8 = y0 + 8 * NTP;
#pragma unroll
        for (int ni = 0; ni < 8; ni++) {
            int t = t0 + wt * 64 + ni * 8 + tig * 2;
            *(float2*)(y0 + t) = make_float2(acc[mi][ni][0], acc[mi][ni][1]);
            *(float2*)(y8 + t) = make_float2(acc[mi][ni][2], acc[mi][ni][3]);
        }
    }
}

// ---------------- residual dilated layer (bf16x3, K=256, sparse, 1 sync/chunk) ----------------
__global__ void __launch_bounds__(256, 2) k_layer_mma(int srcIsA, int lidx,
                                                      const float* __restrict__ bias,
                                                      int o0, int o1, int sparse, int lvl) {
    __shared__ __align__(16) __nv_bfloat16 Ah[2][128][24];
    __shared__ __align__(16) __nv_bfloat16 Al[2][128][24];
    __shared__ __align__(16) __nv_bfloat16 Bh[2][16][136];
    __shared__ __align__(16) __nv_bfloat16 Bl[2][16][136];
    const float* X = srcIsA ? g_bufA : g_bufB;
    float* Y = srcIsA ? g_bufB : g_bufA;
    int tid = threadIdx.x;
    int b = blockIdx.y, blk = blockIdx.x, t0 = blk * 128;

    if (sparse && !g_act[b * 256 + blk]) {
        int tx = tid & 15, ty = tid >> 4;
#pragma unroll
        for (int i = 0; i < 8; i++) {
            float v = g_base[(lvl + 1) * 128 + ty * 8 + i];
#pragma unroll
            for (int j = 0; j < 8; j++) {
                int t = t0 + ((j < 4) ? (tx * 4 + j) : (64 + tx * 4 + j - 4));
                Y[(b * NC + ty * 8 + i) * NTP + GOF + t] = v;
            }
        }
        return;
    }

    int w = tid >> 5, lane = tid & 31;
    int wu = w >> 1, wt = w & 1;
    int q = lane >> 3, r = lane & 7;
    const float* Xb = X + b * NC * NTP;
    int dOff = o1 - o0;
    const __nv_bfloat16* WAh = g_WA + (size_t)(lidx * 2 + 0) * 32768;
    const __nv_bfloat16* WAl = g_WA + (size_t)(lidx * 2 + 1) * 32768;

    float acc[2][8][4];
#pragma unroll
    for (int mi = 0; mi < 2; mi++)
#pragma unroll
        for (int ni = 0; ni < 8; ni++)
#pragma unroll
            for (int v = 0; v < 4; v++) acc[mi][ni][v] = 0.f;

    unsigned aA[2], bA[8];
#pragma unroll
    for (int mi = 0; mi < 2; mi++)
        aA[mi] = (unsigned)__cvta_generic_to_shared(
            &Ah[0][wu * 32 + mi * 16 + (q & 1) * 8 + r][(q >> 1) * 8]);
#pragma unroll
    for (int ni = 0; ni < 8; ni++)
        bA[ni] = (unsigned)__cvta_generic_to_shared(&Bh[0][lane & 15][wt * 64 + ni * 8]);
    unsigned dA = (unsigned)__cvta_generic_to_shared(&Al[0][0][0]) -
                  (unsigned)__cvta_generic_to_shared(&Ah[0][0][0]);
    unsigned dB = (unsigned)__cvta_generic_to_shared(&Bl[0][0][0]) -
                  (unsigned)__cvta_generic_to_shared(&Bh[0][0][0]);
    const unsigned SA = 128 * 24 * 2, SBt = 16 * 136 * 2;

    int brow = tid >> 4, bcb = (tid & 15) * 8;
    int arow = tid >> 1, ahalf = (tid & 1) * 8;

    float vr[8];
    cp16(&Ah[0][arow][ahalf], WAh + arow * 256 + ahalf);
    cp16(&Al[0][arow][ahalf], WAl + arow * 256 + ahalf);
    CP_COMMIT();
    {
        int k = brow;
        const float* src = Xb + (k >> 1) * NTP + GOF + t0 + o0 + (k & 1) * dOff + bcb;
#pragma unroll
        for (int j = 0; j < 8; j++) vr[j] = src[j];
        CONV_B(0);
        k = 16 + brow;
        const float* s1 = Xb + (k >> 1) * NTP + GOF + t0 + o0 + (k & 1) * dOff + bcb;
#pragma unroll
        for (int j = 0; j < 8; j++) vr[j] = s1[j];
    }
    CP_WAIT0(); __syncthreads();

    for (int ck = 0; ck < 16; ck++) {
        int s = ck & 1;
        if (ck + 1 < 16) {
            int kc1 = (ck + 1) * 16;
            cp16(&Ah[s ^ 1][arow][ahalf], WAh + arow * 256 + kc1 + ahalf);
            cp16(&Al[s ^ 1][arow][ahalf], WAl + arow * 256 + kc1 + ahalf);
            CP_COMMIT();
            CONV_B(s ^ 1);
            if (ck + 2 < 16) {
                int k = (ck + 2) * 16 + brow;
                const float* src = Xb + (k >> 1) * NTP + GOF + t0 + o0 + (k & 1) * dOff + bcb;
#pragma unroll
                for (int j = 0; j < 8; j++) vr[j] = src[j];
            }
        }
        MMA_CONSUME(s * SA, s * SBt);
        if (ck + 1 < 16) CP_WAIT0();
        __syncthreads();
    }
    int gid = lane >> 2, tig = lane & 3;
#pragma unroll
    for (int mi = 0; mi < 2; mi++) {
        int c = wu * 32 + mi * 16 + gid;
        float bi0 = bias[c], bi8 = bias[c + 8];
        const float* x0 = Xb + c * NTP + GOF;
        const float* x8 = x0 + 8 * NTP;
        float* y0 = Y + (b * NC + c) * NTP + GOF;
        float* y8 = y0 + 8 * NTP;
#pragma unroll
        for (int ni = 0; ni < 8; ni++) {
            int t = t0 + wt * 64 + ni * 8 + tig * 2;
            float h0 = acc[mi][ni][0] + bi0; h0 = (h0 > 0.f) ? h0 : 0.2f * h0;
            float h1 = acc[mi][ni][1] + bi0; h1 = (h1 > 0.f) ? h1 : 0.2f * h1;
            float h2 = acc[mi][ni][2] + bi8; h2 = (h2 > 0.f) ? h2 : 0.2f * h2;
            float h3 = acc[mi][ni][3] + bi8; h3 = (h3 > 0.f) ? h3 : 0.2f * h3;
            float2 xa = *(const float2*)(x0 + t);
            float2 xb2 = *(const float2*)(x8 + t);
            *(float2*)(y0 + t) = make_float2(xa.x + h0, xa.y + h1);
            *(float2*)(y8 + t) = make_float2(xb2.x + h2, xb2.y + h3);
        }
    }
}

// ---------------- encoder output transpose -> bf16 [b][t][c] ----------------
__global__ void k_xB() {
    __shared__ float tile[32][33];
    int b = blockIdx.z;
    int t0 = blockIdx.x * 32, c0 = blockIdx.y * 32;
    int lx = threadIdx.x, ly = threadIdx.y;
#pragma unroll
    for (int i = 0; i < 32; i += 8)
        tile[ly + i][lx] = g_bufA[(b * NC + c0 + ly + i) * NTP + GOF + t0 + lx];
    __syncthreads();
#pragma unroll
    for (int i = 0; i < 32; i += 8) {
        int t = t0 + ly + i, c = c0 + lx;
        g_xB[(long)(b * NT + t) * 128 + c] = __float2bfloat16(tile[lx][ly + i]);
    }
}

// ---------------- subsampled up-projection ----------------
__global__ void __launch_bounds__(256) k_sub(const float* __restrict__ up_b) {
    __shared__ float es[16][128];
    int b = blockIdx.z;
    int u = blockIdx.x * 256 + threadIdx.x;
    int ts0 = blockIdx.y * 16;
    const float* E = g_bufA + b * NC * NTP + GOF;
    for (int i = threadIdx.x; i < 16 * 128; i += 256) {
        int tsl = i >> 7, c = i & 127;
        es[tsl][c] = E[c * NTP + (ts0 + tsl) * 64];
    }
    __syncthreads();
    float acc[16];
    float bi = up_b[u];
#pragma unroll
    for (int j = 0; j < 16; j++) acc[j] = bi;
    for (int c = 0; c < 128; c++) {
        float w = g_upwT[c * 2048 + u];
#pragma unroll
        for (int j = 0; j < 16; j++) acc[j] += w * es[j][c];
    }
#pragma unroll
    for (int j = 0; j < 16; j++)
        g_ysub[(b * 2048 + u) * 512 + ts0 + j] = acc[j];
}

__device__ __forceinline__ unsigned f2ord(float v) {
    unsigned u = __float_as_uint(v);
    return (u & 0x80000000u) ? ~u : (u | 0x80000000u);
}
__device__ __forceinline__ float ord2f(unsigned k) {
    unsigned u = (k & 0x80000000u) ? (k ^ 0x80000000u) : ~k;
    return __uint_as_float(u);
}

// ---------------- parallel threshold (4-stage) ----------------
__global__ void k_hz() {
    int i = blockIdx.x * 256 + threadIdx.x;
    if (i < NB * 2048) g_h1[i] = 0;
}
__global__ void k_h1() {
    __shared__ unsigned hist[2048];
    int b = blockIdx.y;
    const float* ys = g_ysub + b * 2048 * 512;
    for (int i = threadIdx.x; i < 2048; i += 256) hist[i] = 0;
    __syncthreads();
    for (int i = blockIdx.x * 256 + threadIdx.x; i < 2048 * 512; i += gridDim.x * 256)
        atomicAdd(&hist[f2ord(ys[i]) >> 21], 1u);
    __syncthreads();
    for (int i = threadIdx.x; i < 2048; i += 256)
        if (hist[i]) atomicAdd(&g_h1[b * 2048 + i], hist[i]);
}
__global__ void k_tmid() {
    int b = blockIdx.x;
    if (threadIdx.x == 0) {
        unsigned acc = 0;
        int b1 = 0, m = 64;
        for (int i = 2047; i >= 0; i--) {
            unsigned h = g_h1[b * 2048 + i];
            acc += h;
            if (acc >= 64) { b1 = i; m = 64 - (int)(acc - h); break; }
        }
        g_tb1[b] = b1; g_tm[b] = m;
    }
    for (int i = threadIdx.x; i < 2048; i += blockDim.x) g_h2[b * 2048 + i] = 0;
}
__global__ void k_h2() {
    __shared__ unsigned hist[2048];
    int b = blockIdx.y;
    int b1 = g_tb1[b];
    const float* ys = g_ysub + b * 2048 * 512;
    for (int i = threadIdx.x; i < 2048; i += 256) hist[i] = 0;
    __syncthreads();
    for (int i = blockIdx.x * 256 + threadIdx.x; i < 2048 * 512; i += gridDim.x * 256) {
        unsigned key = f2ord(ys[i]);
        if ((int)(key >> 21) == b1) atomicAdd(&hist[(key >> 10) & 2047], 1u);
    }
    __syncthreads();
    for (int i = threadIdx.x; i < 2048; i += 256)
        if (hist[i]) atomicAdd(&g_h2[b * 2048 + i], hist[i]);
}
__global__ void k_tfin() {
    int b = blockIdx.x;
    if (threadIdx.x) return;
    int m = g_tm[b];
    unsigned acc = 0;
    int b2 = 0;
    for (int i = 2047; i >= 0; i--) {
        acc += g_h2[b * 2048 + i];
        if ((int)acc >= m) { b2 = i; break; }
    }
    unsigned tk = ((unsigned)g_tb1[b] << 21) | ((unsigned)b2 << 10);
    if (tk >= (1u << 10)) tk -= (1u << 10);
    float tf = ord2f(tk);
    g_thresh[b] = tf - 0.05f * fabsf(tf);
    g_candCnt[b] = 0;
}

// ---------------- up-projection (bf16 single-plane, K=128) ----------------
__global__ void __launch_bounds__(256, 2) k_up_mma(const float* __restrict__ up_b) {
    __shared__ __align__(16) __nv_bfloat16 Ah[128][136];
    __shared__ __align__(16) __nv_bfloat16 Bs[2][128][24];
    int tid = threadIdx.x;
    int b = blockIdx.z;
    int u0 = blockIdx.y * 128;
    int t0 = blockIdx.x * 128;
    int w = tid >> 5, lane = tid & 31;
    int wu = w >> 1, wt = w & 1;
    int q = lane >> 3, r = lane & 7;

    const __nv_bfloat16* Bg = g_xB + (long)(b * NT + t0) * 128;
    int lr = tid >> 1, lh = tid & 1;

    for (int i = tid; i < 2048; i += 256) {
        int row = i >> 4, c8 = (i & 15) * 8;
        cp16(&Ah[row][c8], g_upA + (u0 + row) * 128 + c8);
    }
    cp16(&Bs[0][lr][lh * 8], Bg + lr * 128 + 0 + lh * 8);
    CP_COMMIT();

    float acc[2][8][4];
#pragma unroll
    for (int mi = 0; mi < 2; mi++)
#pragma unroll
        for (int ni = 0; ni < 8; ni++)
#pragma unroll
            for (int v = 0; v < 4; v++) acc[mi][ni][v] = 0.f;

    unsigned aA[2], bA[8];
#pragma unroll
    for (int mi = 0; mi < 2; mi++)
        aA[mi] = (unsigned)__cvta_generic_to_shared(
            &Ah[wu * 32 + mi * 16 + (q & 1) * 8 + r][(q >> 1) * 8]);
#pragma unroll
    for (int ni = 0; ni < 8; ni++)
        bA[ni] = (unsigned)__cvta_generic_to_shared(
            &Bs[0][wt * 64 + ni * 8 + r][(q & 1) * 8]);
    const unsigned SB = 128 * 24 * 2;

    for (int ck = 0; ck < 8; ck++) {
        int s = ck & 1;
        CP_WAIT0();
        __syncthreads();
        if (ck + 1 < 8)
            cp16(&Bs[s ^ 1][lr][lh * 8], Bg + lr * 128 + (ck + 1) * 16 + lh * 8);
        CP_COMMIT();
        unsigned bq[8][2], af[2][4];
#pragma unroll
        for (int ni = 0; ni < 8; ni++) ldmB2(bq[ni], bA[ni] + s * SB);
#pragma unroll
        for (int mi = 0; mi < 2; mi++) ldmA4(af[mi], aA[mi] + ck * 32);
#pragma unroll
        for (int mi = 0; mi < 2; mi++)
#pragma unroll
            for (int ni = 0; ni < 8; ni++) mma16816(acc[mi][ni], af[mi], bq[ni]);
    }

    float T0 = g_thresh[b];
    int gid = lane >> 2, tig = lane & 3;
#pragma unroll
    for (int mi = 0; mi < 2; mi++) {
        int ub = u0 + wu * 32 + mi * 16 + gid;
        float bi0 = up_b[ub];
        float bi8 = up_b[ub + 8];
#pragma unroll
        for (int ni = 0; ni < 8; ni++) {
            int tb = t0 + wt * 64 + ni * 8 + tig * 2;
            float vv[4] = {acc[mi][ni][0] + bi0, acc[mi][ni][1] + bi0,
                           acc[mi][ni][2] + bi8, acc[mi][ni][3] + bi8};
            int uu[4] = {ub, ub, ub + 8, ub + 8};
            int tt[4] = {tb, tb + 1, tb, tb + 1};
#pragma unroll
            for (int v = 0; v < 4; v++) {
                if (vv[v] >= T0) {
                    int idx = atomicAdd(&g_candCnt[b], 1);
                    if (idx < CAP) {
                        g_candVal[b * CAP + idx] = vv[v];
                        g_candPack[b * CAP + idx] =
                            ((unsigned)uu[v] << 16) | (unsigned)tt[v];
                    }
                }
            }
        }
    }
}

__global__ void k_rescoreAll(const float* __restrict__ up_w, const float* __restrict__ up_b) {
    int b = blockIdx.y;
    int cnt = g_candCnt[b];
    if (cnt > CAP) cnt = CAP;
    int warpId = blockIdx.x * 8 + (threadIdx.x >> 5);
    int nw = gridDim.x * 8;
    int lane = threadIdx.x & 31;
    for (int i = warpId; i < cnt; i += nw) {
        unsigned pack = g_candPack[b * CAP + i];
        int u = (int)(pack >> 16), t = (int)(pack & 0xFFFFu);
        float s = 0.f;
#pragma unroll
        for (int c = lane; c < 128; c += 32)
            s += up_w[u * 128 + c] * g_bufA[(b * NC + c) * NTP + GOF + t];
#pragma unroll
        for (int o = 16; o; o >>= 1) s += __shfl_xor_sync(0xFFFFFFFFu, s, o);
        if (lane == 0) g_candVal[b * CAP + i] = s + up_b[u];
    }
}

__global__ void k_select() {
    __shared__ ull keys[5632];
    __shared__ ull red[256];
    int b = blockIdx.x, tid = threadIdx.x;
    int cnt = g_candCnt[b];
    if (cnt > CAP) cnt = CAP;
    bool useS = (cnt <= 5632);
    if (useS) {
        for (int i = tid; i < cnt; i += 256) {
            unsigned key = f2ord(g_candVal[b * CAP + i]);
            unsigned pack = g_candPack[b * CAP + i];
            keys[i] = ((ull)key << 32) | (ull)(~pack);
        }
    }
    __syncthreads();
    ull prev = 0xFFFFFFFFFFFFFFFFull;
    for (int r = 0; r < 64; r++) {
        ull best = 0;
        if (useS) {
            for (int i = tid; i < cnt; i += 256) {
                ull k64 = keys[i];
                if (k64 < prev && k64 > best) best = k64;
            }
        } else {
            for (int i = tid; i < cnt; i += 256) {
                unsigned key = f2ord(g_candVal[b * CAP + i]);
                unsigned pack = g_candPack[b * CAP + i];
                ull k64 = ((ull)key << 32) | (ull)(~pack);
                if (k64 < prev && k64 > best) best = k64;
            }
        }
        red[tid] = best;
        __syncthreads();
        for (int s = 128; s > 0; s >>= 1) {
            if (tid < s) { if (red[tid + s] > red[tid]) red[tid] = red[tid + s]; }
            __syncthreads();
        }
        best = red[0];
        if (tid == 0) {
            unsigned key = (unsigned)(best >> 32);
            unsigned pack = ~((unsigned)best);
            g_selVal[b * 64 + r] = ord2f(key);
            g_selU[b * 64 + r] = (int)(pack >> 16);
            g_selT[b * 64 + r] = (int)(pack & 0xFFFFu);
        }
        prev = best;
        __syncthreads();
    }
}

__global__ void k_base(const float* __restrict__ down_b, const float* __restrict__ dec_b) {
    __shared__ float cur[128];
    int c = threadIdx.x;
    cur[c] = down_b[c];
    g_base[c] = cur[c];
    __syncthreads();
    for (int l = 0; l < 6; l++) {
        const float* Wt = g_Wt + (6 + l) * 32768;
        float h = dec_b[l * 128 + c];
        for (int ci = 0; ci < 128; ci++)
            h += (Wt[(2 * ci) * 128 + c] + Wt[(2 * ci + 1) * 128 + c]) * cur[ci];
        h = (h > 0.f) ? h : 0.2f * h;
        float nv = cur[c] + h;
        __syncthreads();
        cur[c] = nv;
        g_base[(l + 1) * 128 + c] = nv;
        __syncthreads();
    }
}

__global__ void k_flags() {
    int idx = threadIdx.x;
    if (idx >= NB * 256) return;
    int b = idx >> 8, blk = idx & 255;
    int lo = blk * 128, hi = lo + 127;
    int act = (lo < 123) ? 1 : 0;
    for (int e = 0; e < 64; e++) {
        int s = g_selT[b * 64 + e];
        if (s <= hi && s + 122 >= lo) act = 1;
    }
    g_act[idx] = act;
}

__global__ void k_fill(const float* __restrict__ down_b) {
    int idx = blockIdx.x * 256 + threadIdx.x;
    if (idx >= NB * NC * NT / 4) return;
    int row = idx >> 13, t4 = idx & 8191;
    float v = down_b[row & 127];
    *(float4*)(&g_bufB[row * NTP + GOF + t4 * 4]) = make_float4(v, v, v, v);
}

__global__ void k_scatter(const float* __restrict__ down_w) {
    int tid = threadIdx.x;
    int b = tid >> 7, c = tid & 127;
    float* dst = g_bufB + (b * NC + c) * NTP + GOF;
    for (int e = 0; e < 64; e++) {
        float v = g_selVal[b * 64 + e];
        int u = g_selU[b * 64 + e];
        int t = g_selT[b * 64 + e];
        dst[t] += down_w[c * 2048 + u] * v;
    }
}

__global__ void k_pref(const float* __restrict__ fb) {
    __shared__ float pr[512];
    int j = threadIdx.x;
    float s = 0.f;
    for (int c = 0; c < 128; c++) s += g_base[768 + c] * fb[c * 512 + j];
    pr[j] = s;
    __syncthreads();
    if (j == 0) {
        float acc = 0.f;
        g_pref[0] = 0.f;
        for (int k = 0; k < 512; k++) { acc += pr[k]; g_pref[k + 1] = acc; }
    }
}

__global__ void k_fillOut(float* __restrict__ out) {
    int idx = blockIdx.x * 256 + threadIdx.x;
    if (idx >= NB * NT) return;
    int t = idx & (NT - 1);
    int jlo = 256 + t - (NT - 1); if (jlo < 0) jlo = 0;
    int jhi = 256 + t; if (jhi > 511) jhi = 511;
    out[idx] = g_pref[jhi + 1] - g_pref[jlo];
}

__global__ void __launch_bounds__(256) k_corr(const float* __restrict__ fb,
                                              float* __restrict__ out) {
    __shared__ __align__(16) float fbx[8][768];
    __shared__ __align__(16) float dev[8][128];
    int b = blockIdx.z, blk = blockIdx.x, cg = blockIdx.y;
    if (!g_act[b * 256 + blk]) return;
    int s = blk * 128;
    int tid = threadIdx.x;
    const float* D = g_bufB + b * NC * NTP + GOF;

    for (int i = tid; i < 8 * 256; i += 256) {
        int c = i >> 8, p = i & 255;
        fbx[c][(p < 128) ? p : (512 + p)] = 0.f;
    }
    for (int i = tid; i < 8 * 512; i += 256)
        fbx[i >> 9][128 + (i & 511)] = fb[(cg * 8 + (i >> 9)) * 512 + (i & 511)];
    for (int i = tid; i < 8 * 128; i += 256) {
        int c = i >> 7, col = i & 127;
        dev[c][col] = D[(cg * 8 + c) * NTP + s + col] - g_base[768 + cg * 8 + c];
    }
    __syncthreads();

    if (tid >= 160) return;
    float a0 = 0.f, a1 = 0.f, a2 = 0.f, a3 = 0.f;
    int t0 = 4 * tid;
#pragma unroll 2
    for (int c = 0; c < 8; c++) {
        const float* fx = &fbx[c][0];
        const float4* dv4 = (const float4*)&dev[c][0];
        int m0 = t0 + 4;
        float4 fa = *(const float4*)&fx[m0 - 4];
        for (int c4 = 31; c4 >= 0; c4--) {
            float4 d4 = dv4[c4];
            float4 fbv = *(const float4*)&fx[m0];
            float wm3 = fa.y, wm2 = fa.z, wm1 = fa.w;
            a0 += fbv.x * d4.x + wm1 * d4.y + wm2 * d4.z + wm3 * d4.w;
            a1 += fbv.y * d4.x + fbv.x * d4.y + wm1 * d4.z + wm2 * d4.w;
            a2 += fbv.z * d4.x + fbv.y * d4.y + fbv.x * d4.z + wm1 * d4.w;
            a3 += fbv.w * d4.x + fbv.z * d4.y + fbv.y * d4.z + fbv.x * d4.w;
            fa = fbv;
            m0 += 4;
        }
    }
    float av[4] = {a0, a1, a2, a3};
#pragma unroll
    for (int qd = 0; qd < 4; qd++) {
        int t = t0 + qd;
        if (t < 639) {
            int tg = s - 256 + t;
            if (tg >= 0 && tg < NT && av[qd] != 0.f)
                atomicAdd(&out[b * NT + tg], av[qd]);
        }
    }
}

// ---------------- host driver ----------------
extern "C" void kernel_launch(void* const* d_in, const int* in_sizes, int n_in,
                              void* d_out, int out_size) {
    const float* x      = (const float*)d_in[0];
    const float* fb     = (const float*)d_in[1];
    const float* enc_w  = (const float*)d_in[2];
    const float* enc_b  = (const float*)d_in[3];
    const float* up_w   = (const float*)d_in[4];
    const float* up_b   = (const float*)d_in[5];
    const float* down_w = (const float*)d_in[6];
    const float* down_b = (const float*)d_in[7];
    const float* dec_w  = (const float*)d_in[8];
    const float* dec_b  = (const float*)d_in[9];
    float* out = (float*)d_out;

    static const int dil[6] = {1, 3, 9, 27, 81, 1};

    k_wt<<<(12 * 256 * 128 + 255) / 256, 256>>>(enc_w, dec_w);
    k_wA<<<(12 * 128 * 256 + 255) / 256, 256>>>(enc_w, dec_w);
    k_fbA<<<(128 * 512 + 255) / 256, 256>>>(fb);
    k_upwT<<<(128 * 2048 + 255) / 256, 256>>>(up_w);
    k_upA<<<(NU * 128 + 255) / 256, 256>>>(up_w);
    k_xp<<<(NB * XP + 255) / 256, 256>>>(x);
    k_guard<<<(2 * NB * NC * 512 + 255) / 256, 256>>>();
    k_hz<<<16, 256>>>();

    k_fb_mma<<<dim3(NT / 128, NB), 256>>>();

    int srcIsA = 1;
    for (int l = 0; l < 6; l++) {
        k_layer_mma<<<dim3(256, NB), 256>>>(srcIsA, l, enc_b + l * 128, 0, dil[l], 0, 0);
        srcIsA ^= 1;
    }

    k_xB<<<dim3(NT / 32, NC / 32, NB), dim3(32, 8)>>>();
    k_sub<<<dim3(NU / 256, 512 / 16, NB), 256>>>(up_b);
    k_h1<<<dim3(64, NB), 256>>>();
    k_tmid<<<NB, 256>>>();
    k_h2<<<dim3(64, NB), 256>>>();
    k_tfin<<<NB, 32>>>();
    k_up_mma<<<dim3(NT / 128, NU / 128, NB), 256>>>(up_b);
    k_rescoreAll<<<dim3(64, NB), 256>>>(up_w, up_b);
    k_select<<<NB, 256>>>();

    k_base<<<1, 128>>>(down_b, dec_b);
    k_flags<<<1, 512>>>();
    k_fill<<<(NB * NC * NT / 4 + 255) / 256, 256>>>(down_b);
    k_scatter<<<1, 256>>>(down_w);

    srcIsA = 0;
    for (int l = 0; l < 6; l++) {
        k_layer_mma<<<dim3(256, NB), 256>>>(srcIsA, 6 + l, dec_b + l * 128, -dil[l], 0, 1, l);
        srcIsA ^= 1;
    }

    k_pref<<<1, 512>>>(fb);
    k_fillOut<<<(NB * NT + 255) / 256, 256>>>(out);
    k_corr<<<dim3(256, 16, NB), 256>>>(fb, out);
    (void)in_sizes; (void)n_in; (void)out_size;
}

// round 14
// speedup vs baseline: 1.6437x; 1.0200x over previous
#include <cuda_runtime.h>
#include <cuda_bf16.h>
#include <cstdint>

#define NB 2
#define NC 128
#define NU 2048
#define NZK 64
#define NT 32768
#define NTP (NT + 512)
#define GOF 256
#define XP  (NT + 512)
#define CAP (1<<18)

typedef unsigned long long ull;

static __device__ __align__(16) float g_bufA[NB*NC*NTP];
static __device__ __align__(16) float g_bufB[NB*NC*NTP];
static __device__ __align__(16) float g_Wt[12*256*128];
static __device__ __align__(16) float g_upwT[128*2048];
static __device__ __align__(16) float g_xp[NB*XP];
static __device__ __align__(16) __nv_bfloat16 g_WA[12*2*128*256];
static __device__ __align__(16) __nv_bfloat16 g_fbA[2*128*512];
static __device__ __align__(16) __nv_bfloat16 g_upA[NU*128];
static __device__ __align__(16) __nv_bfloat16 g_xB[(long)NB*NT*128];
static __device__ float g_ysub[NB*2048*512];
static __device__ float g_thresh[NB];
static __device__ int   g_candCnt[NB];
static __device__ float g_candVal[NB*CAP];
static __device__ unsigned g_candPack[NB*CAP];
static __device__ float g_selVal[NB*NZK];
static __device__ int   g_selU[NB*NZK];
static __device__ int   g_selT[NB*NZK];
static __device__ float g_base[7*128];
static __device__ int   g_act[NB*256];
static __device__ float g_pref[513];
static __device__ unsigned g_h1[NB*2048];
static __device__ unsigned g_h2[NB*2048];
static __device__ int g_tb1[NB];
static __device__ int g_tm[NB];

__device__ __forceinline__ void cp16(void* dst, const void* src) {
    unsigned d = (unsigned)__cvta_generic_to_shared(dst);
    asm volatile("cp.async.cg.shared.global [%0], [%1], 16;\n" :: "r"(d), "l"(src));
}
#define CP_COMMIT() asm volatile("cp.async.commit_group;\n")
#define CP_WAIT0()  asm volatile("cp.async.wait_group 0;\n")
#define CP_WAIT1()  asm volatile("cp.async.wait_group 1;\n")

__device__ __forceinline__ void ldmA4(unsigned* a, unsigned addr) {
    asm volatile("ldmatrix.sync.aligned.m8n8.x4.shared.b16 {%0,%1,%2,%3}, [%4];"
                 : "=r"(a[0]), "=r"(a[1]), "=r"(a[2]), "=r"(a[3]) : "r"(addr));
}
__device__ __forceinline__ void ldmB2t(unsigned* bq, unsigned addr) {
    asm volatile("ldmatrix.sync.aligned.m8n8.x2.trans.shared.b16 {%0,%1}, [%2];"
                 : "=r"(bq[0]), "=r"(bq[1]) : "r"(addr));
}
__device__ __forceinline__ void ldmB2(unsigned* bq, unsigned addr) {
    asm volatile("ldmatrix.sync.aligned.m8n8.x2.shared.b16 {%0,%1}, [%2];"
                 : "=r"(bq[0]), "=r"(bq[1]) : "r"(addr));
}
__device__ __forceinline__ void mma16816(float* c, const unsigned* a, const unsigned* bq) {
    asm volatile("mma.sync.aligned.m16n8k16.row.col.f32.bf16.bf16.f32 "
                 "{%0,%1,%2,%3}, {%4,%5,%6,%7}, {%8,%9}, {%0,%1,%2,%3};"
                 : "+f"(c[0]), "+f"(c[1]), "+f"(c[2]), "+f"(c[3])
                 : "r"(a[0]), "r"(a[1]), "r"(a[2]), "r"(a[3]), "r"(bq[0]), "r"(bq[1]));
}
__device__ __forceinline__ unsigned pkbf(float a, float b) {
    unsigned lo = (unsigned)__bfloat16_as_ushort(__float2bfloat16(a));
    unsigned hi = (unsigned)__bfloat16_as_ushort(__float2bfloat16(b));
    return lo | (hi << 16);
}

// ---------------- fused prep (weights, splits, padding, zeroing) ----------------
__global__ void k_prep(const float* __restrict__ enc_w, const float* __restrict__ dec_w,
                       const float* __restrict__ fb, const float* __restrict__ up_w,
                       const float* __restrict__ x) {
    int idx = blockIdx.x * 256 + threadIdx.x;
    // [0, 393216): g_Wt
    if (idx < 393216) {
        int l = idx / 32768;
        int r = idx - l * 32768;
        int k = r >> 7, c = r & 127;
        const float* w = (l < 6) ? (enc_w + l * 32768) : (dec_w + (l - 6) * 32768);
        g_Wt[idx] = w[(c * 128 + (k >> 1)) * 2 + (k & 1)];
        return;
    }
    idx -= 393216;
    // [0, 393216): g_WA
    if (idx < 393216) {
        int l = idx / 32768;
        int r = idx - l * 32768;
        int c = r >> 8, k = r & 255;
        const float* w = (l < 6) ? (enc_w + l * 32768) : (dec_w + (l - 6) * 32768);
        float v = w[(c * 128 + (k >> 1)) * 2 + (k & 1)];
        __nv_bfloat16 h = __float2bfloat16(v);
        g_WA[((l * 2 + 0) * 128 + c) * 256 + k] = h;
        g_WA[((l * 2 + 1) * 128 + c) * 256 + k] = __float2bfloat16(v - __bfloat162float(h));
        return;
    }
    idx -= 393216;
    // [0, 65536): g_fbA
    if (idx < 65536) {
        float v = fb[idx];
        __nv_bfloat16 h = __float2bfloat16(v);
        g_fbA[idx] = h;
        g_fbA[65536 + idx] = __float2bfloat16(v - __bfloat162float(h));
        return;
    }
    idx -= 65536;
    // [0, 262144): g_upwT
    if (idx < 262144) {
        int c = idx >> 11, u = idx & 2047;
        g_upwT[idx] = up_w[u * 128 + c];
        return;
    }
    idx -= 262144;
    // [0, 262144): g_upA
    if (idx < 262144) {
        g_upA[idx] = __float2bfloat16(up_w[idx]);
        return;
    }
    idx -= 262144;
    // [0, NB*XP): g_xp
    if (idx < NB * XP) {
        int b = idx / XP, w = idx - b * XP;
        g_xp[idx] = (w >= GOF && w < NT + GOF) ? x[b * NT + (w - GOF)] : 0.f;
        return;
    }
    idx -= NB * XP;
    // [0, 262144): guards
    if (idx < 262144) {
        int half = NB * NC * 512;
        float* buf = (idx < half) ? g_bufA : g_bufB;
        int r = (idx < half) ? idx : idx - half;
        int row = r >> 9, w = r & 511;
        int pos = (w < 256) ? w : (NT + 256 + (w - 256));
        buf[row * NTP + pos] = 0.f;
        return;
    }
    idx -= 262144;
    // [0, NB*2048): zero g_h1
    if (idx < NB * 2048) g_h1[idx] = 0;
}

// consume macro: 3 bf16 product groups for one chunk (stage offsets sA/sB)
#define MMA_CONSUME(sA, sB) {                                                \
    unsigned bq[8][2], af[2][4];                                             \
    _Pragma("unroll") for (int ni = 0; ni < 8; ni++) ldmB2t(bq[ni], bA[ni] + (sB)); \
    _Pragma("unroll") for (int mi = 0; mi < 2; mi++) ldmA4(af[mi], aA[mi] + (sA)); \
    _Pragma("unroll") for (int mi = 0; mi < 2; mi++)                         \
        _Pragma("unroll") for (int ni = 0; ni < 8; ni++) mma16816(acc[mi][ni], af[mi], bq[ni]); \
    _Pragma("unroll") for (int mi = 0; mi < 2; mi++) ldmA4(af[mi], aA[mi] + (sA) + dA); \
    _Pragma("unroll") for (int mi = 0; mi < 2; mi++)                         \
        _Pragma("unroll") for (int ni = 0; ni < 8; ni++) mma16816(acc[mi][ni], af[mi], bq[ni]); \
    _Pragma("unroll") for (int ni = 0; ni < 8; ni++) ldmB2t(bq[ni], bA[ni] + (sB) + dB); \
    _Pragma("unroll") for (int mi = 0; mi < 2; mi++) ldmA4(af[mi], aA[mi] + (sA)); \
    _Pragma("unroll") for (int mi = 0; mi < 2; mi++)                         \
        _Pragma("unroll") for (int ni = 0; ni < 8; ni++) mma16816(acc[mi][ni], af[mi], bq[ni]); }

#define CONV_B(st) {                                                         \
    _Pragma("unroll") for (int jj = 0; jj < 4; jj++) {                       \
        float v0 = vr[2 * jj], v1 = vr[2 * jj + 1];                          \
        float h0 = __bfloat162float(__float2bfloat16(v0));                   \
        float h1 = __bfloat162float(__float2bfloat16(v1));                   \
        *(unsigned*)&Bh[st][brow][bcb + 2 * jj] = pkbf(v0, v1);              \
        *(unsigned*)&Bl[st][brow][bcb + 2 * jj] = pkbf(v0 - h0, v1 - h1);    \
    } }

// ---------------- filterbank analysis (bf16x3, K=512, 1 sync/chunk) ----------------
__global__ void __launch_bounds__(256, 2) k_fb_mma() {
    __shared__ __align__(16) __nv_bfloat16 Ah[2][128][24];
    __shared__ __align__(16) __nv_bfloat16 Al[2][128][24];
    __shared__ __align__(16) __nv_bfloat16 Bh[2][16][136];
    __shared__ __align__(16) __nv_bfloat16 Bl[2][16][136];
    int tid = threadIdx.x;
    int b = blockIdx.y, t0 = blockIdx.x * 128;
    int w = tid >> 5, lane = tid & 31;
    int wu = w >> 1, wt = w & 1;
    int q = lane >> 3, r = lane & 7;
    const float* xb = g_xp + b * XP;

    float acc[2][8][4];
#pragma unroll
    for (int mi = 0; mi < 2; mi++)
#pragma unroll
        for (int ni = 0; ni < 8; ni++)
#pragma unroll
            for (int v = 0; v < 4; v++) acc[mi][ni][v] = 0.f;

    unsigned aA[2], bA[8];
#pragma unroll
    for (int mi = 0; mi < 2; mi++)
        aA[mi] = (unsigned)__cvta_generic_to_shared(
            &Ah[0][wu * 32 + mi * 16 + (q & 1) * 8 + r][(q >> 1) * 8]);
#pragma unroll
    for (int ni = 0; ni < 8; ni++)
        bA[ni] = (unsigned)__cvta_generic_to_shared(&Bh[0][lane & 15][wt * 64 + ni * 8]);
    unsigned dA = (unsigned)__cvta_generic_to_shared(&Al[0][0][0]) -
                  (unsigned)__cvta_generic_to_shared(&Ah[0][0][0]);
    unsigned dB = (unsigned)__cvta_generic_to_shared(&Bl[0][0][0]) -
                  (unsigned)__cvta_generic_to_shared(&Bh[0][0][0]);
    const unsigned SA = 128 * 24 * 2, SBt = 16 * 136 * 2;

    int brow = tid >> 4, bcb = (tid & 15) * 8;
    int arow = tid >> 1, ahalf = (tid & 1) * 8;

    float vr[8];
    cp16(&Ah[0][arow][ahalf], g_fbA + arow * 512 + ahalf);
    cp16(&Al[0][arow][ahalf], g_fbA + 65536 + arow * 512 + ahalf);
    CP_COMMIT();
    {
        const float* src = xb + t0 + brow + bcb;
#pragma unroll
        for (int j = 0; j < 8; j++) vr[j] = src[j];
        CONV_B(0);
        const float* s1 = xb + t0 + 16 + brow + bcb;
#pragma unroll
        for (int j = 0; j < 8; j++) vr[j] = s1[j];
    }
    CP_WAIT0(); __syncthreads();

    for (int ck = 0; ck < 32; ck++) {
        int s = ck & 1;
        if (ck + 1 < 32) {
            int kc1 = (ck + 1) * 16;
            cp16(&Ah[s ^ 1][arow][ahalf], g_fbA + arow * 512 + kc1 + ahalf);
            cp16(&Al[s ^ 1][arow][ahalf], g_fbA + 65536 + arow * 512 + kc1 + ahalf);
            CP_COMMIT();
            CONV_B(s ^ 1);
            if (ck + 2 < 32) {
                const float* src = xb + t0 + (ck + 2) * 16 + brow + bcb;
#pragma unroll
                for (int j = 0; j < 8; j++) vr[j] = src[j];
            }
        }
        MMA_CONSUME(s * SA, s * SBt);
        if (ck + 1 < 32) CP_WAIT0();
        __syncthreads();
    }
    int gid = lane >> 2, tig = lane & 3;
#pragma unroll
    for (int mi = 0; mi < 2; mi++) {
        int c = wu * 32 + mi * 16 + gid;
        float* y0 = g_bufA + (b * NC + c) * NTP + GOF;
        float* y8 = y0 + 8 * NTP;
#pragma unroll
        for (int ni = 0; ni < 8; ni++) {
            int t = t0 + wt * 64 + ni * 8 + tig * 2;
            *(float2*)(y0 + t) = make_float2(acc[mi][ni][0], acc[mi][ni][1]);
            *(float2*)(y8 + t) = make_float2(acc[mi][ni][2], acc[mi][ni][3]);
        }
    }
}

// ---------------- residual dilated layer (bf16x3, K=256, sparse, 1 sync/chunk) ----------------
__global__ void __launch_bounds__(256, 2) k_layer_mma(int srcIsA, int lidx,
                                                      const float* __restrict__ bias,
                                                      int o0, int o1, int sparse, int lvl) {
    __shared__ __align__(16) __nv_bfloat16 Ah[2][128][24];
    __shared__ __align__(16) __nv_bfloat16 Al[2][128][24];
    __shared__ __align__(16) __nv_bfloat16 Bh[2][16][136];
    __shared__ __align__(16) __nv_bfloat16 Bl[2][16][136];
    const float* X = srcIsA ? g_bufA : g_bufB;
    float* Y = srcIsA ? g_bufB : g_bufA;
    int tid = threadIdx.x;
    int b = blockIdx.y, blk = blockIdx.x, t0 = blk * 128;

    if (sparse && !g_act[b * 256 + blk]) {
        int tx = tid & 15, ty = tid >> 4;
#pragma unroll
        for (int i = 0; i < 8; i++) {
            float v = g_base[(lvl + 1) * 128 + ty * 8 + i];
#pragma unroll
            for (int j = 0; j < 8; j++) {
                int t = t0 + ((j < 4) ? (tx * 4 + j) : (64 + tx * 4 + j - 4));
                Y[(b * NC + ty * 8 + i) * NTP + GOF + t] = v;
            }
        }
        return;
    }

    int w = tid >> 5, lane = tid & 31;
    int wu = w >> 1, wt = w & 1;
    int q = lane >> 3, r = lane & 7;
    const float* Xb = X + b * NC * NTP;
    int dOff = o1 - o0;
    const __nv_bfloat16* WAh = g_WA + (size_t)(lidx * 2 + 0) * 32768;
    const __nv_bfloat16* WAl = g_WA + (size_t)(lidx * 2 + 1) * 32768;

    float acc[2][8][4];
#pragma unroll
    for (int mi = 0; mi < 2; mi++)
#pragma unroll
        for (int ni = 0; ni < 8; ni++)
#pragma unroll
            for (int v = 0; v < 4; v++) acc[mi][ni][v] = 0.f;

    unsigned aA[2], bA[8];
#pragma unroll
    for (int mi = 0; mi < 2; mi++)
        aA[mi] = (unsigned)__cvta_generic_to_shared(
            &Ah[0][wu * 32 + mi * 16 + (q & 1) * 8 + r][(q >> 1) * 8]);
#pragma unroll
    for (int ni = 0; ni < 8; ni++)
        bA[ni] = (unsigned)__cvta_generic_to_shared(&Bh[0][lane & 15][wt * 64 + ni * 8]);
    unsigned dA = (unsigned)__cvta_generic_to_shared(&Al[0][0][0]) -
                  (unsigned)__cvta_generic_to_shared(&Ah[0][0][0]);
    unsigned dB = (unsigned)__cvta_generic_to_shared(&Bl[0][0][0]) -
                  (unsigned)__cvta_generic_to_shared(&Bh[0][0][0]);
    const unsigned SA = 128 * 24 * 2, SBt = 16 * 136 * 2;

    int brow = tid >> 4, bcb = (tid & 15) * 8;
    int arow = tid >> 1, ahalf = (tid & 1) * 8;

    float vr[8];
    cp16(&Ah[0][arow][ahalf], WAh + arow * 256 + ahalf);
    cp16(&Al[0][arow][ahalf], WAl + arow * 256 + ahalf);
    CP_COMMIT();
    {
        int k = brow;
        const float* src = Xb + (k >> 1) * NTP + GOF + t0 + o0 + (k & 1) * dOff + bcb;
#pragma unroll
        for (int j = 0; j < 8; j++) vr[j] = src[j];
        CONV_B(0);
        k = 16 + brow;
        const float* s1 = Xb + (k >> 1) * NTP + GOF + t0 + o0 + (k & 1) * dOff + bcb;
#pragma unroll
        for (int j = 0; j < 8; j++) vr[j] = s1[j];
    }
    CP_WAIT0(); __syncthreads();

    for (int ck = 0; ck < 16; ck++) {
        int s = ck & 1;
        if (ck + 1 < 16) {
            int kc1 = (ck + 1) * 16;
            cp16(&Ah[s ^ 1][arow][ahalf], WAh + arow * 256 + kc1 + ahalf);
            cp16(&Al[s ^ 1][arow][ahalf], WAl + arow * 256 + kc1 + ahalf);
            CP_COMMIT();
            CONV_B(s ^ 1);
            if (ck + 2 < 16) {
                int k = (ck + 2) * 16 + brow;
                const float* src = Xb + (k >> 1) * NTP + GOF + t0 + o0 + (k & 1) * dOff + bcb;
#pragma unroll
                for (int j = 0; j < 8; j++) vr[j] = src[j];
            }
        }
        MMA_CONSUME(s * SA, s * SBt);
        if (ck + 1 < 16) CP_WAIT0();
        __syncthreads();
    }
    int gid = lane >> 2, tig = lane & 3;
#pragma unroll
    for (int mi = 0; mi < 2; mi++) {
        int c = wu * 32 + mi * 16 + gid;
        float bi0 = bias[c], bi8 = bias[c + 8];
        const float* x0 = Xb + c * NTP + GOF;
        const float* x8 = x0 + 8 * NTP;
        float* y0 = Y + (b * NC + c) * NTP + GOF;
        float* y8 = y0 + 8 * NTP;
#pragma unroll
        for (int ni = 0; ni < 8; ni++) {
            int t = t0 + wt * 64 + ni * 8 + tig * 2;
            float h0 = acc[mi][ni][0] + bi0; h0 = (h0 > 0.f) ? h0 : 0.2f * h0;
            float h1 = acc[mi][ni][1] + bi0; h1 = (h1 > 0.f) ? h1 : 0.2f * h1;
            float h2 = acc[mi][ni][2] + bi8; h2 = (h2 > 0.f) ? h2 : 0.2f * h2;
            float h3 = acc[mi][ni][3] + bi8; h3 = (h3 > 0.f) ? h3 : 0.2f * h3;
            float2 xa = *(const float2*)(x0 + t);
            float2 xb2 = *(const float2*)(x8 + t);
            *(float2*)(y0 + t) = make_float2(xa.x + h0, xa.y + h1);
            *(float2*)(y8 + t) = make_float2(xb2.x + h2, xb2.y + h3);
        }
    }
}

// ---------------- encoder output transpose -> bf16 [b][t][c] ----------------
__global__ void k_xB() {
    __shared__ float tile[32][33];
    int b = blockIdx.z;
    int t0 = blockIdx.x * 32, c0 = blockIdx.y * 32;
    int lx = threadIdx.x, ly = threadIdx.y;
#pragma unroll
    for (int i = 0; i < 32; i += 8)
        tile[ly + i][lx] = g_bufA[(b * NC + c0 + ly + i) * NTP + GOF + t0 + lx];
    __syncthreads();
#pragma unroll
    for (int i = 0; i < 32; i += 8) {
        int t = t0 + ly + i, c = c0 + lx;
        g_xB[(long)(b * NT + t) * 128 + c] = __float2bfloat16(tile[lx][ly + i]);
    }
}

// ---------------- subsampled up-projection ----------------
__global__ void __launch_bounds__(256) k_sub(const float* __restrict__ up_b) {
    __shared__ float es[16][128];
    int b = blockIdx.z;
    int u = blockIdx.x * 256 + threadIdx.x;
    int ts0 = blockIdx.y * 16;
    const float* E = g_bufA + b * NC * NTP + GOF;
    for (int i = threadIdx.x; i < 16 * 128; i += 256) {
        int tsl = i >> 7, c = i & 127;
        es[tsl][c] = E[c * NTP + (ts0 + tsl) * 64];
    }
    __syncthreads();
    float acc[16];
    float bi = up_b[u];
#pragma unroll
    for (int j = 0; j < 16; j++) acc[j] = bi;
    for (int c = 0; c < 128; c++) {
        float w = g_upwT[c * 2048 + u];
#pragma unroll
        for (int j = 0; j < 16; j++) acc[j] += w * es[j][c];
    }
#pragma unroll
    for (int j = 0; j < 16; j++)
        g_ysub[(b * 2048 + u) * 512 + ts0 + j] = acc[j];
}

__device__ __forceinline__ unsigned f2ord(float v) {
    unsigned u = __float_as_uint(v);
    return (u & 0x80000000u) ? ~u : (u | 0x80000000u);
}
__device__ __forceinline__ float ord2f(unsigned k) {
    unsigned u = (k & 0x80000000u) ? (k ^ 0x80000000u) : ~k;
    return __uint_as_float(u);
}

// ---------------- parallel threshold ----------------
__global__ void k_h1() {
    __shared__ unsigned hist[2048];
    int b = blockIdx.y;
    const float* ys = g_ysub + b * 2048 * 512;
    for (int i = threadIdx.x; i < 2048; i += 256) hist[i] = 0;
    __syncthreads();
    for (int i = blockIdx.x * 256 + threadIdx.x; i < 2048 * 512; i += gridDim.x * 256)
        atomicAdd(&hist[f2ord(ys[i]) >> 21], 1u);
    __syncthreads();
    for (int i = threadIdx.x; i < 2048; i += 256)
        if (hist[i]) atomicAdd(&g_h1[b * 2048 + i], hist[i]);
}
__global__ void k_tmid() {
    int b = blockIdx.x;
    if (threadIdx.x == 0) {
        unsigned acc = 0;
        int b1 = 0, m = 64;
        for (int i = 2047; i >= 0; i--) {
            unsigned h = g_h1[b * 2048 + i];
            acc += h;
            if (acc >= 64) { b1 = i; m = 64 - (int)(acc - h); break; }
        }
        g_tb1[b] = b1; g_tm[b] = m;
    }
    for (int i = threadIdx.x; i < 2048; i += blockDim.x) g_h2[b * 2048 + i] = 0;
}
__global__ void k_h2() {
    __shared__ unsigned hist[2048];
    int b = blockIdx.y;
    int b1 = g_tb1[b];
    const float* ys = g_ysub + b * 2048 * 512;
    for (int i = threadIdx.x; i < 2048; i += 256) hist[i] = 0;
    __syncthreads();
    for (int i = blockIdx.x * 256 + threadIdx.x; i < 2048 * 512; i += gridDim.x * 256) {
        unsigned key = f2ord(ys[i]);
        if ((int)(key >> 21) == b1) atomicAdd(&hist[(key >> 10) & 2047], 1u);
    }
    __syncthreads();
    for (int i = threadIdx.x; i < 2048; i += 256)
        if (hist[i]) atomicAdd(&g_h2[b * 2048 + i], hist[i]);
}
__global__ void k_tfin() {
    int b = blockIdx.x;
    if (threadIdx.x) return;
    int m = g_tm[b];
    unsigned acc = 0;
    int b2 = 0;
    for (int i = 2047; i >= 0; i--) {
        acc += g_h2[b * 2048 + i];
        if ((int)acc >= m) { b2 = i; break; }
    }
    unsigned tk = ((unsigned)g_tb1[b] << 21) | ((unsigned)b2 << 10);
    if (tk >= (1u << 10)) tk -= (1u << 10);
    float tf = ord2f(tk);
    g_thresh[b] = tf - 0.05f * fabsf(tf);
    g_candCnt[b] = 0;
}

// ---------------- up-projection (bf16 single-plane, K=128, 3-stage B) ----------------
__global__ void __launch_bounds__(256, 2) k_up_mma(const float* __restrict__ up_b) {
    __shared__ __align__(16) __nv_bfloat16 Ah[128][136];
    __shared__ __align__(16) __nv_bfloat16 Bs[3][128][24];
    int tid = threadIdx.x;
    int b = blockIdx.z;
    int u0 = blockIdx.y * 128;
    int t0 = blockIdx.x * 128;
    int w = tid >> 5, lane = tid & 31;
    int wu = w >> 1, wt = w & 1;
    int q = lane >> 3, r = lane & 7;

    const __nv_bfloat16* Bg = g_xB + (long)(b * NT + t0) * 128;
    int lr = tid >> 1, lh = tid & 1;

    // G0: A + B0; G1: B1
    for (int i = tid; i < 2048; i += 256) {
        int row = i >> 4, c8 = (i & 15) * 8;
        cp16(&Ah[row][c8], g_upA + (u0 + row) * 128 + c8);
    }
    cp16(&Bs[0][lr][lh * 8], Bg + lr * 128 + 0 + lh * 8);
    CP_COMMIT();
    cp16(&Bs[1][lr][lh * 8], Bg + lr * 128 + 16 + lh * 8);
    CP_COMMIT();

    float acc[2][8][4];
#pragma unroll
    for (int mi = 0; mi < 2; mi++)
#pragma unroll
        for (int ni = 0; ni < 8; ni++)
#pragma unroll
            for (int v = 0; v < 4; v++) acc[mi][ni][v] = 0.f;

    unsigned aA[2], bA[8];
#pragma unroll
    for (int mi = 0; mi < 2; mi++)
        aA[mi] = (unsigned)__cvta_generic_to_shared(
            &Ah[wu * 32 + mi * 16 + (q & 1) * 8 + r][(q >> 1) * 8]);
#pragma unroll
    for (int ni = 0; ni < 8; ni++)
        bA[ni] = (unsigned)__cvta_generic_to_shared(
            &Bs[0][wt * 64 + ni * 8 + r][(q & 1) * 8]);
    const unsigned SB = 128 * 24 * 2;

    for (int ck = 0; ck < 8; ck++) {
        if (ck < 6) CP_WAIT1(); else CP_WAIT0();
        __syncthreads();
        if (ck + 2 < 8) {
            cp16(&Bs[(ck + 2) % 3][lr][lh * 8], Bg + lr * 128 + (ck + 2) * 16 + lh * 8);
            CP_COMMIT();
        }
        unsigned bq[8][2], af[2][4];
        unsigned sB = (unsigned)(ck % 3) * SB;
#pragma unroll
        for (int ni = 0; ni < 8; ni++) ldmB2(bq[ni], bA[ni] + sB);
#pragma unroll
        for (int mi = 0; mi < 2; mi++) ldmA4(af[mi], aA[mi] + ck * 32);
#pragma unroll
        for (int mi = 0; mi < 2; mi++)
#pragma unroll
            for (int ni = 0; ni < 8; ni++) mma16816(acc[mi][ni], af[mi], bq[ni]);
    }

    float T0 = g_thresh[b];
    int gid = lane >> 2, tig = lane & 3;
#pragma unroll
    for (int mi = 0; mi < 2; mi++) {
        int ub = u0 + wu * 32 + mi * 16 + gid;
        float bi0 = up_b[ub];
        float bi8 = up_b[ub + 8];
#pragma unroll
        for (int ni = 0; ni < 8; ni++) {
            int tb = t0 + wt * 64 + ni * 8 + tig * 2;
            float vv[4] = {acc[mi][ni][0] + bi0, acc[mi][ni][1] + bi0,
                           acc[mi][ni][2] + bi8, acc[mi][ni][3] + bi8};
            int uu[4] = {ub, ub, ub + 8, ub + 8};
            int tt[4] = {tb, tb + 1, tb, tb + 1};
#pragma unroll
            for (int v = 0; v < 4; v++) {
                if (vv[v] >= T0) {
                    int idx = atomicAdd(&g_candCnt[b], 1);
                    if (idx < CAP) {
                        g_candVal[b * CAP + idx] = vv[v];
                        g_candPack[b * CAP + idx] =
                            ((unsigned)uu[v] << 16) | (unsigned)tt[v];
                    }
                }
            }
        }
    }
}

__global__ void k_rescoreAll(const float* __restrict__ up_w, const float* __restrict__ up_b) {
    int b = blockIdx.y;
    int cnt = g_candCnt[b];
    if (cnt > CAP) cnt = CAP;
    int warpId = blockIdx.x * 8 + (threadIdx.x >> 5);
    int nw = gridDim.x * 8;
    int lane = threadIdx.x & 31;
    for (int i = warpId; i < cnt; i += nw) {
        unsigned pack = g_candPack[b * CAP + i];
        int u = (int)(pack >> 16), t = (int)(pack & 0xFFFFu);
        float s = 0.f;
#pragma unroll
        for (int c = lane; c < 128; c += 32)
            s += up_w[u * 128 + c] * g_bufA[(b * NC + c) * NTP + GOF + t];
#pragma unroll
        for (int o = 16; o; o >>= 1) s += __shfl_xor_sync(0xFFFFFFFFu, s, o);
        if (lane == 0) g_candVal[b * CAP + i] = s + up_b[u];
    }
}

__global__ void k_select() {
    __shared__ ull keys[5632];
    __shared__ ull red[256];
    int b = blockIdx.x, tid = threadIdx.x;
    int cnt = g_candCnt[b];
    if (cnt > CAP) cnt = CAP;
    bool useS = (cnt <= 5632);
    if (useS) {
        for (int i = tid; i < cnt; i += 256) {
            unsigned key = f2ord(g_candVal[b * CAP + i]);
            unsigned pack = g_candPack[b * CAP + i];
            keys[i] = ((ull)key << 32) | (ull)(~pack);
        }
    }
    __syncthreads();
    ull prev = 0xFFFFFFFFFFFFFFFFull;
    for (int r = 0; r < 64; r++) {
        ull best = 0;
        if (useS) {
            for (int i = tid; i < cnt; i += 256) {
                ull k64 = keys[i];
                if (k64 < prev && k64 > best) best = k64;
            }
        } else {
            for (int i = tid; i < cnt; i += 256) {
                unsigned key = f2ord(g_candVal[b * CAP + i]);
                unsigned pack = g_candPack[b * CAP + i];
                ull k64 = ((ull)key << 32) | (ull)(~pack);
                if (k64 < prev && k64 > best) best = k64;
            }
        }
        red[tid] = best;
        __syncthreads();
        for (int s = 128; s > 0; s >>= 1) {
            if (tid < s) { if (red[tid + s] > red[tid]) red[tid] = red[tid + s]; }
            __syncthreads();
        }
        best = red[0];
        if (tid == 0) {
            unsigned key = (unsigned)(best >> 32);
            unsigned pack = ~((unsigned)best);
            g_selVal[b * 64 + r] = ord2f(key);
            g_selU[b * 64 + r] = (int)(pack >> 16);
            g_selT[b * 64 + r] = (int)(pack & 0xFFFFu);
        }
        prev = best;
        __syncthreads();
    }
}

// ---------------- fused base iteration + flags + pref (1 CTA, 512 thr) ----------------
__global__ void k_bpf(const float* __restrict__ down_b, const float* __restrict__ dec_b,
                      const float* __restrict__ fb) {
    __shared__ float cur[128];
    __shared__ float pr[512];
    int tid = threadIdx.x;
    // phase A: decoder steady-state iteration (threads 0..127 compute, all sync)
    if (tid < 128) { cur[tid] = down_b[tid]; g_base[tid] = cur[tid]; }
    __syncthreads();
    for (int l = 0; l < 6; l++) {
        float nv = 0.f;
        if (tid < 128) {
            const float* Wt = g_Wt + (6 + l) * 32768;
            float h = dec_b[l * 128 + tid];
            for (int ci = 0; ci < 128; ci++)
                h += (Wt[(2 * ci) * 128 + tid] + Wt[(2 * ci + 1) * 128 + tid]) * cur[ci];
            h = (h > 0.f) ? h : 0.2f * h;
            nv = cur[tid] + h;
        }
        __syncthreads();
        if (tid < 128) { cur[tid] = nv; g_base[(l + 1) * 128 + tid] = nv; }
        __syncthreads();
    }
    // phase B: active-block flags (512 threads = NB*256)
    {
        int b = tid >> 8, blk = tid & 255;
        int lo = blk * 128, hi = lo + 127;
        int act = (lo < 123) ? 1 : 0;
        for (int e = 0; e < 64; e++) {
            int s = g_selT[b * 64 + e];
            if (s <= hi && s + 122 >= lo) act = 1;
        }
        g_act[tid] = act;
    }
    // phase C: pref (const synthesis prefix sums)
    {
        float s = 0.f;
        for (int c = 0; c < 128; c++) s += cur[c] * fb[c * 512 + tid];
        pr[tid] = s;
    }
    __syncthreads();
    if (tid == 0) {
        float acc = 0.f;
        g_pref[0] = 0.f;
        for (int k = 0; k < 512; k++) { acc += pr[k]; g_pref[k + 1] = acc; }
    }
}

__global__ void k_fill(const float* __restrict__ down_b) {
    int idx = blockIdx.x * 256 + threadIdx.x;
    if (idx >= NB * NC * NT / 4) return;
    int row = idx >> 13, t4 = idx & 8191;
    float v = down_b[row & 127];
    *(float4*)(&g_bufB[row * NTP + GOF + t4 * 4]) = make_float4(v, v, v, v);
}

__global__ void k_scatter(const float* __restrict__ down_w) {
    int tid = threadIdx.x;
    int b = tid >> 7, c = tid & 127;
    float* dst = g_bufB + (b * NC + c) * NTP + GOF;
    for (int e = 0; e < 64; e++) {
        float v = g_selVal[b * 64 + e];
        int u = g_selU[b * 64 + e];
        int t = g_selT[b * 64 + e];
        dst[t] += down_w[c * 2048 + u] * v;
    }
}

__global__ void k_fillOut(float* __restrict__ out) {
    int idx = blockIdx.x * 256 + threadIdx.x;
    if (idx >= NB * NT) return;
    int t = idx & (NT - 1);
    int jlo = 256 + t - (NT - 1); if (jlo < 0) jlo = 0;
    int jhi = 256 + t; if (jhi > 511) jhi = 511;
    out[idx] = g_pref[jhi + 1] - g_pref[jlo];
}

__global__ void __launch_bounds__(256) k_corr(const float* __restrict__ fb,
                                              float* __restrict__ out) {
    __shared__ __align__(16) float fbx[8][768];
    __shared__ __align__(16) float dev[8][128];
    int b = blockIdx.z, blk = blockIdx.x, cg = blockIdx.y;
    if (!g_act[b * 256 + blk]) return;
    int s = blk * 128;
    int tid = threadIdx.x;
    const float* D = g_bufB + b * NC * NTP + GOF;

    for (int i = tid; i < 8 * 256; i += 256) {
        int c = i >> 8, p = i & 255;
        fbx[c][(p < 128) ? p : (512 + p)] = 0.f;
    }
    for (int i = tid; i < 8 * 512; i += 256)
        fbx[i >> 9][128 + (i & 511)] = fb[(cg * 8 + (i >> 9)) * 512 + (i & 511)];
    for (int i = tid; i < 8 * 128; i += 256) {
        int c = i >> 7, col = i & 127;
        dev[c][col] = D[(cg * 8 + c) * NTP + s + col] - g_base[768 + cg * 8 + c];
    }
    __syncthreads();

    if (tid >= 160) return;
    float a0 = 0.f, a1 = 0.f, a2 = 0.f, a3 = 0.f;
    int t0 = 4 * tid;
#pragma unroll 2
    for (int c = 0; c < 8; c++) {
        const float* fx = &fbx[c][0];
        const float4* dv4 = (const float4*)&dev[c][0];
        int m0 = t0 + 4;
        float4 fa = *(const float4*)&fx[m0 - 4];
        for (int c4 = 31; c4 >= 0; c4--) {
            float4 d4 = dv4[c4];
            float4 fbv = *(const float4*)&fx[m0];
            float wm3 = fa.y, wm2 = fa.z, wm1 = fa.w;
            a0 += fbv.x * d4.x + wm1 * d4.y + wm2 * d4.z + wm3 * d4.w;
            a1 += fbv.y * d4.x + fbv.x * d4.y + wm1 * d4.z + wm2 * d4.w;
            a2 += fbv.z * d4.x + fbv.y * d4.y + fbv.x * d4.z + wm1 * d4.w;
            a3 += fbv.w * d4.x + fbv.z * d4.y + fbv.y * d4.z + fbv.x * d4.w;
            fa = fbv;
            m0 += 4;
        }
    }
    float av[4] = {a0, a1, a2, a3};
#pragma unroll
    for (int qd = 0; qd < 4; qd++) {
        int t = t0 + qd;
        if (t < 639) {
            int tg = s - 256 + t;
            if (tg >= 0 && tg < NT && av[qd] != 0.f)
                atomicAdd(&out[b * NT + tg], av[qd]);
        }
    }
}

// ---------------- host driver ----------------
extern "C" void kernel_launch(void* const* d_in, const int* in_sizes, int n_in,
                              void* d_out, int out_size) {
    const float* x      = (const float*)d_in[0];
    const float* fb     = (const float*)d_in[1];
    const float* enc_w  = (const float*)d_in[2];
    const float* enc_b  = (const float*)d_in[3];
    const float* up_w   = (const float*)d_in[4];
    const float* up_b   = (const float*)d_in[5];
    const float* down_w = (const float*)d_in[6];
    const float* down_b = (const float*)d_in[7];
    const float* dec_w  = (const float*)d_in[8];
    const float* dec_b  = (const float*)d_in[9];
    float* out = (float*)d_out;

    static const int dil[6] = {1, 3, 9, 27, 81, 1};

    int prepTotal = 393216 * 2 + 65536 + 262144 * 2 + NB * XP + 262144 + NB * 2048;
    k_prep<<<(prepTotal + 255) / 256, 256>>>(enc_w, dec_w, fb, up_w, x);

    k_fb_mma<<<dim3(NT / 128, NB), 256>>>();

    int srcIsA = 1;
    for (int l = 0; l < 6; l++) {
        k_layer_mma<<<dim3(256, NB), 256>>>(srcIsA, l, enc_b + l * 128, 0, dil[l], 0, 0);
        srcIsA ^= 1;
    }

    k_xB<<<dim3(NT / 32, NC / 32, NB), dim3(32, 8)>>>();
    k_sub<<<dim3(NU / 256, 512 / 16, NB), 256>>>(up_b);
    k_h1<<<dim3(64, NB), 256>>>();
    k_tmid<<<NB, 256>>>();
    k_h2<<<dim3(64, NB), 256>>>();
    k_tfin<<<NB, 32>>>();
    k_up_mma<<<dim3(NT / 128, NU / 128, NB), 256>>>(up_b);
    k_rescoreAll<<<dim3(64, NB), 256>>>(up_w, up_b);
    k_select<<<NB, 256>>>();

    k_bpf<<<1, 512>>>(down_b, dec_b, fb);
    k_fill<<<(NB * NC * NT / 4 + 255) / 256, 256>>>(down_b);
    k_scatter<<<1, 256>>>(down_w);

    srcIsA = 0;
    for (int l = 0; l < 6; l++) {
        k_layer_mma<<<dim3(256, NB), 256>>>(srcIsA, 6 + l, dec_b + l * 128, -dil[l], 0, 1, l);
        srcIsA ^= 1;
    }

    k_fillOut<<<(NB * NT + 255) / 256, 256>>>(out);
    k_corr<<<dim3(256, 16, NB), 256>>>(fb, out);
    (void)in_sizes; (void)n_in; (void)out_size;
}

// round 15
// speedup vs baseline: 1.7149x; 1.0433x over previous
#include <cuda_runtime.h>
#include <cuda_bf16.h>
#include <cstdint>

#define NB 2
#define NC 128
#define NU 2048
#define NZK 64
#define NT 32768
#define NTP (NT + 512)
#define GOF 256
#define XP  (NT + 512)
#define CAP (1<<18)

typedef unsigned long long ull;

static __device__ __align__(16) float g_bufA[NB*NC*NTP];
static __device__ __align__(16) float g_bufB[NB*NC*NTP];
static __device__ __align__(16) float g_Wt[12*256*128];
static __device__ __align__(16) float g_upwT[128*2048];
static __device__ __align__(16) float g_xp[NB*XP];
static __device__ __align__(16) __nv_bfloat16 g_WA[12*2*128*256];
static __device__ __align__(16) __nv_bfloat16 g_fbA[2*128*512];
static __device__ __align__(16) __nv_bfloat16 g_upA[NU*128];
static __device__ __align__(16) __nv_bfloat16 g_xB[(long)NB*NT*128];
static __device__ float g_ysub[NB*2048*512];
static __device__ float g_thresh[NB];
static __device__ int   g_candCnt[NB];
static __device__ float g_candVal[NB*CAP];
static __device__ unsigned g_candPack[NB*CAP];
static __device__ float g_selVal[NB*NZK];
static __device__ int   g_selU[NB*NZK];
static __device__ int   g_selT[NB*NZK];
static __device__ float g_base[7*128];
static __device__ int   g_act[NB*256];
static __device__ float g_pref[513];
static __device__ unsigned g_h1[NB*2048];
static __device__ unsigned g_h2[NB*2048];
static __device__ int g_tb1[NB];
static __device__ int g_tm[NB];

__device__ __forceinline__ void cp16(void* dst, const void* src) {
    unsigned d = (unsigned)__cvta_generic_to_shared(dst);
    asm volatile("cp.async.cg.shared.global [%0], [%1], 16;\n" :: "r"(d), "l"(src));
}
#define CP_COMMIT() asm volatile("cp.async.commit_group;\n")
#define CP_WAIT0()  asm volatile("cp.async.wait_group 0;\n")
#define CP_WAIT1()  asm volatile("cp.async.wait_group 1;\n")

__device__ __forceinline__ void ldmA4(unsigned* a, unsigned addr) {
    asm volatile("ldmatrix.sync.aligned.m8n8.x4.shared.b16 {%0,%1,%2,%3}, [%4];"
                 : "=r"(a[0]), "=r"(a[1]), "=r"(a[2]), "=r"(a[3]) : "r"(addr));
}
__device__ __forceinline__ void ldmB4t(unsigned* bq, unsigned addr) {
    asm volatile("ldmatrix.sync.aligned.m8n8.x4.trans.shared.b16 {%0,%1,%2,%3}, [%4];"
                 : "=r"(bq[0]), "=r"(bq[1]), "=r"(bq[2]), "=r"(bq[3]) : "r"(addr));
}
__device__ __forceinline__ void mma16816(float* c, const unsigned* a, const unsigned* bq) {
    asm volatile("mma.sync.aligned.m16n8k16.row.col.f32.bf16.bf16.f32 "
                 "{%0,%1,%2,%3}, {%4,%5,%6,%7}, {%8,%9}, {%0,%1,%2,%3};"
                 : "+f"(c[0]), "+f"(c[1]), "+f"(c[2]), "+f"(c[3])
                 : "r"(a[0]), "r"(a[1]), "r"(a[2]), "r"(a[3]), "r"(bq[0]), "r"(bq[1]));
}
__device__ __forceinline__ unsigned pkbf(float a, float b) {
    unsigned lo = (unsigned)__bfloat16_as_ushort(__float2bfloat16(a));
    unsigned hi = (unsigned)__bfloat16_as_ushort(__float2bfloat16(b));
    return lo | (hi << 16);
}

// ---------------- fused prep ----------------
__global__ void k_prep(const float* __restrict__ enc_w, const float* __restrict__ dec_w,
                       const float* __restrict__ fb, const float* __restrict__ up_w,
                       const float* __restrict__ x) {
    int idx = blockIdx.x * 256 + threadIdx.x;
    if (idx < 393216) {
        int l = idx / 32768;
        int r = idx - l * 32768;
        int k = r >> 7, c = r & 127;
        const float* w = (l < 6) ? (enc_w + l * 32768) : (dec_w + (l - 6) * 32768);
        g_Wt[idx] = w[(c * 128 + (k >> 1)) * 2 + (k & 1)];
        return;
    }
    idx -= 393216;
    if (idx < 393216) {
        int l = idx / 32768;
        int r = idx - l * 32768;
        int c = r >> 8, k = r & 255;
        const float* w = (l < 6) ? (enc_w + l * 32768) : (dec_w + (l - 6) * 32768);
        float v = w[(c * 128 + (k >> 1)) * 2 + (k & 1)];
        __nv_bfloat16 h = __float2bfloat16(v);
        g_WA[((l * 2 + 0) * 128 + c) * 256 + k] = h;
        g_WA[((l * 2 + 1) * 128 + c) * 256 + k] = __float2bfloat16(v - __bfloat162float(h));
        return;
    }
    idx -= 393216;
    if (idx < 65536) {
        float v = fb[idx];
        __nv_bfloat16 h = __float2bfloat16(v);
        g_fbA[idx] = h;
        g_fbA[65536 + idx] = __float2bfloat16(v - __bfloat162float(h));
        return;
    }
    idx -= 65536;
    if (idx < 262144) {
        int c = idx >> 11, u = idx & 2047;
        g_upwT[idx] = up_w[u * 128 + c];
        return;
    }
    idx -= 262144;
    if (idx < 262144) {
        g_upA[idx] = __float2bfloat16(up_w[idx]);
        return;
    }
    idx -= 262144;
    if (idx < NB * XP) {
        int b = idx / XP, w = idx - b * XP;
        g_xp[idx] = (w >= GOF && w < NT + GOF) ? x[b * NT + (w - GOF)] : 0.f;
        return;
    }
    idx -= NB * XP;
    if (idx < 262144) {
        int half = NB * NC * 512;
        float* buf = (idx < half) ? g_bufA : g_bufB;
        int r = (idx < half) ? idx : idx - half;
        int row = r >> 9, w = r & 511;
        int pos = (w < 256) ? w : (NT + 256 + (w - 256));
        buf[row * NTP + pos] = 0.f;
        return;
    }
    idx -= 262144;
    if (idx < NB * 2048) g_h1[idx] = 0;
}

// consume: 3 product groups, A-reuse, x4 B loads (12 LDSM total)
#define MMA_CONSUME(sA, sB) {                                                \
    unsigned afH[2][4], afL[2][4], bq[4][4];                                 \
    _Pragma("unroll") for (int mi = 0; mi < 2; mi++) ldmA4(afH[mi], aA[mi] + (sA)); \
    _Pragma("unroll") for (int mi = 0; mi < 2; mi++) ldmA4(afL[mi], aA[mi] + (sA) + dA); \
    _Pragma("unroll") for (int nj = 0; nj < 4; nj++) ldmB4t(bq[nj], bA[nj] + (sB)); \
    _Pragma("unroll") for (int mi = 0; mi < 2; mi++)                         \
        _Pragma("unroll") for (int nj = 0; nj < 4; nj++) {                   \
            mma16816(acc[mi][nj*2],   afH[mi], &bq[nj][0]);                  \
            mma16816(acc[mi][nj*2+1], afH[mi], &bq[nj][2]);                  \
        }                                                                    \
    _Pragma("unroll") for (int mi = 0; mi < 2; mi++)                         \
        _Pragma("unroll") for (int nj = 0; nj < 4; nj++) {                   \
            mma16816(acc[mi][nj*2],   afL[mi], &bq[nj][0]);                  \
            mma16816(acc[mi][nj*2+1], afL[mi], &bq[nj][2]);                  \
        }                                                                    \
    _Pragma("unroll") for (int nj = 0; nj < 4; nj++) ldmB4t(bq[nj], bA[nj] + (sB) + dB); \
    _Pragma("unroll") for (int mi = 0; mi < 2; mi++)                         \
        _Pragma("unroll") for (int nj = 0; nj < 4; nj++) {                   \
            mma16816(acc[mi][nj*2],   afH[mi], &bq[nj][0]);                  \
            mma16816(acc[mi][nj*2+1], afH[mi], &bq[nj][2]);                  \
        }                                                                    \
    }

#define CONV_B(st) {                                                         \
    _Pragma("unroll") for (int jj = 0; jj < 4; jj++) {                       \
        float v0 = vr[2 * jj], v1 = vr[2 * jj + 1];                          \
        float h0 = __bfloat162float(__float2bfloat16(v0));                   \
        float h1 = __bfloat162float(__float2bfloat16(v1));                   \
        *(unsigned*)&Bh[st][brow][bcb + 2 * jj] = pkbf(v0, v1);              \
        *(unsigned*)&Bl[st][brow][bcb + 2 * jj] = pkbf(v0 - h0, v1 - h1);    \
    } }

// ---------------- filterbank analysis (bf16x3, K=512) ----------------
__global__ void __launch_bounds__(256, 2) k_fb_mma() {
    __shared__ __align__(16) __nv_bfloat16 Ah[2][128][24];
    __shared__ __align__(16) __nv_bfloat16 Al[2][128][24];
    __shared__ __align__(16) __nv_bfloat16 Bh[2][16][136];
    __shared__ __align__(16) __nv_bfloat16 Bl[2][16][136];
    int tid = threadIdx.x;
    int b = blockIdx.y, t0 = blockIdx.x * 128;
    int w = tid >> 5, lane = tid & 31;
    int wu = w >> 1, wt = w & 1;
    int q = lane >> 3, r = lane & 7;
    const float* xb = g_xp + b * XP;

    float acc[2][8][4];
#pragma unroll
    for (int mi = 0; mi < 2; mi++)
#pragma unroll
        for (int ni = 0; ni < 8; ni++)
#pragma unroll
            for (int v = 0; v < 4; v++) acc[mi][ni][v] = 0.f;

    unsigned aA[2], bA[4];
#pragma unroll
    for (int mi = 0; mi < 2; mi++)
        aA[mi] = (unsigned)__cvta_generic_to_shared(
            &Ah[0][wu * 32 + mi * 16 + (q & 1) * 8 + r][(q >> 1) * 8]);
#pragma unroll
    for (int nj = 0; nj < 4; nj++)
        bA[nj] = (unsigned)__cvta_generic_to_shared(
            &Bh[0][lane & 15][wt * 64 + nj * 16 + ((lane >> 4) << 3)]);
    unsigned dA = (unsigned)__cvta_generic_to_shared(&Al[0][0][0]) -
                  (unsigned)__cvta_generic_to_shared(&Ah[0][0][0]);
    unsigned dB = (unsigned)__cvta_generic_to_shared(&Bl[0][0][0]) -
                  (unsigned)__cvta_generic_to_shared(&Bh[0][0][0]);
    const unsigned SA = 128 * 24 * 2, SBt = 16 * 136 * 2;

    int brow = tid >> 4, bcb = (tid & 15) * 8;
    int arow = tid >> 1, ahalf = (tid & 1) * 8;

    float vr[8];
    cp16(&Ah[0][arow][ahalf], g_fbA + arow * 512 + ahalf);
    cp16(&Al[0][arow][ahalf], g_fbA + 65536 + arow * 512 + ahalf);
    CP_COMMIT();
    {
        const float* src = xb + t0 + brow + bcb;
#pragma unroll
        for (int j = 0; j < 8; j++) vr[j] = src[j];
        CONV_B(0);
        const float* s1 = xb + t0 + 16 + brow + bcb;
#pragma unroll
        for (int j = 0; j < 8; j++) vr[j] = s1[j];
    }
    CP_WAIT0(); __syncthreads();

    for (int ck = 0; ck < 32; ck++) {
        int s = ck & 1;
        if (ck + 1 < 32) {
            int kc1 = (ck + 1) * 16;
            cp16(&Ah[s ^ 1][arow][ahalf], g_fbA + arow * 512 + kc1 + ahalf);
            cp16(&Al[s ^ 1][arow][ahalf], g_fbA + 65536 + arow * 512 + kc1 + ahalf);
            CP_COMMIT();
            CONV_B(s ^ 1);
            if (ck + 2 < 32) {
                const float* src = xb + t0 + (ck + 2) * 16 + brow + bcb;
#pragma unroll
                for (int j = 0; j < 8; j++) vr[j] = src[j];
            }
        }
        MMA_CONSUME(s * SA, s * SBt);
        if (ck + 1 < 32) CP_WAIT0();
        __syncthreads();
    }
    int gid = lane >> 2, tig = lane & 3;
#pragma unroll
    for (int mi = 0; mi < 2; mi++) {
        int c = wu * 32 + mi * 16 + gid;
        float* y0 = g_bufA + (b * NC + c) * NTP + GOF;
        float* y8 = y0 + 8 * NTP;
#pragma unroll
        for (int ni = 0; ni < 8; ni++) {
            int t = t0 + wt * 64 + ni * 8 + tig * 2;
            *(float2*)(y0 + t) = make_float2(acc[mi][ni][0], acc[mi][ni][1]);
            *(float2*)(y8 + t) = make_float2(acc[mi][ni][2], acc[mi][ni][3]);
        }
    }
}

// ---------------- residual dilated layer (bf16x3, K=256, sparse) ----------------
__global__ void __launch_bounds__(256, 2) k_layer_mma(int srcIsA, int lidx,
                                                      const float* __restrict__ bias,
                                                      int o0, int o1, int sparse, int lvl) {
    __shared__ __align__(16) __nv_bfloat16 Ah[2][128][24];
    __shared__ __align__(16) __nv_bfloat16 Al[2][128][24];
    __shared__ __align__(16) __nv_bfloat16 Bh[2][16][136];
    __shared__ __align__(16) __nv_bfloat16 Bl[2][16][136];
    const float* X = srcIsA ? g_bufA : g_bufB;
    float* Y = srcIsA ? g_bufB : g_bufA;
    int tid = threadIdx.x;
    int b = blockIdx.y, blk = blockIdx.x, t0 = blk * 128;

    if (sparse && !g_act[b * 256 + blk]) {
        int tx = tid & 15, ty = tid >> 4;
#pragma unroll
        for (int i = 0; i < 8; i++) {
            float v = g_base[(lvl + 1) * 128 + ty * 8 + i];
#pragma unroll
            for (int j = 0; j < 8; j++) {
                int t = t0 + ((j < 4) ? (tx * 4 + j) : (64 + tx * 4 + j - 4));
                Y[(b * NC + ty * 8 + i) * NTP + GOF + t] = v;
            }
        }
        return;
    }

    int w = tid >> 5, lane = tid & 31;
    int wu = w >> 1, wt = w & 1;
    int q = lane >> 3, r = lane & 7;
    const float* Xb = X + b * NC * NTP;
    int dOff = o1 - o0;
    const __nv_bfloat16* WAh = g_WA + (size_t)(lidx * 2 + 0) * 32768;
    const __nv_bfloat16* WAl = g_WA + (size_t)(lidx * 2 + 1) * 32768;

    float acc[2][8][4];
#pragma unroll
    for (int mi = 0; mi < 2; mi++)
#pragma unroll
        for (int ni = 0; ni < 8; ni++)
#pragma unroll
            for (int v = 0; v < 4; v++) acc[mi][ni][v] = 0.f;

    unsigned aA[2], bA[4];
#pragma unroll
    for (int mi = 0; mi < 2; mi++)
        aA[mi] = (unsigned)__cvta_generic_to_shared(
            &Ah[0][wu * 32 + mi * 16 + (q & 1) * 8 + r][(q >> 1) * 8]);
#pragma unroll
    for (int nj = 0; nj < 4; nj++)
        bA[nj] = (unsigned)__cvta_generic_to_shared(
            &Bh[0][lane & 15][wt * 64 + nj * 16 + ((lane >> 4) << 3)]);
    unsigned dA = (unsigned)__cvta_generic_to_shared(&Al[0][0][0]) -
                  (unsigned)__cvta_generic_to_shared(&Ah[0][0][0]);
    unsigned dB = (unsigned)__cvta_generic_to_shared(&Bl[0][0][0]) -
                  (unsigned)__cvta_generic_to_shared(&Bh[0][0][0]);
    const unsigned SA = 128 * 24 * 2, SBt = 16 * 136 * 2;

    int brow = tid >> 4, bcb = (tid & 15) * 8;
    int arow = tid >> 1, ahalf = (tid & 1) * 8;

    float vr[8];
    cp16(&Ah[0][arow][ahalf], WAh + arow * 256 + ahalf);
    cp16(&Al[0][arow][ahalf], WAl + arow * 256 + ahalf);
    CP_COMMIT();
    {
        int k = brow;
        const float* src = Xb + (k >> 1) * NTP + GOF + t0 + o0 + (k & 1) * dOff + bcb;
#pragma unroll
        for (int j = 0; j < 8; j++) vr[j] = src[j];
        CONV_B(0);
        k = 16 + brow;
        const float* s1 = Xb + (k >> 1) * NTP + GOF + t0 + o0 + (k & 1) * dOff + bcb;
#pragma unroll
        for (int j = 0; j < 8; j++) vr[j] = s1[j];
    }
    CP_WAIT0(); __syncthreads();

    for (int ck = 0; ck < 16; ck++) {
        int s = ck & 1;
        if (ck + 1 < 16) {
            int kc1 = (ck + 1) * 16;
            cp16(&Ah[s ^ 1][arow][ahalf], WAh + arow * 256 + kc1 + ahalf);
            cp16(&Al[s ^ 1][arow][ahalf], WAl + arow * 256 + kc1 + ahalf);
            CP_COMMIT();
            CONV_B(s ^ 1);
            if (ck + 2 < 16) {
                int k = (ck + 2) * 16 + brow;
                const float* src = Xb + (k >> 1) * NTP + GOF + t0 + o0 + (k & 1) * dOff + bcb;
#pragma unroll
                for (int j = 0; j < 8; j++) vr[j] = src[j];
            }
        }
        MMA_CONSUME(s * SA, s * SBt);
        if (ck + 1 < 16) CP_WAIT0();
        __syncthreads();
    }
    int gid = lane >> 2, tig = lane & 3;
#pragma unroll
    for (int mi = 0; mi < 2; mi++) {
        int c = wu * 32 + mi * 16 + gid;
        float bi0 = bias[c], bi8 = bias[c + 8];
        const float* x0 = Xb + c * NTP + GOF;
        const float* x8 = x0 + 8 * NTP;
        float* y0 = Y + (b * NC + c) * NTP + GOF;
        float* y8 = y0 + 8 * NTP;
#pragma unroll
        for (int ni = 0; ni < 8; ni++) {
            int t = t0 + wt * 64 + ni * 8 + tig * 2;
            float h0 = acc[mi][ni][0] + bi0; h0 = (h0 > 0.f) ? h0 : 0.2f * h0;
            float h1 = acc[mi][ni][1] + bi0; h1 = (h1 > 0.f) ? h1 : 0.2f * h1;
            float h2 = acc[mi][ni][2] + bi8; h2 = (h2 > 0.f) ? h2 : 0.2f * h2;
            float h3 = acc[mi][ni][3] + bi8; h3 = (h3 > 0.f) ? h3 : 0.2f * h3;
            float2 xa = *(const float2*)(x0 + t);
            float2 xb2 = *(const float2*)(x8 + t);
            *(float2*)(y0 + t) = make_float2(xa.x + h0, xa.y + h1);
            *(float2*)(y8 + t) = make_float2(xb2.x + h2, xb2.y + h3);
        }
    }
}

// ---------------- encoder output transpose -> bf16 [b][t][c] ----------------
__global__ void k_xB() {
    __shared__ float tile[32][33];
    int b = blockIdx.z;
    int t0 = blockIdx.x * 32, c0 = blockIdx.y * 32;
    int lx = threadIdx.x, ly = threadIdx.y;
#pragma unroll
    for (int i = 0; i < 32; i += 8)
        tile[ly + i][lx] = g_bufA[(b * NC + c0 + ly + i) * NTP + GOF + t0 + lx];
    __syncthreads();
#pragma unroll
    for (int i = 0; i < 32; i += 8) {
        int t = t0 + ly + i, c = c0 + lx;
        g_xB[(long)(b * NT + t) * 128 + c] = __float2bfloat16(tile[lx][ly + i]);
    }
}

// ---------------- subsampled up-projection ----------------
__global__ void __launch_bounds__(256) k_sub(const float* __restrict__ up_b) {
    __shared__ float es[16][128];
    int b = blockIdx.z;
    int u = blockIdx.x * 256 + threadIdx.x;
    int ts0 = blockIdx.y * 16;
    const float* E = g_bufA + b * NC * NTP + GOF;
    for (int i = threadIdx.x; i < 16 * 128; i += 256) {
        int tsl = i >> 7, c = i & 127;
        es[tsl][c] = E[c * NTP + (ts0 + tsl) * 64];
    }
    __syncthreads();
    float acc[16];
    float bi = up_b[u];
#pragma unroll
    for (int j = 0; j < 16; j++) acc[j] = bi;
    for (int c = 0; c < 128; c++) {
        float w = g_upwT[c * 2048 + u];
#pragma unroll
        for (int j = 0; j < 16; j++) acc[j] += w * es[j][c];
    }
#pragma unroll
    for (int j = 0; j < 16; j++)
        g_ysub[(b * 2048 + u) * 512 + ts0 + j] = acc[j];
}

__device__ __forceinline__ unsigned f2ord(float v) {
    unsigned u = __float_as_uint(v);
    return (u & 0x80000000u) ? ~u : (u | 0x80000000u);
}
__device__ __forceinline__ float ord2f(unsigned k) {
    unsigned u = (k & 0x80000000u) ? (k ^ 0x80000000u) : ~k;
    return __uint_as_float(u);
}

// ---------------- parallel threshold ----------------
__global__ void k_h1() {
    __shared__ unsigned hist[2048];
    int b = blockIdx.y;
    const float* ys = g_ysub + b * 2048 * 512;
    for (int i = threadIdx.x; i < 2048; i += 256) hist[i] = 0;
    __syncthreads();
    for (int i = blockIdx.x * 256 + threadIdx.x; i < 2048 * 512; i += gridDim.x * 256)
        atomicAdd(&hist[f2ord(ys[i]) >> 21], 1u);
    __syncthreads();
    for (int i = threadIdx.x; i < 2048; i += 256)
        if (hist[i]) atomicAdd(&g_h1[b * 2048 + i], hist[i]);
}
__global__ void k_tmid() {
    int b = blockIdx.x;
    if (threadIdx.x == 0) {
        unsigned acc = 0;
        int b1 = 0, m = 64;
        for (int i = 2047; i >= 0; i--) {
            unsigned h = g_h1[b * 2048 + i];
            acc += h;
            if (acc >= 64) { b1 = i; m = 64 - (int)(acc - h); break; }
        }
        g_tb1[b] = b1; g_tm[b] = m;
    }
    for (int i = threadIdx.x; i < 2048; i += blockDim.x) g_h2[b * 2048 + i] = 0;
}
__global__ void k_h2() {
    __shared__ unsigned hist[2048];
    int b = blockIdx.y;
    int b1 = g_tb1[b];
    const float* ys = g_ysub + b * 2048 * 512;
    for (int i = threadIdx.x; i < 2048; i += 256) hist[i] = 0;
    __syncthreads();
    for (int i = blockIdx.x * 256 + threadIdx.x; i < 2048 * 512; i += gridDim.x * 256) {
        unsigned key = f2ord(ys[i]);
        if ((int)(key >> 21) == b1) atomicAdd(&hist[(key >> 10) & 2047], 1u);
    }
    __syncthreads();
    for (int i = threadIdx.x; i < 2048; i += 256)
        if (hist[i]) atomicAdd(&g_h2[b * 2048 + i], hist[i]);
}
__global__ void k_tfin() {
    int b = blockIdx.x;
    if (threadIdx.x) return;
    int m = g_tm[b];
    unsigned acc = 0;
    int b2 = 0;
    for (int i = 2047; i >= 0; i--) {
        acc += g_h2[b * 2048 + i];
        if ((int)acc >= m) { b2 = i; break; }
    }
    unsigned tk = ((unsigned)g_tb1[b] << 21) | ((unsigned)b2 << 10);
    if (tk >= (1u << 10)) tk -= (1u << 10);
    float tf = ord2f(tk);
    g_thresh[b] = tf - 0.05f * fabsf(tf);
    g_candCnt[b] = 0;
}

// ---------------- up-projection (bf16 single-plane, K=128, 3-stage B, x4 loads) ----------------
__global__ void __launch_bounds__(256, 2) k_up_mma(const float* __restrict__ up_b) {
    __shared__ __align__(16) __nv_bfloat16 Ah[128][136];
    __shared__ __align__(16) __nv_bfloat16 Bs[3][128][24];
    int tid = threadIdx.x;
    int b = blockIdx.z;
    int u0 = blockIdx.y * 128;
    int t0 = blockIdx.x * 128;
    int w = tid >> 5, lane = tid & 31;
    int wu = w >> 1, wt = w & 1;
    int q = lane >> 3, r = lane & 7;

    const __nv_bfloat16* Bg = g_xB + (long)(b * NT + t0) * 128;
    int lr = tid >> 1, lh = tid & 1;

    for (int i = tid; i < 2048; i += 256) {
        int row = i >> 4, c8 = (i & 15) * 8;
        cp16(&Ah[row][c8], g_upA + (u0 + row) * 128 + c8);
    }
    cp16(&Bs[0][lr][lh * 8], Bg + lr * 128 + 0 + lh * 8);
    CP_COMMIT();
    cp16(&Bs[1][lr][lh * 8], Bg + lr * 128 + 16 + lh * 8);
    CP_COMMIT();

    float acc[2][8][4];
#pragma unroll
    for (int mi = 0; mi < 2; mi++)
#pragma unroll
        for (int ni = 0; ni < 8; ni++)
#pragma unroll
            for (int v = 0; v < 4; v++) acc[mi][ni][v] = 0.f;

    unsigned aA[2], bA[4];
#pragma unroll
    for (int mi = 0; mi < 2; mi++)
        aA[mi] = (unsigned)__cvta_generic_to_shared(
            &Ah[wu * 32 + mi * 16 + (q & 1) * 8 + r][(q >> 1) * 8]);
#pragma unroll
    for (int nj = 0; nj < 4; nj++)
        bA[nj] = (unsigned)__cvta_generic_to_shared(
            &Bs[0][wt * 64 + (nj * 2 + (q >> 1)) * 8 + r][(q & 1) * 8]);
    const unsigned SB = 128 * 24 * 2;

    for (int ck = 0; ck < 8; ck++) {
        if (ck < 6) CP_WAIT1(); else CP_WAIT0();
        __syncthreads();
        if (ck + 2 < 8) {
            cp16(&Bs[(ck + 2) % 3][lr][lh * 8], Bg + lr * 128 + (ck + 2) * 16 + lh * 8);
            CP_COMMIT();
        }
        unsigned bq[4][4], af[2][4];
        unsigned sB = (unsigned)(ck % 3) * SB;
#pragma unroll
        for (int nj = 0; nj < 4; nj++) ldmA4(bq[nj], bA[nj] + sB);
#pragma unroll
        for (int mi = 0; mi < 2; mi++) ldmA4(af[mi], aA[mi] + ck * 32);
#pragma unroll
        for (int mi = 0; mi < 2; mi++)
#pragma unroll
            for (int nj = 0; nj < 4; nj++) {
                mma16816(acc[mi][nj * 2],     af[mi], &bq[nj][0]);
                mma16816(acc[mi][nj * 2 + 1], af[mi], &bq[nj][2]);
            }
    }

    float T0 = g_thresh[b];
    int gid = lane >> 2, tig = lane & 3;
#pragma unroll
    for (int mi = 0; mi < 2; mi++) {
        int ub = u0 + wu * 32 + mi * 16 + gid;
        float bi0 = up_b[ub];
        float bi8 = up_b[ub + 8];
#pragma unroll
        for (int ni = 0; ni < 8; ni++) {
            int tb = t0 + wt * 64 + ni * 8 + tig * 2;
            float vv[4] = {acc[mi][ni][0] + bi0, acc[mi][ni][1] + bi0,
                           acc[mi][ni][2] + bi8, acc[mi][ni][3] + bi8};
            int uu[4] = {ub, ub, ub + 8, ub + 8};
            int tt[4] = {tb, tb + 1, tb, tb + 1};
#pragma unroll
            for (int v = 0; v < 4; v++) {
                if (vv[v] >= T0) {
                    int idx = atomicAdd(&g_candCnt[b], 1);
                    if (idx < CAP) {
                        g_candVal[b * CAP + idx] = vv[v];
                        g_candPack[b * CAP + idx] =
                            ((unsigned)uu[v] << 16) | (unsigned)tt[v];
                    }
                }
            }
        }
    }
}

__global__ void k_rescoreAll(const float* __restrict__ up_w, const float* __restrict__ up_b) {
    int b = blockIdx.y;
    int cnt = g_candCnt[b];
    if (cnt > CAP) cnt = CAP;
    int warpId = blockIdx.x * 8 + (threadIdx.x >> 5);
    int nw = gridDim.x * 8;
    int lane = threadIdx.x & 31;
    for (int i = warpId; i < cnt; i += nw) {
        unsigned pack = g_candPack[b * CAP + i];
        int u = (int)(pack >> 16), t = (int)(pack & 0xFFFFu);
        float s = 0.f;
#pragma unroll
        for (int c = lane; c < 128; c += 32)
            s += up_w[u * 128 + c] * g_bufA[(b * NC + c) * NTP + GOF + t];
#pragma unroll
        for (int o = 16; o; o >>= 1) s += __shfl_xor_sync(0xFFFFFFFFu, s, o);
        if (lane == 0) g_candVal[b * CAP + i] = s + up_b[u];
    }
}

__global__ void k_select() {
    __shared__ ull keys[5632];
    __shared__ ull red[256];
    int b = blockIdx.x, tid = threadIdx.x;
    int cnt = g_candCnt[b];
    if (cnt > CAP) cnt = CAP;
    bool useS = (cnt <= 5632);
    if (useS) {
        for (int i = tid; i < cnt; i += 256) {
            unsigned key = f2ord(g_candVal[b * CAP + i]);
            unsigned pack = g_candPack[b * CAP + i];
            keys[i] = ((ull)key << 32) | (ull)(~pack);
        }
    }
    __syncthreads();
    ull prev = 0xFFFFFFFFFFFFFFFFull;
    for (int r = 0; r < 64; r++) {
        ull best = 0;
        if (useS) {
            for (int i = tid; i < cnt; i += 256) {
                ull k64 = keys[i];
                if (k64 < prev && k64 > best) best = k64;
            }
        } else {
            for (int i = tid; i < cnt; i += 256) {
                unsigned key = f2ord(g_candVal[b * CAP + i]);
                unsigned pack = g_candPack[b * CAP + i];
                ull k64 = ((ull)key << 32) | (ull)(~pack);
                if (k64 < prev && k64 > best) best = k64;
            }
        }
        red[tid] = best;
        __syncthreads();
        for (int s = 128; s > 0; s >>= 1) {
            if (tid < s) { if (red[tid + s] > red[tid]) red[tid] = red[tid + s]; }
            __syncthreads();
        }
        best = red[0];
        if (tid == 0) {
            unsigned key = (unsigned)(best >> 32);
            unsigned pack = ~((unsigned)best);
            g_selVal[b * 64 + r] = ord2f(key);
            g_selU[b * 64 + r] = (int)(pack >> 16);
            g_selT[b * 64 + r] = (int)(pack & 0xFFFFu);
        }
        prev = best;
        __syncthreads();
    }
}

// ---------------- fused base + flags + pref ----------------
__global__ void k_bpf(const float* __restrict__ down_b, const float* __restrict__ dec_b,
                      const float* __restrict__ fb) {
    __shared__ float cur[128];
    __shared__ float pr[512];
    int tid = threadIdx.x;
    if (tid < 128) { cur[tid] = down_b[tid]; g_base[tid] = cur[tid]; }
    __syncthreads();
    for (int l = 0; l < 6; l++) {
        float nv = 0.f;
        if (tid < 128) {
            const float* Wt = g_Wt + (6 + l) * 32768;
            float h = dec_b[l * 128 + tid];
            for (int ci = 0; ci < 128; ci++)
                h += (Wt[(2 * ci) * 128 + tid] + Wt[(2 * ci + 1) * 128 + tid]) * cur[ci];
            h = (h > 0.f) ? h : 0.2f * h;
            nv = cur[tid] + h;
        }
        __syncthreads();
        if (tid < 128) { cur[tid] = nv; g_base[(l + 1) * 128 + tid] = nv; }
        __syncthreads();
    }
    {
        int b = tid >> 8, blk = tid & 255;
        int lo = blk * 128, hi = lo + 127;
        int act = (lo < 123) ? 1 : 0;
        for (int e = 0; e < 64; e++) {
            int s = g_selT[b * 64 + e];
            if (s <= hi && s + 122 >= lo) act = 1;
        }
        g_act[tid] = act;
    }
    {
        float s = 0.f;
        for (int c = 0; c < 128; c++) s += cur[c] * fb[c * 512 + tid];
        pr[tid] = s;
    }
    __syncthreads();
    if (tid == 0) {
        float acc = 0.f;
        g_pref[0] = 0.f;
        for (int k = 0; k < 512; k++) { acc += pr[k]; g_pref[k + 1] = acc; }
    }
}

__global__ void k_fill(const float* __restrict__ down_b) {
    int idx = blockIdx.x * 256 + threadIdx.x;
    if (idx >= NB * NC * NT / 4) return;
    int row = idx >> 13, t4 = idx & 8191;
    float v = down_b[row & 127];
    *(float4*)(&g_bufB[row * NTP + GOF + t4 * 4]) = make_float4(v, v, v, v);
}

__global__ void k_scatter(const float* __restrict__ down_w) {
    int tid = threadIdx.x;
    int b = tid >> 7, c = tid & 127;
    float* dst = g_bufB + (b * NC + c) * NTP + GOF;
    for (int e = 0; e < 64; e++) {
        float v = g_selVal[b * 64 + e];
        int u = g_selU[b * 64 + e];
        int t = g_selT[b * 64 + e];
        dst[t] += down_w[c * 2048 + u] * v;
    }
}

__global__ void k_fillOut(float* __restrict__ out) {
    int idx = blockIdx.x * 256 + threadIdx.x;
    if (idx >= NB * NT) return;
    int t = idx & (NT - 1);
    int jlo = 256 + t - (NT - 1); if (jlo < 0) jlo = 0;
    int jhi = 256 + t; if (jhi > 511) jhi = 511;
    out[idx] = g_pref[jhi + 1] - g_pref[jlo];
}

__global__ void __launch_bounds__(256) k_corr(const float* __restrict__ fb,
                                              float* __restrict__ out) {
    __shared__ __align__(16) float fbx[8][768];
    __shared__ __align__(16) float dev[8][128];
    int b = blockIdx.z, blk = blockIdx.x, cg = blockIdx.y;
    if (!g_act[b * 256 + blk]) return;
    int s = blk * 128;
    int tid = threadIdx.x;
    const float* D = g_bufB + b * NC * NTP + GOF;

    for (int i = tid; i < 8 * 256; i += 256) {
        int c = i >> 8, p = i & 255;
        fbx[c][(p < 128) ? p : (512 + p)] = 0.f;
    }
    for (int i = tid; i < 8 * 512; i += 256)
        fbx[i >> 9][128 + (i & 511)] = fb[(cg * 8 + (i >> 9)) * 512 + (i & 511)];
    for (int i = tid; i < 8 * 128; i += 256) {
        int c = i >> 7, col = i & 127;
        dev[c][col] = D[(cg * 8 + c) * NTP + s + col] - g_base[768 + cg * 8 + c];
    }
    __syncthreads();

    if (tid >= 160) return;
    float a0 = 0.f, a1 = 0.f, a2 = 0.f, a3 = 0.f;
    int t0 = 4 * tid;
#pragma unroll 2
    for (int c = 0; c < 8; c++) {
        const float* fx = &fbx[c][0];
        const float4* dv4 = (const float4*)&dev[c][0];
        int m0 = t0 + 4;
        float4 fa = *(const float4*)&fx[m0 - 4];
        for (int c4 = 31; c4 >= 0; c4--) {
            float4 d4 = dv4[c4];
            float4 fbv = *(const float4*)&fx[m0];
            float wm3 = fa.y, wm2 = fa.z, wm1 = fa.w;
            a0 += fbv.x * d4.x + wm1 * d4.y + wm2 * d4.z + wm3 * d4.w;
            a1 += fbv.y * d4.x + fbv.x * d4.y + wm1 * d4.z + wm2 * d4.w;
            a2 += fbv.z * d4.x + fbv.y * d4.y + fbv.x * d4.z + wm1 * d4.w;
            a3 += fbv.w * d4.x + fbv.z * d4.y + fbv.y * d4.z + fbv.x * d4.w;
            fa = fbv;
            m0 += 4;
        }
    }
    float av[4] = {a0, a1, a2, a3};
#pragma unroll
    for (int qd = 0; qd < 4; qd++) {
        int t = t0 + qd;
        if (t < 639) {
            int tg = s - 256 + t;
            if (tg >= 0 && tg < NT && av[qd] != 0.f)
                atomicAdd(&out[b * NT + tg], av[qd]);
        }
    }
}

// ---------------- host driver ----------------
extern "C" void kernel_launch(void* const* d_in, const int* in_sizes, int n_in,
                              void* d_out, int out_size) {
    const float* x      = (const float*)d_in[0];
    const float* fb     = (const float*)d_in[1];
    const float* enc_w  = (const float*)d_in[2];
    const float* enc_b  = (const float*)d_in[3];
    const float* up_w   = (const float*)d_in[4];
    const float* up_b   = (const float*)d_in[5];
    const float* down_w = (const float*)d_in[6];
    const float* down_b = (const float*)d_in[7];
    const float* dec_w  = (const float*)d_in[8];
    const float* dec_b  = (const float*)d_in[9];
    float* out = (float*)d_out;

    static const int dil[6] = {1, 3, 9, 27, 81, 1};

    int prepTotal = 393216 * 2 + 65536 + 262144 * 2 + NB * XP + 262144 + NB * 2048;
    k_prep<<<(prepTotal + 255) / 256, 256>>>(enc_w, dec_w, fb, up_w, x);

    k_fb_mma<<<dim3(NT / 128, NB), 256>>>();

    int srcIsA = 1;
    for (int l = 0; l < 6; l++) {
        k_layer_mma<<<dim3(256, NB), 256>>>(srcIsA, l, enc_b + l * 128, 0, dil[l], 0, 0);
        srcIsA ^= 1;
    }

    k_xB<<<dim3(NT / 32, NC / 32, NB), dim3(32, 8)>>>();
    k_sub<<<dim3(NU / 256, 512 / 16, NB), 256>>>(up_b);
    k_h1<<<dim3(64, NB), 256>>>();
    k_tmid<<<NB, 256>>>();
    k_h2<<<dim3(64, NB), 256>>>();
    k_tfin<<<NB, 32>>>();
    k_up_mma<<<dim3(NT / 128, NU / 128, NB), 256>>>(up_b);
    k_rescoreAll<<<dim3(64, NB), 256>>>(up_w, up_b);
    k_select<<<NB, 256>>>();

    k_bpf<<<1, 512>>>(down_b, dec_b, fb);
    k_fill<<<(NB * NC * NT / 4 + 255) / 256, 256>>>(down_b);
    k_scatter<<<1, 256>>>(down_w);

    srcIsA = 0;
    for (int l = 0; l < 6; l++) {
        k_layer_mma<<<dim3(256, NB), 256>>>(srcIsA, 6 + l, dec_b + l * 128, -dil[l], 0, 1, l);
        srcIsA ^= 1;
    }

    k_fillOut<<<(NB * NT + 255) / 256, 256>>>(out);
    k_corr<<<dim3(256, 16, NB), 256>>>(fb, out);
    (void)in_sizes; (void)n_in; (void)out_size;
}